// round 6
// baseline (speedup 1.0000x reference)
#include <cuda_runtime.h>
#include <math.h>

#define BSZ    8
#define NTOK   1024
#define DMODEL 512
#define QKV3   1536
#define NH     8
#define DHE    64
#define DINNER 512
#define ASCALE 0.125f

// ---------------- scratch (device globals; no runtime allocation) ----------
__device__ float  g_qkv[BSZ * NTOK * QKV3];    // [b*N + n][1536]
__device__ float  g_attn[BSZ * NTOK * DINNER]; // [b*N + n][512]
__device__ double g_score[BSZ * NTOK];
__device__ float  g_nnz[NTOK];
__device__ int    g_src[BSZ * NTOK];

// ---------------- f32x2 helpers ---------------------------------------------
static __device__ __forceinline__ unsigned long long dup2(float v) {
    unsigned long long r;
    asm("mov.b64 %0, {%1, %1};" : "=l"(r) : "f"(v));
    return r;
}
static __device__ __forceinline__ void fma2(unsigned long long& d,
                                            unsigned long long a,
                                            unsigned long long b) {
    asm("fma.rn.f32x2 %0, %1, %2, %0;" : "+l"(d) : "l"(a), "l"(b));
}
static __device__ __forceinline__ float2 unpack2(unsigned long long v) {
    float2 f;
    asm("mov.b64 {%0, %1}, %2;" : "=f"(f.x), "=f"(f.y) : "l"(v));
    return f;
}

// ---------------- zero score -------------------------------------------------
__global__ void zero_score_kernel() {
    int i = blockIdx.x * blockDim.x + threadIdx.x;
    if (i < BSZ * NTOK) g_score[i] = 0.0;
}

// ---------------- nnz per mask row -------------------------------------------
__global__ void nnz_kernel(const int* __restrict__ mask) {
    int row = blockIdx.x;
    int t = threadIdx.x;
    int cnt = 0;
    for (int c = t; c < NTOK; c += 256) cnt += (mask[row * NTOK + c] != 0);
    for (int o = 16; o; o >>= 1) cnt += __shfl_xor_sync(0xffffffffu, cnt, o);
    __shared__ int sred[8];
    if ((t & 31) == 0) sred[t >> 5] = cnt;
    __syncthreads();
    if (t == 0) {
        int s = 0;
        for (int i = 0; i < 8; i++) s += sred[i];
        g_nnz[row] = (float)s;
    }
}

// ---------------- GEMM 1: qkv = x @ w_qkv  (8192 x 1536 x 512) ---------------
__global__ __launch_bounds__(256) void gemm_qkv_kernel(
    const float* __restrict__ A, const float* __restrict__ Bw)
{
    const int BM = 128, BN = 128, BK = 16;
    __shared__ float As[2][BK][BM + 8];
    __shared__ float Bs[2][BK][BN];
    int bm = blockIdx.y * BM;
    int bn = blockIdx.x * BN;
    int tid = threadIdx.x;
    int ty = tid >> 4, tx = tid & 15;

    float4 pa[2], pb[2];
    int ar[2], ac4[2], br[2], bc4[2];
#pragma unroll
    for (int l = 0; l < 2; l++) {
        int idx = tid + l * 256;
        ar[l] = idx >> 2;  ac4[l] = idx & 3;
        br[l] = idx >> 5;  bc4[l] = idx & 31;
    }

    unsigned long long acc[8][4];
#pragma unroll
    for (int i = 0; i < 8; i++)
#pragma unroll
        for (int j = 0; j < 4; j++) acc[i][j] = 0ULL;

#pragma unroll
    for (int l = 0; l < 2; l++) {
        pa[l] = *reinterpret_cast<const float4*>(&A[(size_t)(bm + ar[l]) * DMODEL + ac4[l] * 4]);
        pb[l] = *reinterpret_cast<const float4*>(&Bw[(size_t)br[l] * QKV3 + bn + bc4[l] * 4]);
    }
#pragma unroll
    for (int l = 0; l < 2; l++) {
        As[0][ac4[l] * 4 + 0][ar[l]] = pa[l].x;
        As[0][ac4[l] * 4 + 1][ar[l]] = pa[l].y;
        As[0][ac4[l] * 4 + 2][ar[l]] = pa[l].z;
        As[0][ac4[l] * 4 + 3][ar[l]] = pa[l].w;
        *reinterpret_cast<float4*>(&Bs[0][br[l]][bc4[l] * 4]) = pb[l];
    }
    __syncthreads();

    int buf = 0;
    for (int k0 = 0; k0 < DMODEL; k0 += BK) {
        if (k0 + BK < DMODEL) {
#pragma unroll
            for (int l = 0; l < 2; l++) {
                pa[l] = *reinterpret_cast<const float4*>(&A[(size_t)(bm + ar[l]) * DMODEL + k0 + BK + ac4[l] * 4]);
                pb[l] = *reinterpret_cast<const float4*>(&Bw[(size_t)(k0 + BK + br[l]) * QKV3 + bn + bc4[l] * 4]);
            }
        }
#pragma unroll
        for (int k = 0; k < BK; k++) {
            float4 a0 = *reinterpret_cast<const float4*>(&As[buf][k][ty * 8]);
            float4 a1 = *reinterpret_cast<const float4*>(&As[buf][k][ty * 8 + 4]);
            ulonglong2 b01 = *reinterpret_cast<const ulonglong2*>(&Bs[buf][k][tx * 8]);
            ulonglong2 b23 = *reinterpret_cast<const ulonglong2*>(&Bs[buf][k][tx * 8 + 4]);
            float av[8] = {a0.x, a0.y, a0.z, a0.w, a1.x, a1.y, a1.z, a1.w};
#pragma unroll
            for (int i = 0; i < 8; i++) {
                unsigned long long ad = dup2(av[i]);
                fma2(acc[i][0], ad, b01.x);
                fma2(acc[i][1], ad, b01.y);
                fma2(acc[i][2], ad, b23.x);
                fma2(acc[i][3], ad, b23.y);
            }
        }
        if (k0 + BK < DMODEL) {
            int nb = buf ^ 1;
#pragma unroll
            for (int l = 0; l < 2; l++) {
                As[nb][ac4[l] * 4 + 0][ar[l]] = pa[l].x;
                As[nb][ac4[l] * 4 + 1][ar[l]] = pa[l].y;
                As[nb][ac4[l] * 4 + 2][ar[l]] = pa[l].z;
                As[nb][ac4[l] * 4 + 3][ar[l]] = pa[l].w;
                *reinterpret_cast<float4*>(&Bs[nb][br[l]][bc4[l] * 4]) = pb[l];
            }
            __syncthreads();
            buf = nb;
        }
    }
#pragma unroll
    for (int i = 0; i < 8; i++) {
        int row = bm + ty * 8 + i;
        float2 c0 = unpack2(acc[i][0]), c1 = unpack2(acc[i][1]);
        float2 c2 = unpack2(acc[i][2]), c3 = unpack2(acc[i][3]);
        *reinterpret_cast<float4*>(&g_qkv[(size_t)row * QKV3 + bn + tx * 8]) =
            make_float4(c0.x, c0.y, c1.x, c1.y);
        *reinterpret_cast<float4*>(&g_qkv[(size_t)row * QKV3 + bn + tx * 8 + 4]) =
            make_float4(c2.x, c2.y, c3.x, c3.y);
    }
}

// ---------------- fused attention + score ------------------------------------
// grid (8 qtiles, 8 h, 8 b), block 256 (16ty x 16tx). Tile 128q x 128k.
// S packs accumulators over d (even/odd partials): both fma2 operands are
// contiguous u64s from natural-layout smem -> NO dup MOVs. PV packs over k,
// reading P[q][k] natural and V transposed [d][k]. Final = lo + hi.
// Thread's k columns: {4*tx+m} and {64+4*tx+m}; PV d columns: {4*tx+m}.
#define QS  68
#define KS  68
#define VTS 132
#define PTS 132
__global__ __launch_bounds__(256, 1) void attn_kernel(const int* __restrict__ mask)
{
    extern __shared__ float sm[];
    float* Qs = sm;                       // [128][68]  natural, pre-scaled
    float* Ks = Qs + 128 * QS;            // [128][68]  natural
    float* Vt = Ks + 128 * KS;            // [64][132]  transposed [d][k]
    float* Ps = Vt + 64 * VTS;            // [128][132] natural [q][k]

    int qt = blockIdx.x, h = blockIdx.y, b = blockIdx.z;
    int tid = threadIdx.x;
    int ty = tid >> 4, tx = tid & 15;
    int q0 = qt * 128;

    // ---- load Q natural [q][d], scaled ----
    {
        const float* qbase = g_qkv + (size_t)(b * NTOK + q0) * QKV3 + h * DHE;
#pragma unroll
        for (int l = 0; l < 8; l++) {
            int idx = tid + l * 256;          // 2048 float4
            int r = idx >> 4, d4 = idx & 15;
            float4 v = *reinterpret_cast<const float4*>(qbase + (size_t)r * QKV3 + d4 * 4);
            *reinterpret_cast<float4*>(&Qs[r * QS + d4 * 4]) =
                make_float4(v.x * ASCALE, v.y * ASCALE, v.z * ASCALE, v.w * ASCALE);
        }
    }

    unsigned long long o2[8][4];
    float l_i[8];
    double scd[8];
#pragma unroll
    for (int i = 0; i < 8; i++) {
        l_i[i] = 0.f; scd[i] = 0.0;
#pragma unroll
        for (int m = 0; m < 4; m++) o2[i][m] = 0ULL;
    }

    for (int kt = 0; kt < 8; kt++) {
        int k0 = kt * 128;
        // ---- K natural [k][d] ----
        {
            const float* kbase = g_qkv + (size_t)(b * NTOK + k0) * QKV3 + DMODEL + h * DHE;
#pragma unroll
            for (int l = 0; l < 8; l++) {
                int idx = tid + l * 256;
                int r = idx >> 4, d4 = idx & 15;
                *reinterpret_cast<float4*>(&Ks[r * KS + d4 * 4]) =
                    *reinterpret_cast<const float4*>(kbase + (size_t)r * QKV3 + d4 * 4);
            }
        }
        // ---- V transposed [d][k] (register transpose of 4 rows) ----
        {
            const float* vbase = g_qkv + (size_t)(b * NTOK + k0) * QKV3 + 2 * DMODEL + h * DHE;
#pragma unroll
            for (int l = 0; l < 2; l++) {
                int idx = tid + l * 256;      // 512 items, each 4 k-rows x float4
                int r4 = idx >> 4, d4 = idx & 15;
                const float* p = vbase + (size_t)(4 * r4) * QKV3 + d4 * 4;
                float4 a0 = *reinterpret_cast<const float4*>(p);
                float4 a1 = *reinterpret_cast<const float4*>(p + QKV3);
                float4 a2 = *reinterpret_cast<const float4*>(p + 2 * QKV3);
                float4 a3 = *reinterpret_cast<const float4*>(p + 3 * QKV3);
                *reinterpret_cast<float4*>(&Vt[(d4 * 4 + 0) * VTS + 4 * r4]) = make_float4(a0.x, a1.x, a2.x, a3.x);
                *reinterpret_cast<float4*>(&Vt[(d4 * 4 + 1) * VTS + 4 * r4]) = make_float4(a0.y, a1.y, a2.y, a3.y);
                *reinterpret_cast<float4*>(&Vt[(d4 * 4 + 2) * VTS + 4 * r4]) = make_float4(a0.z, a1.z, a2.z, a3.z);
                *reinterpret_cast<float4*>(&Vt[(d4 * 4 + 3) * VTS + 4 * r4]) = make_float4(a0.w, a1.w, a2.w, a3.w);
            }
        }
        __syncthreads();

        // ---- S (two k-halves) + mask + exp + P store ----
#pragma unroll
        for (int half = 0; half < 2; half++) {
            int kb = half * 64 + tx * 4;      // this thread's 4 k-columns
            unsigned long long s2[8][4];
#pragma unroll
            for (int i = 0; i < 8; i++)
#pragma unroll
                for (int m = 0; m < 4; m++) s2[i][m] = 0ULL;

#pragma unroll 4
            for (int c = 0; c < 16; c++) {    // 16B of d per step (4 floats = 2 u64)
                ulonglong2 kv[4];
#pragma unroll
                for (int m = 0; m < 4; m++)
                    kv[m] = *reinterpret_cast<const ulonglong2*>(&Ks[(kb + m) * KS + c * 4]);
#pragma unroll
                for (int i = 0; i < 8; i++) {
                    ulonglong2 qv = *reinterpret_cast<const ulonglong2*>(&Qs[(ty * 8 + i) * QS + c * 4]);
#pragma unroll
                    for (int m = 0; m < 4; m++) {
                        fma2(s2[i][m], qv.x, kv[m].x);
                        fma2(s2[i][m], qv.y, kv[m].y);
                    }
                }
            }

            const int* mb = mask + (size_t)(q0 + ty * 8) * NTOK + k0 + kb;
#pragma unroll
            for (int i = 0; i < 8; i++) {
                int4 m4 = *reinterpret_cast<const int4*>(mb + (size_t)i * NTOK);
                float2 e0 = unpack2(s2[i][0]);
                float2 e1 = unpack2(s2[i][1]);
                float2 e2 = unpack2(s2[i][2]);
                float2 e3 = unpack2(s2[i][3]);
                float lg[4];
                lg[0] = (e0.x + e0.y) * (float)m4.x;
                lg[1] = (e1.x + e1.y) * (float)m4.y;
                lg[2] = (e2.x + e2.y) * (float)m4.z;
                lg[3] = (e3.x + e3.y) * (float)m4.w;
                float ssum = fabsf(lg[0]) + fabsf(lg[1]) + fabsf(lg[2]) + fabsf(lg[3]);
                float p0 = __expf(lg[0]);
                float p1 = __expf(lg[1]);
                float p2 = __expf(lg[2]);
                float p3 = __expf(lg[3]);
                scd[i] += (double)ssum;
                l_i[i] += (p0 + p1) + (p2 + p3);
                *reinterpret_cast<float4*>(&Ps[(ty * 8 + i) * PTS + kb]) =
                    make_float4(p0, p1, p2, p3);
            }
        }
        __syncthreads();

        // ---- O += P @ V, packed over k ----
#pragma unroll 4
        for (int kc = 0; kc < 32; kc++) {     // 4 k per chunk
            int k = kc * 4;
            ulonglong2 vv[4];
#pragma unroll
            for (int m = 0; m < 4; m++)
                vv[m] = *reinterpret_cast<const ulonglong2*>(&Vt[(tx * 4 + m) * VTS + k]);
#pragma unroll
            for (int i = 0; i < 8; i++) {
                ulonglong2 pp = *reinterpret_cast<const ulonglong2*>(&Ps[(ty * 8 + i) * PTS + k]);
#pragma unroll
                for (int m = 0; m < 4; m++) {
                    fma2(o2[i][m], pp.x, vv[m].x);
                    fma2(o2[i][m], pp.y, vv[m].y);
                }
            }
        }
        __syncthreads();
    }

    // ---- epilogue ----
#pragma unroll
    for (int i = 0; i < 8; i++) {
        int q = q0 + ty * 8 + i;
        float lsum = l_i[i];
#pragma unroll
        for (int off = 8; off; off >>= 1)
            lsum += __shfl_xor_sync(0xffffffffu, lsum, off);
        float inv = 1.0f / lsum;
        float2 f0 = unpack2(o2[i][0]);
        float2 f1 = unpack2(o2[i][1]);
        float2 f2 = unpack2(o2[i][2]);
        float2 f3 = unpack2(o2[i][3]);
        *reinterpret_cast<float4*>(&g_attn[(size_t)(b * NTOK + q) * DINNER + h * DHE + tx * 4]) =
            make_float4((f0.x + f0.y) * inv, (f1.x + f1.y) * inv,
                        (f2.x + f2.y) * inv, (f3.x + f3.y) * inv);
        double ssum = scd[i];
#pragma unroll
        for (int off = 8; off; off >>= 1)
            ssum += __shfl_xor_sync(0xffffffffu, ssum, off);
        if (tx == 0) atomicAdd(&g_score[b * NTOK + q], ssum);
    }
}

// ---------------- sort + swap map --------------------------------------------
__global__ __launch_bounds__(1024) void sort_swap_kernel(const int* __restrict__ patches)
{
    int bb = blockIdx.x;
    int t = threadIdx.x;
    __shared__ double sval[NTOK];
    __shared__ int sidx[NTOK];
    sval[t] = g_score[bb * NTOK + t] / (double)g_nnz[t];
    sidx[t] = t;
    __syncthreads();

    for (int k = 2; k <= NTOK; k <<= 1) {
        for (int j = k >> 1; j > 0; j >>= 1) {
            int ixj = t ^ j;
            if (ixj > t) {
                double v1 = sval[t], v2 = sval[ixj];
                int i1 = sidx[t], i2 = sidx[ixj];
                bool gt = (v1 > v2) || (v1 == v2 && i1 > i2);
                bool up = ((t & k) == 0);
                if (gt == up) {
                    sval[t] = v2; sval[ixj] = v1;
                    sidx[t] = i2; sidx[ixj] = i1;
                }
            }
            __syncthreads();
        }
    }

    int bo = (BSZ - 1) - bb;
    g_src[bo * NTOK + t] = t;
    __syncthreads();
    if (t == 0) {
        int P = patches[0];
        for (int i = 1; i <= P; i++) {
            int ti = sidx[i];
            g_src[bo * NTOK + i] = ti;
            g_src[bo * NTOK + ti] = i;
        }
    }
}

// ---------------- GEMM 2: out = gather(attn) @ w_out + b_out -----------------
__global__ __launch_bounds__(256) void gemm_out_kernel(
    const float* __restrict__ Wo, const float* __restrict__ bias,
    float* __restrict__ Out)
{
    const int BM = 128, BN = 128, BK = 16;
    __shared__ float As[2][BK][BM + 8];
    __shared__ float Bs[2][BK][BN];
    __shared__ int rowmap[BM];
    int bm = blockIdx.y * BM;
    int bn = blockIdx.x * BN;
    int tid = threadIdx.x;
    int ty = tid >> 4, tx = tid & 15;

    if (tid < BM) {
        int row = bm + tid;
        rowmap[tid] = (row & ~(NTOK - 1)) + g_src[row];
    }
    __syncthreads();

    float4 pa[2], pb[2];
    int ar[2], ac4[2], br[2], bc4[2];
#pragma unroll
    for (int l = 0; l < 2; l++) {
        int idx = tid + l * 256;
        ar[l] = idx >> 2;  ac4[l] = idx & 3;
        br[l] = idx >> 5;  bc4[l] = idx & 31;
    }

    unsigned long long acc[8][4];
#pragma unroll
    for (int i = 0; i < 8; i++)
#pragma unroll
        for (int j = 0; j < 4; j++) acc[i][j] = 0ULL;

#pragma unroll
    for (int l = 0; l < 2; l++) {
        pa[l] = *reinterpret_cast<const float4*>(&g_attn[(size_t)rowmap[ar[l]] * DINNER + ac4[l] * 4]);
        pb[l] = *reinterpret_cast<const float4*>(&Wo[(size_t)br[l] * DMODEL + bn + bc4[l] * 4]);
    }
#pragma unroll
    for (int l = 0; l < 2; l++) {
        As[0][ac4[l] * 4 + 0][ar[l]] = pa[l].x;
        As[0][ac4[l] * 4 + 1][ar[l]] = pa[l].y;
        As[0][ac4[l] * 4 + 2][ar[l]] = pa[l].z;
        As[0][ac4[l] * 4 + 3][ar[l]] = pa[l].w;
        *reinterpret_cast<float4*>(&Bs[0][br[l]][bc4[l] * 4]) = pb[l];
    }
    __syncthreads();

    int buf = 0;
    for (int k0 = 0; k0 < DINNER; k0 += BK) {
        if (k0 + BK < DINNER) {
#pragma unroll
            for (int l = 0; l < 2; l++) {
                pa[l] = *reinterpret_cast<const float4*>(&g_attn[(size_t)rowmap[ar[l]] * DINNER + k0 + BK + ac4[l] * 4]);
                pb[l] = *reinterpret_cast<const float4*>(&Wo[(size_t)(k0 + BK + br[l]) * DMODEL + bn + bc4[l] * 4]);
            }
        }
#pragma unroll
        for (int k = 0; k < BK; k++) {
            float4 a0 = *reinterpret_cast<const float4*>(&As[buf][k][ty * 8]);
            float4 a1 = *reinterpret_cast<const float4*>(&As[buf][k][ty * 8 + 4]);
            ulonglong2 b01 = *reinterpret_cast<const ulonglong2*>(&Bs[buf][k][tx * 8]);
            ulonglong2 b23 = *reinterpret_cast<const ulonglong2*>(&Bs[buf][k][tx * 8 + 4]);
            float av[8] = {a0.x, a0.y, a0.z, a0.w, a1.x, a1.y, a1.z, a1.w};
#pragma unroll
            for (int i = 0; i < 8; i++) {
                unsigned long long ad = dup2(av[i]);
                fma2(acc[i][0], ad, b01.x);
                fma2(acc[i][1], ad, b01.y);
                fma2(acc[i][2], ad, b23.x);
                fma2(acc[i][3], ad, b23.y);
            }
        }
        if (k0 + BK < DINNER) {
            int nb = buf ^ 1;
#pragma unroll
            for (int l = 0; l < 2; l++) {
                As[nb][ac4[l] * 4 + 0][ar[l]] = pa[l].x;
                As[nb][ac4[l] * 4 + 1][ar[l]] = pa[l].y;
                As[nb][ac4[l] * 4 + 2][ar[l]] = pa[l].z;
                As[nb][ac4[l] * 4 + 3][ar[l]] = pa[l].w;
                *reinterpret_cast<float4*>(&Bs[nb][br[l]][bc4[l] * 4]) = pb[l];
            }
            __syncthreads();
            buf = nb;
        }
    }
#pragma unroll
    for (int i = 0; i < 8; i++) {
        int row = bm + ty * 8 + i;
        int col = bn + tx * 8;
        float2 c0 = unpack2(acc[i][0]), c1 = unpack2(acc[i][1]);
        float2 c2 = unpack2(acc[i][2]), c3 = unpack2(acc[i][3]);
        *reinterpret_cast<float4*>(&Out[(size_t)row * DMODEL + col]) =
            make_float4(c0.x + bias[col + 0], c0.y + bias[col + 1],
                        c1.x + bias[col + 2], c1.y + bias[col + 3]);
        *reinterpret_cast<float4*>(&Out[(size_t)row * DMODEL + col + 4]) =
            make_float4(c2.x + bias[col + 4], c2.y + bias[col + 5],
                        c3.x + bias[col + 6], c3.y + bias[col + 7]);
    }
}

// ---------------- launch ------------------------------------------------------
extern "C" void kernel_launch(void* const* d_in, const int* in_sizes, int n_in,
                              void* d_out, int out_size)
{
    const float* x       = (const float*)d_in[0];
    const int*   cp_mask = (const int*)d_in[1];
    const float* w_qkv   = (const float*)d_in[2];
    const float* w_out   = (const float*)d_in[3];
    const float* b_out   = (const float*)d_in[4];
    const int*   patches = (const int*)d_in[5];
    float* out = (float*)d_out;

    const int attn_smem = (128 * QS + 128 * KS + 64 * VTS + 128 * PTS) * (int)sizeof(float);
    cudaFuncSetAttribute(attn_kernel, cudaFuncAttributeMaxDynamicSharedMemorySize, attn_smem);

    zero_score_kernel<<<32, 256>>>();
    nnz_kernel<<<NTOK, 256>>>(cp_mask);
    gemm_qkv_kernel<<<dim3(QKV3 / 128, (BSZ * NTOK) / 128), 256>>>(x, w_qkv);
    attn_kernel<<<dim3(8, NH, BSZ), 256, attn_smem>>>(cp_mask);
    sort_swap_kernel<<<BSZ, 1024>>>(patches);
    gemm_out_kernel<<<dim3(DMODEL / 128, (BSZ * NTOK) / 128), 256>>>(w_out, b_out, out);
}

// round 9
// speedup vs baseline: 1.4507x; 1.4507x over previous
#include <cuda_runtime.h>
#include <cuda_bf16.h>
#include <math.h>
#include <stdint.h>

#define BSZ    8
#define NTOK   1024
#define DMODEL 512
#define QKV3   1536
#define NH     8
#define DHE    64
#define DINNER 512
#define ASCALE 0.125f
typedef unsigned long long u64;

// ---------------- scratch (device globals; referenced ONLY from device code) --
__device__ float  g_qkv[BSZ * NTOK * QKV3];
__device__ float  g_attn[BSZ * NTOK * DINNER];
__device__ double g_score[BSZ * NTOK];
__device__ float  g_nnz[NTOK];
__device__ int    g_src[BSZ * NTOK];
__device__ __align__(16) __nv_bfloat16 g_xh[BSZ*NTOK*DMODEL], g_xm[BSZ*NTOK*DMODEL], g_xl[BSZ*NTOK*DMODEL];
__device__ __align__(16) __nv_bfloat16 g_ah[BSZ*NTOK*DINNER], g_am[BSZ*NTOK*DINNER], g_al[BSZ*NTOK*DINNER];
__device__ __align__(16) __nv_bfloat16 g_wqh[QKV3*DMODEL], g_wqm[QKV3*DMODEL], g_wql[QKV3*DMODEL];
__device__ __align__(16) __nv_bfloat16 g_woh[DINNER*DMODEL], g_wom[DINNER*DMODEL], g_wol[DINNER*DMODEL];

// ---------------- mma helpers --------------------------------------------------
static __device__ __forceinline__ uint32_t smem_to_u32(const void* p) {
    uint32_t a;
    asm("{ .reg .u64 t; cvta.to.shared.u64 t, %1; cvt.u32.u64 %0, t; }" : "=r"(a) : "l"(p));
    return a;
}
static __device__ __forceinline__ void ldsm4(uint32_t addr, uint32_t& r0, uint32_t& r1,
                                             uint32_t& r2, uint32_t& r3) {
    asm volatile("ldmatrix.sync.aligned.m8n8.x4.shared.b16 {%0,%1,%2,%3}, [%4];"
        : "=r"(r0), "=r"(r1), "=r"(r2), "=r"(r3) : "r"(addr));
}
static __device__ __forceinline__ void mma16816(float* c,
    uint32_t a0, uint32_t a1, uint32_t a2, uint32_t a3, uint32_t b0, uint32_t b1) {
    asm volatile("mma.sync.aligned.m16n8k16.row.col.f32.bf16.bf16.f32 "
        "{%0,%1,%2,%3}, {%4,%5,%6,%7}, {%8,%9}, {%0,%1,%2,%3};"
        : "+f"(c[0]), "+f"(c[1]), "+f"(c[2]), "+f"(c[3])
        : "r"(a0), "r"(a1), "r"(a2), "r"(a3), "r"(b0), "r"(b1));
}

// ---------------- f32x2 helpers (attn) ----------------------------------------
static __device__ __forceinline__ u64 dup2(float v) {
    u64 r; asm("mov.b64 %0, {%1, %1};" : "=l"(r) : "f"(v)); return r;
}
static __device__ __forceinline__ void fma2(u64& d, u64 a, u64 b) {
    asm("fma.rn.f32x2 %0, %1, %2, %0;" : "+l"(d) : "l"(a), "l"(b));
}
static __device__ __forceinline__ float2 unpack2(u64 v) {
    float2 f; asm("mov.b64 {%0, %1}, %2;" : "=f"(f.x), "=f"(f.y) : "l"(v)); return f;
}

// ---------------- small kernels -------------------------------------------------
__global__ void zero_score_kernel() {
    int i = blockIdx.x * blockDim.x + threadIdx.x;
    if (i < BSZ * NTOK) g_score[i] = 0.0;
}
__global__ void nnz_kernel(const int* __restrict__ mask) {
    int row = blockIdx.x, t = threadIdx.x;
    int cnt = 0;
    for (int c = t; c < NTOK; c += 256) cnt += (mask[row * NTOK + c] != 0);
    for (int o = 16; o; o >>= 1) cnt += __shfl_xor_sync(0xffffffffu, cnt, o);
    __shared__ int sred[8];
    if ((t & 31) == 0) sred[t >> 5] = cnt;
    __syncthreads();
    if (t == 0) {
        int s = 0;
        for (int i = 0; i < 8; i++) s += sred[i];
        g_nnz[row] = (float)s;
    }
}
// fp32 -> bf16 hi/mid/lo. sel=0: src=x (arg), dst g_x*; sel=1: src=g_attn, dst g_a*.
__global__ void cvt_split3_kernel(const float* __restrict__ xsrc, int sel, int n)
{
    int i = blockIdx.x * blockDim.x + threadIdx.x;
    if (i >= n) return;
    const float* src = sel ? g_attn : xsrc;
    __nv_bfloat16 *h = sel ? g_ah : g_xh;
    __nv_bfloat16 *m = sel ? g_am : g_xm;
    __nv_bfloat16 *l = sel ? g_al : g_xl;
    float v = src[i];
    __nv_bfloat16 hh = __float2bfloat16(v);
    float r1 = v - __bfloat162float(hh);
    __nv_bfloat16 mm = __float2bfloat16(r1);
    float r2 = r1 - __bfloat162float(mm);
    h[i] = hh; m[i] = mm; l[i] = __float2bfloat16(r2);
}
// W[K][N] -> Wt[N][K] bf16 hi/mid/lo. sel=0: dst g_wq*; sel=1: dst g_wo*.
__global__ void transpose_split3_kernel(const float* __restrict__ src, int sel,
                                        int K, int N)
{
    __shared__ float t[32][33];
    __nv_bfloat16 *h = sel ? g_woh : g_wqh;
    __nv_bfloat16 *m = sel ? g_wom : g_wqm;
    __nv_bfloat16 *l = sel ? g_wol : g_wql;
    int k0 = blockIdx.y * 32, n0 = blockIdx.x * 32;
    int tx = threadIdx.x, ty = threadIdx.y;
#pragma unroll
    for (int j = 0; j < 32; j += 8)
        t[ty + j][tx] = src[(size_t)(k0 + ty + j) * N + n0 + tx];
    __syncthreads();
#pragma unroll
    for (int j = 0; j < 32; j += 8) {
        float v = t[tx][ty + j];
        int n = n0 + ty + j, k = k0 + tx;
        __nv_bfloat16 hh = __float2bfloat16(v);
        float r1 = v - __bfloat162float(hh);
        __nv_bfloat16 mm = __float2bfloat16(r1);
        float r2 = r1 - __bfloat162float(mm);
        h[(size_t)n * K + k] = hh;
        m[(size_t)n * K + k] = mm;
        l[(size_t)n * K + k] = __float2bfloat16(r2);
    }
}

// ---------------- HMMA GEMM (mma.sync, bf16 3-way split, 6 terms) ---------------
// Block tile 128x128, K-chunk 64, 256 threads (8 warps; warp tile 32m x 64n).
// sel=0: qkv = x @ wq (Out g_qkv stride 1536, identity rows, no bias)
// sel=1: out = gather(attn) @ wo + bias (Out ext stride 512)
#define TILE_B 16384
#define SMG_HDR 1024
#define GEMM_SMEM (SMG_HDR + 6 * TILE_B)

__global__ __launch_bounds__(256, 2) void gemm_mma_kernel(
    int sel, float* __restrict__ OutX, const float* __restrict__ bias)
{
    extern __shared__ char smg[];
    uint32_t sb = smem_to_u32(smg);
    int tid = threadIdx.x, lane = tid & 31, wid = tid >> 5;
    int wm = wid & 3, wn = wid >> 2;
    int bm = blockIdx.y * 128, bn = blockIdx.x * 128;

    const uint4 *A0, *A1, *A2, *B0, *B1, *B2;
    float* Out; int Nt;
    if (sel) {
        A0 = (const uint4*)g_ah;  A1 = (const uint4*)g_am;  A2 = (const uint4*)g_al;
        B0 = (const uint4*)g_woh; B1 = (const uint4*)g_wom; B2 = (const uint4*)g_wol;
        Out = OutX; Nt = DMODEL;
    } else {
        A0 = (const uint4*)g_xh;  A1 = (const uint4*)g_xm;  A2 = (const uint4*)g_xl;
        B0 = (const uint4*)g_wqh; B1 = (const uint4*)g_wqm; B2 = (const uint4*)g_wql;
        Out = g_qkv; Nt = QKV3;
    }
    int* rmap = (int*)smg;
    float* sbias = (float*)(smg + 512);
    if (tid < 128) {
        int row = bm + tid;
        rmap[tid] = sel ? ((row & ~(NTOK - 1)) + g_src[row]) : row;
        sbias[tid] = sel ? bias[bn + tid] : 0.f;
    }

    float acc[16][4];
#pragma unroll
    for (int i = 0; i < 16; i++)
#pragma unroll
        for (int j = 0; j < 4; j++) acc[i][j] = 0.f;

#pragma unroll 1
    for (int c = 0; c < 8; c++) {
        __syncthreads();
        // ---- load 6 tiles [128 rows][64 bf16] with swizzle ----
#pragma unroll
        for (int l = 0; l < 4; l++) {
            int idx = tid + l * 256;
            int r = idx >> 3, q = idx & 7;
            uint32_t so = (uint32_t)(r * 128 + ((q ^ (r & 7)) << 4));
            size_t ga = (size_t)rmap[r] * 64 + c * 8 + q;
            size_t gb = (size_t)(bn + r) * 64 + c * 8 + q;
            *(uint4*)(smg + SMG_HDR + 0 * TILE_B + so) = A0[ga];
            *(uint4*)(smg + SMG_HDR + 1 * TILE_B + so) = A1[ga];
            *(uint4*)(smg + SMG_HDR + 2 * TILE_B + so) = A2[ga];
            *(uint4*)(smg + SMG_HDR + 3 * TILE_B + so) = B0[gb];
            *(uint4*)(smg + SMG_HDR + 4 * TILE_B + so) = B1[gb];
            *(uint4*)(smg + SMG_HDR + 5 * TILE_B + so) = B2[gb];
        }
        __syncthreads();

        // ---- mma: 4 k16 steps x 6 split terms ----
#pragma unroll
        for (int ks = 0; ks < 4; ks++) {
            int ch = ks * 2 + (lane >> 4);
            uint32_t ar0 = (uint32_t)(wm * 32 + (lane & 15));
            uint32_t ar1 = ar0 + 16;
            uint32_t aoff0 = ar0 * 128 + (((uint32_t)ch ^ (ar0 & 7)) << 4);
            uint32_t aoff1 = ar1 * 128 + (((uint32_t)ch ^ (ar1 & 7)) << 4);
            uint32_t boff[4];
#pragma unroll
            for (int nb = 0; nb < 4; nb++) {
                uint32_t br = (uint32_t)(wn * 64 + nb * 16 + (lane & 15));
                boff[nb] = br * 128 + (((uint32_t)ch ^ (br & 7)) << 4);
            }
            const int pa[6] = {0, 0, 1, 0, 1, 2};
            const int pb[6] = {0, 1, 0, 2, 1, 0};
#pragma unroll
            for (int t = 0; t < 6; t++) {
                uint32_t abase = sb + SMG_HDR + pa[t] * TILE_B;
                uint32_t bbase = sb + SMG_HDR + (3 + pb[t]) * TILE_B;
                uint32_t a0, a1, a2, a3, a4, a5, a6, a7;
                ldsm4(abase + aoff0, a0, a1, a2, a3);
                ldsm4(abase + aoff1, a4, a5, a6, a7);
#pragma unroll
                for (int nb = 0; nb < 4; nb++) {
                    uint32_t b0, b1, b2, b3;
                    ldsm4(bbase + boff[nb], b0, b1, b2, b3);
                    mma16816(acc[nb * 2 + 0],     a0, a1, a2, a3, b0, b2);
                    mma16816(acc[nb * 2 + 1],     a0, a1, a2, a3, b1, b3);
                    mma16816(acc[8 + nb * 2 + 0], a4, a5, a6, a7, b0, b2);
                    mma16816(acc[8 + nb * 2 + 1], a4, a5, a6, a7, b1, b3);
                }
            }
        }
    }

    // ---- epilogue: direct global stores (+bias) ----
#pragma unroll
    for (int ma = 0; ma < 2; ma++) {
        int row = bm + wm * 32 + ma * 16 + (lane >> 2);
#pragma unroll
        for (int na = 0; na < 8; na++) {
            int colr = wn * 64 + na * 8 + (lane & 3) * 2;
            int col = bn + colr;
            float* a = acc[ma * 8 + na];
            float2 v0 = make_float2(a[0] + sbias[colr], a[1] + sbias[colr + 1]);
            float2 v1 = make_float2(a[2] + sbias[colr], a[3] + sbias[colr + 1]);
            *(float2*)&Out[(size_t)row * Nt + col] = v0;
            *(float2*)&Out[(size_t)(row + 8) * Nt + col] = v1;
        }
    }
}

// ---------------- fused attention + score (best scalar variant, 488us) ----------
#define QTS 132
#define KTS 132
#define VTS 68
#define PTS 132
__global__ __launch_bounds__(256, 1) void attn_kernel(const int* __restrict__ mask)
{
    extern __shared__ float sm[];
    float* Qt = sm;
    float* Kt = Qt + 64 * QTS;
    float* Vs = Kt + 64 * KTS;
    float* Ps = Vs + 128 * VTS;

    int qt = blockIdx.x, h = blockIdx.y, b = blockIdx.z;
    int tid = threadIdx.x;
    int ty = tid >> 4, tx = tid & 15;
    int q0 = qt * 128;

    {
        const float* qbase = g_qkv + (size_t)(b * NTOK + q0) * QKV3 + h * DHE;
#pragma unroll
        for (int l = 0; l < 2; l++) {
            int idx = tid + l * 256;
            int r4 = idx >> 4, d4 = idx & 15;
            const float* p = qbase + (size_t)(4 * r4) * QKV3 + d4 * 4;
            float4 a0 = *reinterpret_cast<const float4*>(p);
            float4 a1 = *reinterpret_cast<const float4*>(p + QKV3);
            float4 a2 = *reinterpret_cast<const float4*>(p + 2 * QKV3);
            float4 a3 = *reinterpret_cast<const float4*>(p + 3 * QKV3);
            *reinterpret_cast<float4*>(&Qt[(d4 * 4 + 0) * QTS + 4 * r4]) = make_float4(a0.x, a1.x, a2.x, a3.x);
            *reinterpret_cast<float4*>(&Qt[(d4 * 4 + 1) * QTS + 4 * r4]) = make_float4(a0.y, a1.y, a2.y, a3.y);
            *reinterpret_cast<float4*>(&Qt[(d4 * 4 + 2) * QTS + 4 * r4]) = make_float4(a0.z, a1.z, a2.z, a3.z);
            *reinterpret_cast<float4*>(&Qt[(d4 * 4 + 3) * QTS + 4 * r4]) = make_float4(a0.w, a1.w, a2.w, a3.w);
        }
    }

    u64 o2[8][2];
    float l_i[8];
    double scd[8];
#pragma unroll
    for (int i = 0; i < 8; i++) {
        o2[i][0] = 0ULL; o2[i][1] = 0ULL;
        l_i[i] = 0.f; scd[i] = 0.0;
    }

    for (int kt = 0; kt < 8; kt++) {
        int k0 = kt * 128;
        const float* kbase = g_qkv + (size_t)(b * NTOK + k0) * QKV3 + DMODEL + h * DHE;
#pragma unroll
        for (int l = 0; l < 2; l++) {
            int idx = tid + l * 256;
            int r4 = idx >> 4, d4 = idx & 15;
            const float* p = kbase + (size_t)(4 * r4) * QKV3 + d4 * 4;
            float4 a0 = *reinterpret_cast<const float4*>(p);
            float4 a1 = *reinterpret_cast<const float4*>(p + QKV3);
            float4 a2 = *reinterpret_cast<const float4*>(p + 2 * QKV3);
            float4 a3 = *reinterpret_cast<const float4*>(p + 3 * QKV3);
            *reinterpret_cast<float4*>(&Kt[(d4 * 4 + 0) * KTS + 4 * r4]) = make_float4(a0.x, a1.x, a2.x, a3.x);
            *reinterpret_cast<float4*>(&Kt[(d4 * 4 + 1) * KTS + 4 * r4]) = make_float4(a0.y, a1.y, a2.y, a3.y);
            *reinterpret_cast<float4*>(&Kt[(d4 * 4 + 2) * KTS + 4 * r4]) = make_float4(a0.z, a1.z, a2.z, a3.z);
            *reinterpret_cast<float4*>(&Kt[(d4 * 4 + 3) * KTS + 4 * r4]) = make_float4(a0.w, a1.w, a2.w, a3.w);
        }
        const float* vbase = g_qkv + (size_t)(b * NTOK + k0) * QKV3 + 2 * DMODEL + h * DHE;
#pragma unroll
        for (int l = 0; l < 8; l++) {
            int idx = tid + l * 256;
            int r = idx >> 4, d4 = idx & 15;
            *reinterpret_cast<float4*>(&Vs[r * VTS + d4 * 4]) =
                *reinterpret_cast<const float4*>(vbase + (size_t)r * QKV3 + d4 * 4);
        }
        __syncthreads();

        u64 s2[8][4];
#pragma unroll
        for (int i = 0; i < 8; i++)
#pragma unroll
            for (int j = 0; j < 4; j++) s2[i][j] = 0ULL;

#pragma unroll 4
        for (int d = 0; d < 64; d++) {
            float4 qa = *reinterpret_cast<const float4*>(&Qt[d * QTS + ty * 8]);
            float4 qb = *reinterpret_cast<const float4*>(&Qt[d * QTS + ty * 8 + 4]);
            ulonglong2 k01 = *reinterpret_cast<const ulonglong2*>(&Kt[d * KTS + tx * 8]);
            ulonglong2 k23 = *reinterpret_cast<const ulonglong2*>(&Kt[d * KTS + tx * 8 + 4]);
            float qv[8] = {qa.x, qa.y, qa.z, qa.w, qb.x, qb.y, qb.z, qb.w};
#pragma unroll
            for (int i = 0; i < 8; i++) {
                u64 qd = dup2(qv[i]);
                fma2(s2[i][0], qd, k01.x);
                fma2(s2[i][1], qd, k01.y);
                fma2(s2[i][2], qd, k23.x);
                fma2(s2[i][3], qd, k23.y);
            }
        }

        const int* mbase = mask + (size_t)(q0 + ty * 8) * NTOK + k0 + tx * 8;
        int4 ma = *reinterpret_cast<const int4*>(mbase);
        int4 mb = *reinterpret_cast<const int4*>(mbase + 4);
#pragma unroll
        for (int i = 0; i < 8; i++) {
            int4 na, nb;
            if (i < 7) {
                na = *reinterpret_cast<const int4*>(mbase + (size_t)(i + 1) * NTOK);
                nb = *reinterpret_cast<const int4*>(mbase + (size_t)(i + 1) * NTOK + 4);
            }
            float2 v0 = unpack2(s2[i][0]), v1 = unpack2(s2[i][1]);
            float2 v2 = unpack2(s2[i][2]), v3 = unpack2(s2[i][3]);
            float lg[8];
            lg[0] = v0.x * (ASCALE * (float)ma.x);
            lg[1] = v0.y * (ASCALE * (float)ma.y);
            lg[2] = v1.x * (ASCALE * (float)ma.z);
            lg[3] = v1.y * (ASCALE * (float)ma.w);
            lg[4] = v2.x * (ASCALE * (float)mb.x);
            lg[5] = v2.y * (ASCALE * (float)mb.y);
            lg[6] = v3.x * (ASCALE * (float)mb.z);
            lg[7] = v3.y * (ASCALE * (float)mb.w);
            float ssum = 0.f, lsum = 0.f;
            float p[8];
#pragma unroll
            for (int j = 0; j < 8; j++) ssum += fabsf(lg[j]);
#pragma unroll
            for (int j = 0; j < 8; j++) p[j] = __expf(lg[j]);
#pragma unroll
            for (int j = 0; j < 8; j++) lsum += p[j];
            scd[i] += (double)ssum;
            l_i[i] += lsum;
            *reinterpret_cast<float4*>(&Ps[(ty * 8 + i) * PTS + tx * 8]) =
                make_float4(p[0], p[1], p[2], p[3]);
            *reinterpret_cast<float4*>(&Ps[(ty * 8 + i) * PTS + tx * 8 + 4]) =
                make_float4(p[4], p[5], p[6], p[7]);
            ma = na; mb = nb;
        }
        __syncthreads();

        for (int k = 0; k < 128; k += 4) {
            ulonglong2 va = *reinterpret_cast<const ulonglong2*>(&Vs[(k + 0) * VTS + tx * 4]);
            ulonglong2 vb = *reinterpret_cast<const ulonglong2*>(&Vs[(k + 1) * VTS + tx * 4]);
            ulonglong2 vc = *reinterpret_cast<const ulonglong2*>(&Vs[(k + 2) * VTS + tx * 4]);
            ulonglong2 vd = *reinterpret_cast<const ulonglong2*>(&Vs[(k + 3) * VTS + tx * 4]);
#pragma unroll
            for (int i = 0; i < 8; i++) {
                float4 pv = *reinterpret_cast<const float4*>(&Ps[(ty * 8 + i) * PTS + k]);
                u64 pd;
                pd = dup2(pv.x); fma2(o2[i][0], pd, va.x); fma2(o2[i][1], pd, va.y);
                pd = dup2(pv.y); fma2(o2[i][0], pd, vb.x); fma2(o2[i][1], pd, vb.y);
                pd = dup2(pv.z); fma2(o2[i][0], pd, vc.x); fma2(o2[i][1], pd, vc.y);
                pd = dup2(pv.w); fma2(o2[i][0], pd, vd.x); fma2(o2[i][1], pd, vd.y);
            }
        }
        __syncthreads();
    }

#pragma unroll
    for (int i = 0; i < 8; i++) {
        int q = q0 + ty * 8 + i;
        float lsum = l_i[i];
#pragma unroll
        for (int off = 8; off; off >>= 1)
            lsum += __shfl_xor_sync(0xffffffffu, lsum, off);
        float inv = 1.0f / lsum;
        float2 oa = unpack2(o2[i][0]);
        float2 ob = unpack2(o2[i][1]);
        *reinterpret_cast<float4*>(&g_attn[(size_t)(b * NTOK + q) * DINNER + h * DHE + tx * 4]) =
            make_float4(oa.x * inv, oa.y * inv, ob.x * inv, ob.y * inv);
        double ssum = scd[i];
#pragma unroll
        for (int off = 8; off; off >>= 1)
            ssum += __shfl_xor_sync(0xffffffffu, ssum, off);
        if (tx == 0) atomicAdd(&g_score[b * NTOK + q], ssum);
    }
}

// ---------------- sort + swap map ------------------------------------------------
__global__ __launch_bounds__(1024) void sort_swap_kernel(const int* __restrict__ patches)
{
    int bb = blockIdx.x;
    int t = threadIdx.x;
    __shared__ double sval[NTOK];
    __shared__ int sidx[NTOK];
    sval[t] = g_score[bb * NTOK + t] / (double)g_nnz[t];
    sidx[t] = t;
    __syncthreads();

    for (int k = 2; k <= NTOK; k <<= 1) {
        for (int j = k >> 1; j > 0; j >>= 1) {
            int ixj = t ^ j;
            if (ixj > t) {
                double v1 = sval[t], v2 = sval[ixj];
                int i1 = sidx[t], i2 = sidx[ixj];
                bool gt = (v1 > v2) || (v1 == v2 && i1 > i2);
                bool up = ((t & k) == 0);
                if (gt == up) {
                    sval[t] = v2; sval[ixj] = v1;
                    sidx[t] = i2; sidx[ixj] = i1;
                }
            }
            __syncthreads();
        }
    }

    int bo = (BSZ - 1) - bb;
    g_src[bo * NTOK + t] = t;
    __syncthreads();
    if (t == 0) {
        int P = patches[0];
        for (int i = 1; i <= P; i++) {
            int ti = sidx[i];
            g_src[bo * NTOK + i] = ti;
            g_src[bo * NTOK + ti] = i;
        }
    }
}

// ---------------- launch -----------------------------------------------------------
extern "C" void kernel_launch(void* const* d_in, const int* in_sizes, int n_in,
                              void* d_out, int out_size)
{
    const float* x       = (const float*)d_in[0];
    const int*   cp_mask = (const int*)d_in[1];
    const float* w_qkv   = (const float*)d_in[2];
    const float* w_out   = (const float*)d_in[3];
    const float* b_out   = (const float*)d_in[4];
    const int*   patches = (const int*)d_in[5];
    float* out = (float*)d_out;

    const int attn_smem = (64 * QTS + 64 * KTS + 128 * VTS + 128 * PTS) * (int)sizeof(float);
    cudaFuncSetAttribute(attn_kernel, cudaFuncAttributeMaxDynamicSharedMemorySize, attn_smem);
    cudaFuncSetAttribute(gemm_mma_kernel, cudaFuncAttributeMaxDynamicSharedMemorySize, GEMM_SMEM);

    zero_score_kernel<<<32, 256>>>();
    nnz_kernel<<<NTOK, 256>>>(cp_mask);
    cvt_split3_kernel<<<(BSZ * NTOK * DMODEL) / 512, 512>>>(x, 0, BSZ * NTOK * DMODEL);
    transpose_split3_kernel<<<dim3(QKV3 / 32, DMODEL / 32), dim3(32, 8)>>>(w_qkv, 0, DMODEL, QKV3);
    transpose_split3_kernel<<<dim3(DMODEL / 32, DINNER / 32), dim3(32, 8)>>>(w_out, 1, DINNER, DMODEL);
    gemm_mma_kernel<<<dim3(QKV3 / 128, (BSZ * NTOK) / 128), 256, GEMM_SMEM>>>(0, nullptr, nullptr);
    attn_kernel<<<dim3(8, NH, BSZ), 256, attn_smem>>>(cp_mask);
    sort_swap_kernel<<<BSZ, 1024>>>(patches);
    cvt_split3_kernel<<<(BSZ * NTOK * DINNER) / 512, 512>>>(nullptr, 1, BSZ * NTOK * DINNER);
    gemm_mma_kernel<<<dim3(DMODEL / 128, (BSZ * NTOK) / 128), 256, GEMM_SMEM>>>(1, out, b_out);
}

// round 11
// speedup vs baseline: 1.9944x; 1.3748x over previous
#include <cuda_runtime.h>
#include <cuda_bf16.h>
#include <math.h>
#include <stdint.h>

#define BSZ    8
#define NTOK   1024
#define DMODEL 512
#define QKV3   1536
#define NH     8
#define DHE    64
#define DINNER 512
#define ASCALE 0.125f
typedef unsigned long long u64;

// ---------------- scratch (device globals; referenced ONLY from device code) --
__device__ float  g_qkv[BSZ * NTOK * QKV3];
__device__ float  g_attn[BSZ * NTOK * DINNER];
__device__ double g_score[BSZ * NTOK];
__device__ float  g_nnz[NTOK];
__device__ int    g_src[BSZ * NTOK];
// bf16 hi/mid of [Q*0.125 | K] (cols 0..1023 of qkv), row pitch 1024
__device__ __align__(16) __nv_bfloat16 g_qkvh[BSZ*NTOK*1024], g_qkvm[BSZ*NTOK*1024];
__device__ __align__(16) __nv_bfloat16 g_xh[BSZ*NTOK*DMODEL], g_xm[BSZ*NTOK*DMODEL], g_xl[BSZ*NTOK*DMODEL];
__device__ __align__(16) __nv_bfloat16 g_ah[BSZ*NTOK*DINNER], g_am[BSZ*NTOK*DINNER], g_al[BSZ*NTOK*DINNER];
__device__ __align__(16) __nv_bfloat16 g_wqh[QKV3*DMODEL], g_wqm[QKV3*DMODEL], g_wql[QKV3*DMODEL];
__device__ __align__(16) __nv_bfloat16 g_woh[DINNER*DMODEL], g_wom[DINNER*DMODEL], g_wol[DINNER*DMODEL];

// ---------------- helpers -------------------------------------------------------
static __device__ __forceinline__ uint32_t smem_to_u32(const void* p) {
    uint32_t a;
    asm("{ .reg .u64 t; cvta.to.shared.u64 t, %1; cvt.u32.u64 %0, t; }" : "=r"(a) : "l"(p));
    return a;
}
static __device__ __forceinline__ void ldsm4(uint32_t addr, uint32_t& r0, uint32_t& r1,
                                             uint32_t& r2, uint32_t& r3) {
    asm volatile("ldmatrix.sync.aligned.m8n8.x4.shared.b16 {%0,%1,%2,%3}, [%4];"
        : "=r"(r0), "=r"(r1), "=r"(r2), "=r"(r3) : "r"(addr));
}
static __device__ __forceinline__ void mma16816(float* c,
    uint32_t a0, uint32_t a1, uint32_t a2, uint32_t a3, uint32_t b0, uint32_t b1) {
    asm volatile("mma.sync.aligned.m16n8k16.row.col.f32.bf16.bf16.f32 "
        "{%0,%1,%2,%3}, {%4,%5,%6,%7}, {%8,%9}, {%0,%1,%2,%3};"
        : "+f"(c[0]), "+f"(c[1]), "+f"(c[2]), "+f"(c[3])
        : "r"(a0), "r"(a1), "r"(a2), "r"(a3), "r"(b0), "r"(b1));
}
static __device__ __forceinline__ uint32_t packbf2(float lo, float hi) {
    uint32_t r;
    asm("cvt.rn.bf16x2.f32 %0, %1, %2;" : "=r"(r) : "f"(hi), "f"(lo));
    return r;
}
static __device__ __forceinline__ float bflo(uint32_t p) { return __uint_as_float(p << 16); }
static __device__ __forceinline__ float bfhi(uint32_t p) { return __uint_as_float(p & 0xffff0000u); }
static __device__ __forceinline__ u64 pack4bf(float v0, float v1, float v2, float v3) {
    uint32_t p0 = packbf2(v0, v1), p1 = packbf2(v2, v3);
    u64 r; asm("mov.b64 %0,{%1,%2};" : "=l"(r) : "r"(p0), "r"(p1)); return r;
}

// ---------------- small kernels -------------------------------------------------
__global__ void zero_score_kernel() {
    int i = blockIdx.x * blockDim.x + threadIdx.x;
    if (i < BSZ * NTOK) g_score[i] = 0.0;
}
__global__ void nnz_kernel(const int* __restrict__ mask) {
    int row = blockIdx.x, t = threadIdx.x;
    int cnt = 0;
    for (int c = t; c < NTOK; c += 256) cnt += (mask[row * NTOK + c] != 0);
    for (int o = 16; o; o >>= 1) cnt += __shfl_xor_sync(0xffffffffu, cnt, o);
    __shared__ int sred[8];
    if ((t & 31) == 0) sred[t >> 5] = cnt;
    __syncthreads();
    if (t == 0) {
        int s = 0;
        for (int i = 0; i < 8; i++) s += sred[i];
        g_nnz[row] = (float)s;
    }
}
__global__ void cvt_split3_kernel(const float* __restrict__ xsrc, int sel, int n)
{
    int i = blockIdx.x * blockDim.x + threadIdx.x;
    if (i >= n) return;
    const float* src = sel ? g_attn : xsrc;
    __nv_bfloat16 *h = sel ? g_ah : g_xh;
    __nv_bfloat16 *m = sel ? g_am : g_xm;
    __nv_bfloat16 *l = sel ? g_al : g_xl;
    float v = src[i];
    __nv_bfloat16 hh = __float2bfloat16(v);
    float r1 = v - __bfloat162float(hh);
    __nv_bfloat16 mm = __float2bfloat16(r1);
    float r2 = r1 - __bfloat162float(mm);
    h[i] = hh; m[i] = mm; l[i] = __float2bfloat16(r2);
}
__global__ void transpose_split3_kernel(const float* __restrict__ src, int sel,
                                        int K, int N)
{
    __shared__ float t[32][33];
    __nv_bfloat16 *h = sel ? g_woh : g_wqh;
    __nv_bfloat16 *m = sel ? g_wom : g_wqm;
    __nv_bfloat16 *l = sel ? g_wol : g_wql;
    int k0 = blockIdx.y * 32, n0 = blockIdx.x * 32;
    int tx = threadIdx.x, ty = threadIdx.y;
#pragma unroll
    for (int j = 0; j < 32; j += 8)
        t[ty + j][tx] = src[(size_t)(k0 + ty + j) * N + n0 + tx];
    __syncthreads();
#pragma unroll
    for (int j = 0; j < 32; j += 8) {
        float v = t[tx][ty + j];
        int n = n0 + ty + j, k = k0 + tx;
        __nv_bfloat16 hh = __float2bfloat16(v);
        float r1 = v - __bfloat162float(hh);
        __nv_bfloat16 mm = __float2bfloat16(r1);
        float r2 = r1 - __bfloat162float(mm);
        h[(size_t)n * K + k] = hh;
        m[(size_t)n * K + k] = mm;
        l[(size_t)n * K + k] = __float2bfloat16(r2);
    }
}

// ---------------- HMMA GEMM (bf16 3-way split, hoisted A fragments) -------------
#define TILE_B 16384
#define SMG_HDR 1024
#define GEMM_SMEM (SMG_HDR + 6 * TILE_B)

__global__ __launch_bounds__(256, 2) void gemm_mma_kernel(
    int sel, float* __restrict__ OutX, const float* __restrict__ bias)
{
    extern __shared__ char smg[];
    uint32_t sb = smem_to_u32(smg);
    int tid = threadIdx.x, lane = tid & 31, wid = tid >> 5;
    int wm = wid & 3, wn = wid >> 2;
    int bm = blockIdx.y * 128, bn = blockIdx.x * 128;

    const uint4 *A0, *A1, *A2, *B0, *B1, *B2;
    float* Out; int Nt;
    if (sel) {
        A0 = (const uint4*)g_ah;  A1 = (const uint4*)g_am;  A2 = (const uint4*)g_al;
        B0 = (const uint4*)g_woh; B1 = (const uint4*)g_wom; B2 = (const uint4*)g_wol;
        Out = OutX; Nt = DMODEL;
    } else {
        A0 = (const uint4*)g_xh;  A1 = (const uint4*)g_xm;  A2 = (const uint4*)g_xl;
        B0 = (const uint4*)g_wqh; B1 = (const uint4*)g_wqm; B2 = (const uint4*)g_wql;
        Out = g_qkv; Nt = QKV3;
    }
    int* rmap = (int*)smg;
    float* sbias = (float*)(smg + 512);
    if (tid < 128) {
        int row = bm + tid;
        rmap[tid] = sel ? ((row & ~(NTOK - 1)) + g_src[row]) : row;
        sbias[tid] = sel ? bias[bn + tid] : 0.f;
    }

    float acc[16][4];
#pragma unroll
    for (int i = 0; i < 16; i++)
#pragma unroll
        for (int j = 0; j < 4; j++) acc[i][j] = 0.f;

#pragma unroll 1
    for (int c = 0; c < 8; c++) {
        __syncthreads();
#pragma unroll
        for (int l = 0; l < 4; l++) {
            int idx = tid + l * 256;
            int r = idx >> 3, q = idx & 7;
            uint32_t so = (uint32_t)(r * 128 + ((q ^ (r & 7)) << 4));
            size_t ga = (size_t)rmap[r] * 64 + c * 8 + q;
            size_t gb = (size_t)(bn + r) * 64 + c * 8 + q;
            *(uint4*)(smg + SMG_HDR + 0 * TILE_B + so) = A0[ga];
            *(uint4*)(smg + SMG_HDR + 1 * TILE_B + so) = A1[ga];
            *(uint4*)(smg + SMG_HDR + 2 * TILE_B + so) = A2[ga];
            *(uint4*)(smg + SMG_HDR + 3 * TILE_B + so) = B0[gb];
            *(uint4*)(smg + SMG_HDR + 4 * TILE_B + so) = B1[gb];
            *(uint4*)(smg + SMG_HDR + 5 * TILE_B + so) = B2[gb];
        }
        __syncthreads();

#pragma unroll
        for (int ks = 0; ks < 4; ks++) {
            uint32_t ch = (uint32_t)(ks * 2 + (lane >> 4));
            uint32_t ar0 = (uint32_t)(wm * 32 + (lane & 15));
            uint32_t ar1 = ar0 + 16;
            uint32_t aoff0 = ar0 * 128 + ((ch ^ (ar0 & 7)) << 4);
            uint32_t aoff1 = ar1 * 128 + ((ch ^ (ar1 & 7)) << 4);
            uint32_t boff[4];
#pragma unroll
            for (int nb = 0; nb < 4; nb++) {
                uint32_t br = (uint32_t)(wn * 64 + nb * 16 + (lane & 15));
                boff[nb] = br * 128 + ((ch ^ (br & 7)) << 4);
            }
            uint32_t Af[3][8];
#pragma unroll
            for (int s = 0; s < 3; s++) {
                ldsm4(sb + SMG_HDR + s * TILE_B + aoff0, Af[s][0], Af[s][1], Af[s][2], Af[s][3]);
                ldsm4(sb + SMG_HDR + s * TILE_B + aoff1, Af[s][4], Af[s][5], Af[s][6], Af[s][7]);
            }
#pragma unroll
            for (int bs = 0; bs < 3; bs++) {
                uint32_t bbase = sb + SMG_HDR + (3 + bs) * TILE_B;
#pragma unroll
                for (int nb = 0; nb < 4; nb++) {
                    uint32_t b0, b1, b2, b3;
                    ldsm4(bbase + boff[nb], b0, b1, b2, b3);
#pragma unroll
                    for (int s = 0; s < 3; s++) {
                        if (s + bs <= 2) {
                            mma16816(acc[nb * 2 + 0],     Af[s][0], Af[s][1], Af[s][2], Af[s][3], b0, b2);
                            mma16816(acc[nb * 2 + 1],     Af[s][0], Af[s][1], Af[s][2], Af[s][3], b1, b3);
                            mma16816(acc[8 + nb * 2 + 0], Af[s][4], Af[s][5], Af[s][6], Af[s][7], b0, b2);
                            mma16816(acc[8 + nb * 2 + 1], Af[s][4], Af[s][5], Af[s][6], Af[s][7], b1, b3);
                        }
                    }
                }
            }
        }
    }

    // ---- epilogue (+bias); sel==0 also emits bf16 hi/mid of [Q*0.125 | K] ----
#pragma unroll
    for (int ma = 0; ma < 2; ma++) {
        int row = bm + wm * 32 + ma * 16 + (lane >> 2);
#pragma unroll
        for (int na = 0; na < 8; na++) {
            int colr = wn * 64 + na * 8 + (lane & 3) * 2;
            int col = bn + colr;
            float* a = acc[ma * 8 + na];
            float2 v0 = make_float2(a[0] + sbias[colr], a[1] + sbias[colr + 1]);
            float2 v1 = make_float2(a[2] + sbias[colr], a[3] + sbias[colr + 1]);
            *(float2*)&Out[(size_t)row * Nt + col] = v0;
            *(float2*)&Out[(size_t)(row + 8) * Nt + col] = v1;
            if (!sel && col < 1024) {
                float sc = (col < 512) ? ASCALE : 1.f;
                float u0 = v0.x * sc, u1 = v0.y * sc;
                float w0 = v1.x * sc, w1 = v1.y * sc;
                uint32_t h0 = packbf2(u0, u1), h1 = packbf2(w0, w1);
                uint32_t m0 = packbf2(u0 - bflo(h0), u1 - bfhi(h0));
                uint32_t m1 = packbf2(w0 - bflo(h1), w1 - bfhi(h1));
                *(uint32_t*)&g_qkvh[(size_t)row * 1024 + col] = h0;
                *(uint32_t*)&g_qkvm[(size_t)row * 1024 + col] = m0;
                *(uint32_t*)&g_qkvh[(size_t)(row + 8) * 1024 + col] = h1;
                *(uint32_t*)&g_qkvm[(size_t)(row + 8) * 1024 + col] = m1;
            }
        }
    }
}

// ---------------- HMMA flash attention ------------------------------------------
// Q/K tiles are [128 r][64 d] bf16 = 16384 B each (128 B/row). FIXED spacing.
#define AQH 0
#define AQM 16384
#define AKH 32768
#define AKM 49152
#define AVH 65536
#define AVM 81920
#define ATT_SMEM 98304

__global__ __launch_bounds__(256, 1) void attn_mma_kernel(const int* __restrict__ mask)
{
    extern __shared__ char sma[];
    uint32_t sb = smem_to_u32(sma);
    int tid = threadIdx.x, lane = tid & 31, w = tid >> 5;
    int qt = blockIdx.x, h = blockIdx.y, b = blockIdx.z;
    int q0 = qt * 128;

    // ---- load Q tiles (hi, mid) once ----
#pragma unroll
    for (int l = 0; l < 8; l++) {
        int idx = tid + l * 256;
        int ts = idx >> 10;
        int rem = idx & 1023;
        int r = rem >> 3, q = rem & 7;
        const uint4* src = ts ? (const uint4*)g_qkvm : (const uint4*)g_qkvh;
        uint4 v = src[(size_t)(b * NTOK + q0 + r) * 128 + h * 8 + q];
        uint32_t so = (uint32_t)(r * 128 + ((q ^ (r & 7)) << 4));
        *(uint4*)(sma + (ts ? AQM : AQH) + so) = v;
    }

    float oacc[8][4];
#pragma unroll
    for (int i = 0; i < 8; i++)
#pragma unroll
        for (int j = 0; j < 4; j++) oacc[i][j] = 0.f;
    float l0 = 0.f, l1 = 0.f;
    double scd0 = 0.0, scd1 = 0.0;

#pragma unroll 1
    for (int kt = 0; kt < 8; kt++) {
        int k0 = kt * 128;
        __syncthreads();
#pragma unroll
        for (int l = 0; l < 8; l++) {
            int idx = tid + l * 256;
            int ts = idx >> 10;
            int rem = idx & 1023;
            int r = rem >> 3, q = rem & 7;
            const uint4* src = ts ? (const uint4*)g_qkvm : (const uint4*)g_qkvh;
            uint4 v = src[(size_t)(b * NTOK + k0 + r) * 128 + 64 + h * 8 + q];
            uint32_t so = (uint32_t)(r * 128 + ((q ^ (r & 7)) << 4));
            *(uint4*)(sma + (ts ? AKM : AKH) + so) = v;
        }
#pragma unroll
        for (int l = 0; l < 2; l++) {
            int idx = tid + l * 256;
            int r4 = idx >> 4, d4 = idx & 15;
            const float* p = g_qkv + (size_t)(b * NTOK + k0 + 4 * r4) * QKV3 + 1024 + h * DHE + d4 * 4;
            float4 a0 = *(const float4*)p;
            float4 a1 = *(const float4*)(p + QKV3);
            float4 a2 = *(const float4*)(p + 2 * QKV3);
            float4 a3 = *(const float4*)(p + 3 * QKV3);
            float fr[4][4] = {{a0.x, a1.x, a2.x, a3.x}, {a0.y, a1.y, a2.y, a3.y},
                              {a0.z, a1.z, a2.z, a3.z}, {a0.w, a1.w, a2.w, a3.w}};
#pragma unroll
            for (int j = 0; j < 4; j++) {
                int dd = d4 * 4 + j;
                uint32_t so = (uint32_t)(dd * 256 + (((r4 >> 1) ^ (dd & 7)) << 4) + (r4 & 1) * 8);
                u64 hh = pack4bf(fr[j][0], fr[j][1], fr[j][2], fr[j][3]);
                uint32_t hl = (uint32_t)hh, hu = (uint32_t)(hh >> 32);
                u64 mm = pack4bf(fr[j][0] - bflo(hl), fr[j][1] - bfhi(hl),
                                 fr[j][2] - bflo(hu), fr[j][3] - bfhi(hu));
                *(u64*)(sma + AVH + so) = hh;
                *(u64*)(sma + AVM + so) = mm;
            }
        }
        __syncthreads();

        // ---- S = Q K^T (3 terms) ----
        float sacc[16][4];
#pragma unroll
        for (int i = 0; i < 16; i++)
#pragma unroll
            for (int j = 0; j < 4; j++) sacc[i][j] = 0.f;

#pragma unroll
        for (int ks = 0; ks < 4; ks++) {
            uint32_t ch = (uint32_t)(ks * 2 + (lane >> 4));
            uint32_t ar = (uint32_t)(w * 16 + (lane & 15));
            uint32_t aoff = ar * 128 + ((ch ^ (ar & 7)) << 4);
            uint32_t qh0, qh1, qh2, qh3, qm0, qm1, qm2, qm3;
            ldsm4(sb + AQH + aoff, qh0, qh1, qh2, qh3);
            ldsm4(sb + AQM + aoff, qm0, qm1, qm2, qm3);
#pragma unroll
            for (int nb = 0; nb < 8; nb++) {
                uint32_t br = (uint32_t)(nb * 16 + (lane & 15));
                uint32_t boff = br * 128 + ((ch ^ (br & 7)) << 4);
                uint32_t kh0, kh1, kh2, kh3, km0, km1, km2, km3;
                ldsm4(sb + AKH + boff, kh0, kh1, kh2, kh3);
                ldsm4(sb + AKM + boff, km0, km1, km2, km3);
                mma16816(sacc[2 * nb + 0], qh0, qh1, qh2, qh3, kh0, kh2);
                mma16816(sacc[2 * nb + 1], qh0, qh1, qh2, qh3, kh1, kh3);
                mma16816(sacc[2 * nb + 0], qh0, qh1, qh2, qh3, km0, km2);
                mma16816(sacc[2 * nb + 1], qh0, qh1, qh2, qh3, km1, km3);
                mma16816(sacc[2 * nb + 0], qm0, qm1, qm2, qm3, kh0, kh2);
                mma16816(sacc[2 * nb + 1], qm0, qm1, qm2, qm3, kh1, kh3);
            }
        }

        // ---- mask, score, exp ----
        {
            int r0g = q0 + w * 16 + (lane >> 2);
            const int* mr0 = mask + (size_t)r0g * NTOK + k0 + (lane & 3) * 2;
            const int* mr1 = mr0 + (size_t)8 * NTOK;
            float ss0 = 0.f, ss1 = 0.f, ls0 = 0.f, ls1 = 0.f;
#pragma unroll
            for (int t = 0; t < 16; t++) {
                int2 m0 = *(const int2*)(mr0 + 8 * t);
                int2 m1 = *(const int2*)(mr1 + 8 * t);
                float g0 = sacc[t][0] * (float)m0.x;
                float g1 = sacc[t][1] * (float)m0.y;
                float g2 = sacc[t][2] * (float)m1.x;
                float g3 = sacc[t][3] * (float)m1.y;
                ss0 += fabsf(g0) + fabsf(g1);
                ss1 += fabsf(g2) + fabsf(g3);
                float p0 = __expf(g0), p1 = __expf(g1);
                float p2 = __expf(g2), p3 = __expf(g3);
                ls0 += p0 + p1; ls1 += p2 + p3;
                sacc[t][0] = p0; sacc[t][1] = p1;
                sacc[t][2] = p2; sacc[t][3] = p3;
            }
            scd0 += (double)ss0; scd1 += (double)ss1;
            l0 += ls0; l1 += ls1;
        }

        // ---- O += P V (3 terms) ----
#pragma unroll
        for (int ks = 0; ks < 8; ks++) {
            float* e = sacc[2 * ks];
            float* o = sacc[2 * ks + 1];
            uint32_t ah0 = packbf2(e[0], e[1]);
            uint32_t ah1 = packbf2(e[2], e[3]);
            uint32_t ah2 = packbf2(o[0], o[1]);
            uint32_t ah3 = packbf2(o[2], o[3]);
            uint32_t am0 = packbf2(e[0] - bflo(ah0), e[1] - bfhi(ah0));
            uint32_t am1 = packbf2(e[2] - bflo(ah1), e[3] - bfhi(ah1));
            uint32_t am2 = packbf2(o[0] - bflo(ah2), o[1] - bfhi(ah2));
            uint32_t am3 = packbf2(o[2] - bflo(ah3), o[3] - bfhi(ah3));
            uint32_t ch = (uint32_t)(ks * 2 + (lane >> 4));
#pragma unroll
            for (int nd = 0; nd < 4; nd++) {
                uint32_t br = (uint32_t)(nd * 16 + (lane & 15));
                uint32_t boff = br * 256 + ((ch ^ (br & 7)) << 4);
                uint32_t vh0, vh1, vh2, vh3, vm0, vm1, vm2, vm3;
                ldsm4(sb + AVH + boff, vh0, vh1, vh2, vh3);
                ldsm4(sb + AVM + boff, vm0, vm1, vm2, vm3);
                mma16816(oacc[2 * nd + 0], ah0, ah1, ah2, ah3, vh0, vh2);
                mma16816(oacc[2 * nd + 1], ah0, ah1, ah2, ah3, vh1, vh3);
                mma16816(oacc[2 * nd + 0], ah0, ah1, ah2, ah3, vm0, vm2);
                mma16816(oacc[2 * nd + 1], ah0, ah1, ah2, ah3, vm1, vm3);
                mma16816(oacc[2 * nd + 0], am0, am1, am2, am3, vh0, vh2);
                mma16816(oacc[2 * nd + 1], am0, am1, am2, am3, vh1, vh3);
            }
        }
    }

    // ---- epilogue ----
    l0 += __shfl_xor_sync(0xffffffffu, l0, 1);
    l0 += __shfl_xor_sync(0xffffffffu, l0, 2);
    l1 += __shfl_xor_sync(0xffffffffu, l1, 1);
    l1 += __shfl_xor_sync(0xffffffffu, l1, 2);
    scd0 += __shfl_xor_sync(0xffffffffu, scd0, 1);
    scd0 += __shfl_xor_sync(0xffffffffu, scd0, 2);
    scd1 += __shfl_xor_sync(0xffffffffu, scd1, 1);
    scd1 += __shfl_xor_sync(0xffffffffu, scd1, 2);
    float inv0 = 1.0f / l0, inv1 = 1.0f / l1;

    int r0 = q0 + w * 16 + (lane >> 2);
    int r1 = r0 + 8;
#pragma unroll
    for (int t = 0; t < 8; t++) {
        int col = h * DHE + 8 * t + (lane & 3) * 2;
        *(float2*)&g_attn[(size_t)(b * NTOK + r0) * DINNER + col] =
            make_float2(oacc[t][0] * inv0, oacc[t][1] * inv0);
        *(float2*)&g_attn[(size_t)(b * NTOK + r1) * DINNER + col] =
            make_float2(oacc[t][2] * inv1, oacc[t][3] * inv1);
    }
    if ((lane & 3) == 0) {
        atomicAdd(&g_score[b * NTOK + r0], scd0);
        atomicAdd(&g_score[b * NTOK + r1], scd1);
    }
}

// ---------------- sort + swap map ------------------------------------------------
__global__ __launch_bounds__(1024) void sort_swap_kernel(const int* __restrict__ patches)
{
    int bb = blockIdx.x;
    int t = threadIdx.x;
    __shared__ double sval[NTOK];
    __shared__ int sidx[NTOK];
    sval[t] = g_score[bb * NTOK + t] / (double)g_nnz[t];
    sidx[t] = t;
    __syncthreads();

    for (int k = 2; k <= NTOK; k <<= 1) {
        for (int j = k >> 1; j > 0; j >>= 1) {
            int ixj = t ^ j;
            if (ixj > t) {
                double v1 = sval[t], v2 = sval[ixj];
                int i1 = sidx[t], i2 = sidx[ixj];
                bool gt = (v1 > v2) || (v1 == v2 && i1 > i2);
                bool up = ((t & k) == 0);
                if (gt == up) {
                    sval[t] = v2; sval[ixj] = v1;
                    sidx[t] = i2; sidx[ixj] = i1;
                }
            }
            __syncthreads();
        }
    }

    int bo = (BSZ - 1) - bb;
    g_src[bo * NTOK + t] = t;
    __syncthreads();
    if (t == 0) {
        int P = patches[0];
        for (int i = 1; i <= P; i++) {
            int ti = sidx[i];
            g_src[bo * NTOK + i] = ti;
            g_src[bo * NTOK + ti] = i;
        }
    }
}

// ---------------- launch -----------------------------------------------------------
extern "C" void kernel_launch(void* const* d_in, const int* in_sizes, int n_in,
                              void* d_out, int out_size)
{
    const float* x       = (const float*)d_in[0];
    const int*   cp_mask = (const int*)d_in[1];
    const float* w_qkv   = (const float*)d_in[2];
    const float* w_out   = (const float*)d_in[3];
    const float* b_out   = (const float*)d_in[4];
    const int*   patches = (const int*)d_in[5];
    float* out = (float*)d_out;

    cudaFuncSetAttribute(gemm_mma_kernel, cudaFuncAttributeMaxDynamicSharedMemorySize, GEMM_SMEM);
    cudaFuncSetAttribute(attn_mma_kernel, cudaFuncAttributeMaxDynamicSharedMemorySize, ATT_SMEM);

    zero_score_kernel<<<32, 256>>>();
    nnz_kernel<<<NTOK, 256>>>(cp_mask);
    cvt_split3_kernel<<<(BSZ * NTOK * DMODEL) / 512, 512>>>(x, 0, BSZ * NTOK * DMODEL);
    transpose_split3_kernel<<<dim3(QKV3 / 32, DMODEL / 32), dim3(32, 8)>>>(w_qkv, 0, DMODEL, QKV3);
    transpose_split3_kernel<<<dim3(DMODEL / 32, DINNER / 32), dim3(32, 8)>>>(w_out, 1, DINNER, DMODEL);
    gemm_mma_kernel<<<dim3(QKV3 / 128, (BSZ * NTOK) / 128), 256, GEMM_SMEM>>>(0, nullptr, nullptr);
    attn_mma_kernel<<<dim3(8, NH, BSZ), 256, ATT_SMEM>>>(cp_mask);
    sort_swap_kernel<<<BSZ, 1024>>>(patches);
    cvt_split3_kernel<<<(BSZ * NTOK * DINNER) / 512, 512>>>(nullptr, 1, BSZ * NTOK * DINNER);
    gemm_mma_kernel<<<dim3(DMODEL / 128, (BSZ * NTOK) / 128), 256, GEMM_SMEM>>>(1, out, b_out);
}

// round 12
// speedup vs baseline: 2.1298x; 1.0679x over previous
#include <cuda_runtime.h>
#include <cuda_bf16.h>
#include <math.h>
#include <stdint.h>

#define BSZ    8
#define NTOK   1024
#define DMODEL 512
#define QKV3   1536
#define NH     8
#define DHE    64
#define DINNER 512
#define ASCALE 0.125f
typedef unsigned long long u64;

// ---------------- scratch (device globals; referenced ONLY from device code) --
__device__ float  g_qkv[BSZ * NTOK * QKV3];
__device__ float  g_attn[BSZ * NTOK * DINNER];
__device__ double g_score[BSZ * NTOK];
__device__ float  g_nnz[NTOK];
__device__ int    g_src[BSZ * NTOK];
// bf16 hi/mid of [Q*0.125 | K] (cols 0..1023 of qkv), row pitch 1024
__device__ __align__(16) __nv_bfloat16 g_qkvh[BSZ*NTOK*1024], g_qkvm[BSZ*NTOK*1024];
// V transposed per (b,h): [64 d][1024 tok] bf16 hi/mid
__device__ __align__(16) __nv_bfloat16 g_vth[BSZ*NH*64*1024], g_vtm[BSZ*NH*64*1024];
__device__ __align__(16) __nv_bfloat16 g_xh[BSZ*NTOK*DMODEL], g_xm[BSZ*NTOK*DMODEL], g_xl[BSZ*NTOK*DMODEL];
__device__ __align__(16) __nv_bfloat16 g_ah[BSZ*NTOK*DINNER], g_am[BSZ*NTOK*DINNER], g_al[BSZ*NTOK*DINNER];
__device__ __align__(16) __nv_bfloat16 g_wqh[QKV3*DMODEL], g_wqm[QKV3*DMODEL], g_wql[QKV3*DMODEL];
__device__ __align__(16) __nv_bfloat16 g_woh[DINNER*DMODEL], g_wom[DINNER*DMODEL], g_wol[DINNER*DMODEL];

// ---------------- helpers -------------------------------------------------------
static __device__ __forceinline__ uint32_t smem_to_u32(const void* p) {
    uint32_t a;
    asm("{ .reg .u64 t; cvta.to.shared.u64 t, %1; cvt.u32.u64 %0, t; }" : "=r"(a) : "l"(p));
    return a;
}
static __device__ __forceinline__ void ldsm4(uint32_t addr, uint32_t& r0, uint32_t& r1,
                                             uint32_t& r2, uint32_t& r3) {
    asm volatile("ldmatrix.sync.aligned.m8n8.x4.shared.b16 {%0,%1,%2,%3}, [%4];"
        : "=r"(r0), "=r"(r1), "=r"(r2), "=r"(r3) : "r"(addr));
}
static __device__ __forceinline__ void mma16816(float* c,
    uint32_t a0, uint32_t a1, uint32_t a2, uint32_t a3, uint32_t b0, uint32_t b1) {
    asm volatile("mma.sync.aligned.m16n8k16.row.col.f32.bf16.bf16.f32 "
        "{%0,%1,%2,%3}, {%4,%5,%6,%7}, {%8,%9}, {%0,%1,%2,%3};"
        : "+f"(c[0]), "+f"(c[1]), "+f"(c[2]), "+f"(c[3])
        : "r"(a0), "r"(a1), "r"(a2), "r"(a3), "r"(b0), "r"(b1));
}
static __device__ __forceinline__ uint32_t packbf2(float lo, float hi) {
    uint32_t r;
    asm("cvt.rn.bf16x2.f32 %0, %1, %2;" : "=r"(r) : "f"(hi), "f"(lo));
    return r;
}
static __device__ __forceinline__ float bflo(uint32_t p) { return __uint_as_float(p << 16); }
static __device__ __forceinline__ float bfhi(uint32_t p) { return __uint_as_float(p & 0xffff0000u); }
static __device__ __forceinline__ u64 pack4bf(float v0, float v1, float v2, float v3) {
    uint32_t p0 = packbf2(v0, v1), p1 = packbf2(v2, v3);
    u64 r; asm("mov.b64 %0,{%1,%2};" : "=l"(r) : "r"(p0), "r"(p1)); return r;
}
#define CP_ASYNC16(dst, src) \
    asm volatile("cp.async.cg.shared.global [%0], [%1], 16;" :: "r"(dst), "l"(src) : "memory")
#define CP_COMMIT() asm volatile("cp.async.commit_group;" ::: "memory")
#define CP_WAIT(n)  asm volatile("cp.async.wait_group %0;" :: "n"(n) : "memory")

// ---------------- small kernels -------------------------------------------------
__global__ void zero_score_kernel() {
    int i = blockIdx.x * blockDim.x + threadIdx.x;
    if (i < BSZ * NTOK) g_score[i] = 0.0;
}
__global__ void nnz_kernel(const int* __restrict__ mask) {
    int row = blockIdx.x, t = threadIdx.x;
    int cnt = 0;
    for (int c = t; c < NTOK; c += 256) cnt += (mask[row * NTOK + c] != 0);
    for (int o = 16; o; o >>= 1) cnt += __shfl_xor_sync(0xffffffffu, cnt, o);
    __shared__ int sred[8];
    if ((t & 31) == 0) sred[t >> 5] = cnt;
    __syncthreads();
    if (t == 0) {
        int s = 0;
        for (int i = 0; i < 8; i++) s += sred[i];
        g_nnz[row] = (float)s;
    }
}
__global__ void cvt_split3_kernel(const float* __restrict__ xsrc, int sel, int n)
{
    int i = blockIdx.x * blockDim.x + threadIdx.x;
    if (i >= n) return;
    const float* src = sel ? g_attn : xsrc;
    __nv_bfloat16 *h = sel ? g_ah : g_xh;
    __nv_bfloat16 *m = sel ? g_am : g_xm;
    __nv_bfloat16 *l = sel ? g_al : g_xl;
    float v = src[i];
    __nv_bfloat16 hh = __float2bfloat16(v);
    float r1 = v - __bfloat162float(hh);
    __nv_bfloat16 mm = __float2bfloat16(r1);
    float r2 = r1 - __bfloat162float(mm);
    h[i] = hh; m[i] = mm; l[i] = __float2bfloat16(r2);
}
__global__ void transpose_split3_kernel(const float* __restrict__ src, int sel,
                                        int K, int N)
{
    __shared__ float t[32][33];
    __nv_bfloat16 *h = sel ? g_woh : g_wqh;
    __nv_bfloat16 *m = sel ? g_wom : g_wqm;
    __nv_bfloat16 *l = sel ? g_wol : g_wql;
    int k0 = blockIdx.y * 32, n0 = blockIdx.x * 32;
    int tx = threadIdx.x, ty = threadIdx.y;
#pragma unroll
    for (int j = 0; j < 32; j += 8)
        t[ty + j][tx] = src[(size_t)(k0 + ty + j) * N + n0 + tx];
    __syncthreads();
#pragma unroll
    for (int j = 0; j < 32; j += 8) {
        float v = t[tx][ty + j];
        int n = n0 + ty + j, k = k0 + tx;
        __nv_bfloat16 hh = __float2bfloat16(v);
        float r1 = v - __bfloat162float(hh);
        __nv_bfloat16 mm = __float2bfloat16(r1);
        float r2 = r1 - __bfloat162float(mm);
        h[(size_t)n * K + k] = hh;
        m[(size_t)n * K + k] = mm;
        l[(size_t)n * K + k] = __float2bfloat16(r2);
    }
}
// V region of g_qkv -> transposed bf16 hi/mid [(b,h)][64 d][1024 tok]
__global__ void cvt_v_kernel()
{
    __shared__ float s[64][132];
    int tb = blockIdx.x, h = blockIdx.y, b = blockIdx.z;
    int tid = threadIdx.x;
    int tok0 = tb * 128;
#pragma unroll
    for (int l = 0; l < 8; l++) {
        int idx = tid + l * 256;
        int tok = idx >> 4, d4 = idx & 15;
        float4 v = *(const float4*)&g_qkv[(size_t)(b * NTOK + tok0 + tok) * QKV3 + 1024 + h * DHE + d4 * 4];
        s[d4 * 4 + 0][tok] = v.x;
        s[d4 * 4 + 1][tok] = v.y;
        s[d4 * 4 + 2][tok] = v.z;
        s[d4 * 4 + 3][tok] = v.w;
    }
    __syncthreads();
#pragma unroll
    for (int l = 0; l < 8; l++) {
        int idx = tid + l * 256;
        int d = idx >> 5, tc = idx & 31;
        float f0 = s[d][tc * 4 + 0], f1 = s[d][tc * 4 + 1];
        float f2 = s[d][tc * 4 + 2], f3 = s[d][tc * 4 + 3];
        u64 hh = pack4bf(f0, f1, f2, f3);
        uint32_t hl = (uint32_t)hh, hu = (uint32_t)(hh >> 32);
        u64 mm = pack4bf(f0 - bflo(hl), f1 - bfhi(hl), f2 - bflo(hu), f3 - bfhi(hu));
        size_t off = ((size_t)(b * NH + h) * 64 + d) * 1024 + tok0 + tc * 4;
        *(u64*)&g_vth[off] = hh;
        *(u64*)&g_vtm[off] = mm;
    }
}

// ---------------- HMMA GEMM (bf16 3-way split, hoisted A fragments) -------------
#define TILE_B 16384
#define SMG_HDR 1024
#define GEMM_SMEM (SMG_HDR + 6 * TILE_B)

__global__ __launch_bounds__(256, 2) void gemm_mma_kernel(
    int sel, float* __restrict__ OutX, const float* __restrict__ bias)
{
    extern __shared__ char smg[];
    uint32_t sb = smem_to_u32(smg);
    int tid = threadIdx.x, lane = tid & 31, wid = tid >> 5;
    int wm = wid & 3, wn = wid >> 2;
    int bm = blockIdx.y * 128, bn = blockIdx.x * 128;

    const uint4 *A0, *A1, *A2, *B0, *B1, *B2;
    float* Out; int Nt;
    if (sel) {
        A0 = (const uint4*)g_ah;  A1 = (const uint4*)g_am;  A2 = (const uint4*)g_al;
        B0 = (const uint4*)g_woh; B1 = (const uint4*)g_wom; B2 = (const uint4*)g_wol;
        Out = OutX; Nt = DMODEL;
    } else {
        A0 = (const uint4*)g_xh;  A1 = (const uint4*)g_xm;  A2 = (const uint4*)g_xl;
        B0 = (const uint4*)g_wqh; B1 = (const uint4*)g_wqm; B2 = (const uint4*)g_wql;
        Out = g_qkv; Nt = QKV3;
    }
    int* rmap = (int*)smg;
    float* sbias = (float*)(smg + 512);
    if (tid < 128) {
        int row = bm + tid;
        rmap[tid] = sel ? ((row & ~(NTOK - 1)) + g_src[row]) : row;
        sbias[tid] = sel ? bias[bn + tid] : 0.f;
    }

    float acc[16][4];
#pragma unroll
    for (int i = 0; i < 16; i++)
#pragma unroll
        for (int j = 0; j < 4; j++) acc[i][j] = 0.f;

#pragma unroll 1
    for (int c = 0; c < 8; c++) {
        __syncthreads();
#pragma unroll
        for (int l = 0; l < 4; l++) {
            int idx = tid + l * 256;
            int r = idx >> 3, q = idx & 7;
            uint32_t so = (uint32_t)(r * 128 + ((q ^ (r & 7)) << 4));
            size_t ga = (size_t)rmap[r] * 64 + c * 8 + q;
            size_t gb = (size_t)(bn + r) * 64 + c * 8 + q;
            *(uint4*)(smg + SMG_HDR + 0 * TILE_B + so) = A0[ga];
            *(uint4*)(smg + SMG_HDR + 1 * TILE_B + so) = A1[ga];
            *(uint4*)(smg + SMG_HDR + 2 * TILE_B + so) = A2[ga];
            *(uint4*)(smg + SMG_HDR + 3 * TILE_B + so) = B0[gb];
            *(uint4*)(smg + SMG_HDR + 4 * TILE_B + so) = B1[gb];
            *(uint4*)(smg + SMG_HDR + 5 * TILE_B + so) = B2[gb];
        }
        __syncthreads();

#pragma unroll
        for (int ks = 0; ks < 4; ks++) {
            uint32_t ch = (uint32_t)(ks * 2 + (lane >> 4));
            uint32_t ar0 = (uint32_t)(wm * 32 + (lane & 15));
            uint32_t ar1 = ar0 + 16;
            uint32_t aoff0 = ar0 * 128 + ((ch ^ (ar0 & 7)) << 4);
            uint32_t aoff1 = ar1 * 128 + ((ch ^ (ar1 & 7)) << 4);
            uint32_t boff[4];
#pragma unroll
            for (int nb = 0; nb < 4; nb++) {
                uint32_t br = (uint32_t)(wn * 64 + nb * 16 + (lane & 15));
                boff[nb] = br * 128 + ((ch ^ (br & 7)) << 4);
            }
            uint32_t Af[3][8];
#pragma unroll
            for (int s = 0; s < 3; s++) {
                ldsm4(sb + SMG_HDR + s * TILE_B + aoff0, Af[s][0], Af[s][1], Af[s][2], Af[s][3]);
                ldsm4(sb + SMG_HDR + s * TILE_B + aoff1, Af[s][4], Af[s][5], Af[s][6], Af[s][7]);
            }
#pragma unroll
            for (int bs = 0; bs < 3; bs++) {
                uint32_t bbase = sb + SMG_HDR + (3 + bs) * TILE_B;
#pragma unroll
                for (int nb = 0; nb < 4; nb++) {
                    uint32_t b0, b1, b2, b3;
                    ldsm4(bbase + boff[nb], b0, b1, b2, b3);
#pragma unroll
                    for (int s = 0; s < 3; s++) {
                        if (s + bs <= 2) {
                            mma16816(acc[nb * 2 + 0],     Af[s][0], Af[s][1], Af[s][2], Af[s][3], b0, b2);
                            mma16816(acc[nb * 2 + 1],     Af[s][0], Af[s][1], Af[s][2], Af[s][3], b1, b3);
                            mma16816(acc[8 + nb * 2 + 0], Af[s][4], Af[s][5], Af[s][6], Af[s][7], b0, b2);
                            mma16816(acc[8 + nb * 2 + 1], Af[s][4], Af[s][5], Af[s][6], Af[s][7], b1, b3);
                        }
                    }
                }
            }
        }
    }

    // ---- epilogue (+bias); sel==0 also emits bf16 hi/mid of [Q*0.125 | K] ----
#pragma unroll
    for (int ma = 0; ma < 2; ma++) {
        int row = bm + wm * 32 + ma * 16 + (lane >> 2);
#pragma unroll
        for (int na = 0; na < 8; na++) {
            int colr = wn * 64 + na * 8 + (lane & 3) * 2;
            int col = bn + colr;
            float* a = acc[ma * 8 + na];
            float2 v0 = make_float2(a[0] + sbias[colr], a[1] + sbias[colr + 1]);
            float2 v1 = make_float2(a[2] + sbias[colr], a[3] + sbias[colr + 1]);
            *(float2*)&Out[(size_t)row * Nt + col] = v0;
            *(float2*)&Out[(size_t)(row + 8) * Nt + col] = v1;
            if (!sel && col < 1024) {
                float sc = (col < 512) ? ASCALE : 1.f;
                float u0 = v0.x * sc, u1 = v0.y * sc;
                float w0 = v1.x * sc, w1 = v1.y * sc;
                uint32_t h0 = packbf2(u0, u1), h1 = packbf2(w0, w1);
                uint32_t m0 = packbf2(u0 - bflo(h0), u1 - bfhi(h0));
                uint32_t m1 = packbf2(w0 - bflo(h1), w1 - bfhi(h1));
                *(uint32_t*)&g_qkvh[(size_t)row * 1024 + col] = h0;
                *(uint32_t*)&g_qkvm[(size_t)row * 1024 + col] = m0;
                *(uint32_t*)&g_qkvh[(size_t)(row + 8) * 1024 + col] = h1;
                *(uint32_t*)&g_qkvm[(size_t)(row + 8) * 1024 + col] = m1;
            }
        }
    }
}

// ---------------- HMMA flash attention (cp.async pipelined) ---------------------
// Q: 2x16KB persistent. Per-kt buffer: KH 16K | KM 16K | VH 16K | VM 16K = 64KB, x2.
#define AQH 0
#define AQM 16384
#define ABUF 32768
#define BUF_SZ 65536
#define ATT_SMEM (ABUF + 2 * BUF_SZ)

__global__ __launch_bounds__(256, 1) void attn_mma_kernel(const int* __restrict__ mask)
{
    extern __shared__ char sma[];
    uint32_t sb = smem_to_u32(sma);
    int tid = threadIdx.x, lane = tid & 31, w = tid >> 5;
    int qt = blockIdx.x, h = blockIdx.y, b = blockIdx.z;
    int q0 = qt * 128;

    // ---- Q tiles via cp.async (group 0) ----
#pragma unroll
    for (int l = 0; l < 8; l++) {
        int idx = tid + l * 256;
        int ts = idx >> 10;
        int rem = idx & 1023;
        int r = rem >> 3, q = rem & 7;
        const __nv_bfloat16* src = (ts ? g_qkvm : g_qkvh) +
            (((size_t)(b * NTOK + q0 + r) * 128 + h * 8 + q) << 3);
        uint32_t dst = sb + (ts ? AQM : AQH) + (uint32_t)(r * 128 + ((q ^ (r & 7)) << 4));
        CP_ASYNC16(dst, src);
    }
    // ---- kv tile loader ----
    auto issue_kv = [&](int kt, int buf) {
        int k0 = kt * 128;
        uint32_t bb = sb + ABUF + buf * BUF_SZ;
#pragma unroll
        for (int l = 0; l < 16; l++) {
            int idx = tid + l * 256;
            if (idx < 2048) {             // K hi/mid: [128 r][64 d]
                int ts = idx >> 10;
                int rem = idx & 1023;
                int r = rem >> 3, q = rem & 7;
                const __nv_bfloat16* src = (ts ? g_qkvm : g_qkvh) +
                    (((size_t)(b * NTOK + k0 + r) * 128 + 64 + h * 8 + q) << 3);
                uint32_t dst = bb + ts * 16384 + (uint32_t)(r * 128 + ((q ^ (r & 7)) << 4));
                CP_ASYNC16(dst, src);
            } else {                      // V hi/mid: [64 d][128 tok]
                int idx2 = idx - 2048;
                int ts = idx2 >> 10;
                int rem = idx2 & 1023;
                int d = rem >> 4, c = rem & 15;
                const __nv_bfloat16* src = (ts ? g_vtm : g_vth) +
                    ((((size_t)(b * NH + h) * 64 + d) * 128 + (k0 >> 3) + c) << 3);
                uint32_t dst = bb + 32768 + ts * 16384 + (uint32_t)(d * 256 + ((c ^ (d & 7)) << 4));
                CP_ASYNC16(dst, src);
            }
        }
    };
    issue_kv(0, 0);
    CP_COMMIT();

    float oacc[8][4];
#pragma unroll
    for (int i = 0; i < 8; i++)
#pragma unroll
        for (int j = 0; j < 4; j++) oacc[i][j] = 0.f;
    float l0 = 0.f, l1 = 0.f;
    double scd0 = 0.0, scd1 = 0.0;
    int buf = 0;

#pragma unroll 1
    for (int kt = 0; kt < 8; kt++) {
        int k0 = kt * 128;
        if (kt < 7) { issue_kv(kt + 1, buf ^ 1); CP_COMMIT(); CP_WAIT(1); }
        else        { CP_WAIT(0); }
        __syncthreads();

        uint32_t KH = sb + ABUF + buf * BUF_SZ;
        uint32_t KM = KH + 16384;
        uint32_t VH = KH + 32768;
        uint32_t VM = KH + 49152;

        // ---- S = Q K^T (3 terms) ----
        float sacc[16][4];
#pragma unroll
        for (int i = 0; i < 16; i++)
#pragma unroll
            for (int j = 0; j < 4; j++) sacc[i][j] = 0.f;

#pragma unroll
        for (int ks = 0; ks < 4; ks++) {
            uint32_t ch = (uint32_t)(ks * 2 + (lane >> 4));
            uint32_t ar = (uint32_t)(w * 16 + (lane & 15));
            uint32_t aoff = ar * 128 + ((ch ^ (ar & 7)) << 4);
            uint32_t qh0, qh1, qh2, qh3, qm0, qm1, qm2, qm3;
            ldsm4(sb + AQH + aoff, qh0, qh1, qh2, qh3);
            ldsm4(sb + AQM + aoff, qm0, qm1, qm2, qm3);
#pragma unroll
            for (int nb = 0; nb < 8; nb++) {
                uint32_t br = (uint32_t)(nb * 16 + (lane & 15));
                uint32_t boff = br * 128 + ((ch ^ (br & 7)) << 4);
                uint32_t kh0, kh1, kh2, kh3, km0, km1, km2, km3;
                ldsm4(KH + boff, kh0, kh1, kh2, kh3);
                ldsm4(KM + boff, km0, km1, km2, km3);
                mma16816(sacc[2 * nb + 0], qh0, qh1, qh2, qh3, kh0, kh2);
                mma16816(sacc[2 * nb + 1], qh0, qh1, qh2, qh3, kh1, kh3);
                mma16816(sacc[2 * nb + 0], qh0, qh1, qh2, qh3, km0, km2);
                mma16816(sacc[2 * nb + 1], qh0, qh1, qh2, qh3, km1, km3);
                mma16816(sacc[2 * nb + 0], qm0, qm1, qm2, qm3, kh0, kh2);
                mma16816(sacc[2 * nb + 1], qm0, qm1, qm2, qm3, kh1, kh3);
            }
        }

        // ---- mask, score, exp ----
        {
            int r0g = q0 + w * 16 + (lane >> 2);
            const int* mr0 = mask + (size_t)r0g * NTOK + k0 + (lane & 3) * 2;
            const int* mr1 = mr0 + (size_t)8 * NTOK;
            float ss0 = 0.f, ss1 = 0.f, ls0 = 0.f, ls1 = 0.f;
#pragma unroll
            for (int t = 0; t < 16; t++) {
                int2 m0 = *(const int2*)(mr0 + 8 * t);
                int2 m1 = *(const int2*)(mr1 + 8 * t);
                float g0 = sacc[t][0] * (float)m0.x;
                float g1 = sacc[t][1] * (float)m0.y;
                float g2 = sacc[t][2] * (float)m1.x;
                float g3 = sacc[t][3] * (float)m1.y;
                ss0 += fabsf(g0) + fabsf(g1);
                ss1 += fabsf(g2) + fabsf(g3);
                float p0 = __expf(g0), p1 = __expf(g1);
                float p2 = __expf(g2), p3 = __expf(g3);
                ls0 += p0 + p1; ls1 += p2 + p3;
                sacc[t][0] = p0; sacc[t][1] = p1;
                sacc[t][2] = p2; sacc[t][3] = p3;
            }
            scd0 += (double)ss0; scd1 += (double)ss1;
            l0 += ls0; l1 += ls1;
        }

        // ---- O += P V (3 terms) ----
#pragma unroll
        for (int ks = 0; ks < 8; ks++) {
            float* e = sacc[2 * ks];
            float* o = sacc[2 * ks + 1];
            uint32_t ah0 = packbf2(e[0], e[1]);
            uint32_t ah1 = packbf2(e[2], e[3]);
            uint32_t ah2 = packbf2(o[0], o[1]);
            uint32_t ah3 = packbf2(o[2], o[3]);
            uint32_t am0 = packbf2(e[0] - bflo(ah0), e[1] - bfhi(ah0));
            uint32_t am1 = packbf2(e[2] - bflo(ah1), e[3] - bfhi(ah1));
            uint32_t am2 = packbf2(o[0] - bflo(ah2), o[1] - bfhi(ah2));
            uint32_t am3 = packbf2(o[2] - bflo(ah3), o[3] - bfhi(ah3));
            uint32_t ch = (uint32_t)(ks * 2 + (lane >> 4));
#pragma unroll
            for (int nd = 0; nd < 4; nd++) {
                uint32_t br = (uint32_t)(nd * 16 + (lane & 15));
                uint32_t boff = br * 256 + ((ch ^ (br & 7)) << 4);
                uint32_t vh0, vh1, vh2, vh3, vm0, vm1, vm2, vm3;
                ldsm4(VH + boff, vh0, vh1, vh2, vh3);
                ldsm4(VM + boff, vm0, vm1, vm2, vm3);
                mma16816(oacc[2 * nd + 0], ah0, ah1, ah2, ah3, vh0, vh2);
                mma16816(oacc[2 * nd + 1], ah0, ah1, ah2, ah3, vh1, vh3);
                mma16816(oacc[2 * nd + 0], ah0, ah1, ah2, ah3, vm0, vm2);
                mma16816(oacc[2 * nd + 1], ah0, ah1, ah2, ah3, vm1, vm3);
                mma16816(oacc[2 * nd + 0], am0, am1, am2, am3, vh0, vh2);
                mma16816(oacc[2 * nd + 1], am0, am1, am2, am3, vh1, vh3);
            }
        }
        __syncthreads();
        buf ^= 1;
    }

    // ---- epilogue ----
    l0 += __shfl_xor_sync(0xffffffffu, l0, 1);
    l0 += __shfl_xor_sync(0xffffffffu, l0, 2);
    l1 += __shfl_xor_sync(0xffffffffu, l1, 1);
    l1 += __shfl_xor_sync(0xffffffffu, l1, 2);
    scd0 += __shfl_xor_sync(0xffffffffu, scd0, 1);
    scd0 += __shfl_xor_sync(0xffffffffu, scd0, 2);
    scd1 += __shfl_xor_sync(0xffffffffu, scd1, 1);
    scd1 += __shfl_xor_sync(0xffffffffu, scd1, 2);
    float inv0 = 1.0f / l0, inv1 = 1.0f / l1;

    int r0 = q0 + w * 16 + (lane >> 2);
    int r1 = r0 + 8;
#pragma unroll
    for (int t = 0; t < 8; t++) {
        int col = h * DHE + 8 * t + (lane & 3) * 2;
        *(float2*)&g_attn[(size_t)(b * NTOK + r0) * DINNER + col] =
            make_float2(oacc[t][0] * inv0, oacc[t][1] * inv0);
        *(float2*)&g_attn[(size_t)(b * NTOK + r1) * DINNER + col] =
            make_float2(oacc[t][2] * inv1, oacc[t][3] * inv1);
    }
    if ((lane & 3) == 0) {
        atomicAdd(&g_score[b * NTOK + r0], scd0);
        atomicAdd(&g_score[b * NTOK + r1], scd1);
    }
}

// ---------------- sort + swap map ------------------------------------------------
__global__ __launch_bounds__(1024) void sort_swap_kernel(const int* __restrict__ patches)
{
    int bb = blockIdx.x;
    int t = threadIdx.x;
    __shared__ double sval[NTOK];
    __shared__ int sidx[NTOK];
    sval[t] = g_score[bb * NTOK + t] / (double)g_nnz[t];
    sidx[t] = t;
    __syncthreads();

    for (int k = 2; k <= NTOK; k <<= 1) {
        for (int j = k >> 1; j > 0; j >>= 1) {
            int ixj = t ^ j;
            if (ixj > t) {
                double v1 = sval[t], v2 = sval[ixj];
                int i1 = sidx[t], i2 = sidx[ixj];
                bool gt = (v1 > v2) || (v1 == v2 && i1 > i2);
                bool up = ((t & k) == 0);
                if (gt == up) {
                    sval[t] = v2; sval[ixj] = v1;
                    sidx[t] = i2; sidx[ixj] = i1;
                }
            }
            __syncthreads();
        }
    }

    int bo = (BSZ - 1) - bb;
    g_src[bo * NTOK + t] = t;
    __syncthreads();
    if (t == 0) {
        int P = patches[0];
        for (int i = 1; i <= P; i++) {
            int ti = sidx[i];
            g_src[bo * NTOK + i] = ti;
            g_src[bo * NTOK + ti] = i;
        }
    }
}

// ---------------- launch -----------------------------------------------------------
extern "C" void kernel_launch(void* const* d_in, const int* in_sizes, int n_in,
                              void* d_out, int out_size)
{
    const float* x       = (const float*)d_in[0];
    const int*   cp_mask = (const int*)d_in[1];
    const float* w_qkv   = (const float*)d_in[2];
    const float* w_out   = (const float*)d_in[3];
    const float* b_out   = (const float*)d_in[4];
    const int*   patches = (const int*)d_in[5];
    float* out = (float*)d_out;

    cudaFuncSetAttribute(gemm_mma_kernel, cudaFuncAttributeMaxDynamicSharedMemorySize, GEMM_SMEM);
    cudaFuncSetAttribute(attn_mma_kernel, cudaFuncAttributeMaxDynamicSharedMemorySize, ATT_SMEM);

    zero_score_kernel<<<32, 256>>>();
    nnz_kernel<<<NTOK, 256>>>(cp_mask);
    cvt_split3_kernel<<<(BSZ * NTOK * DMODEL) / 512, 512>>>(x, 0, BSZ * NTOK * DMODEL);
    transpose_split3_kernel<<<dim3(QKV3 / 32, DMODEL / 32), dim3(32, 8)>>>(w_qkv, 0, DMODEL, QKV3);
    transpose_split3_kernel<<<dim3(DMODEL / 32, DINNER / 32), dim3(32, 8)>>>(w_out, 1, DINNER, DMODEL);
    gemm_mma_kernel<<<dim3(QKV3 / 128, (BSZ * NTOK) / 128), 256, GEMM_SMEM>>>(0, nullptr, nullptr);
    cvt_v_kernel<<<dim3(8, NH, BSZ), 256>>>();
    attn_mma_kernel<<<dim3(8, NH, BSZ), 256, ATT_SMEM>>>(cp_mask);
    sort_swap_kernel<<<BSZ, 1024>>>(patches);
    cvt_split3_kernel<<<(BSZ * NTOK * DINNER) / 512, 512>>>(nullptr, 1, BSZ * NTOK * DINNER);
    gemm_mma_kernel<<<dim3(DMODEL / 128, (BSZ * NTOK) / 128), 256, GEMM_SMEM>>>(1, out, b_out);
}

// round 13
// speedup vs baseline: 2.3959x; 1.1249x over previous
#include <cuda_runtime.h>
#include <cuda_bf16.h>
#include <math.h>
#include <stdint.h>

#define BSZ    8
#define NTOK   1024
#define DMODEL 512
#define QKV3   1536
#define NH     8
#define DHE    64
#define DINNER 512
#define ASCALE 0.125f
typedef unsigned long long u64;

// ---------------- scratch (device globals; referenced ONLY from device code) --
__device__ float  g_qkv[BSZ * NTOK * QKV3];
__device__ double g_score[BSZ * NTOK];
__device__ float  g_nnz[NTOK];
__device__ int    g_src[BSZ * NTOK];
// bf16 hi/mid of [Q*0.125 | K] (cols 0..1023 of qkv), row pitch 1024
__device__ __align__(16) __nv_bfloat16 g_qkvh[BSZ*NTOK*1024], g_qkvm[BSZ*NTOK*1024];
// V transposed per (b,h): [64 d][1024 tok] bf16 hi/mid
__device__ __align__(16) __nv_bfloat16 g_vth[BSZ*NH*64*1024], g_vtm[BSZ*NH*64*1024];
__device__ __align__(16) __nv_bfloat16 g_xh[BSZ*NTOK*DMODEL], g_xm[BSZ*NTOK*DMODEL], g_xl[BSZ*NTOK*DMODEL];
// attn output, bf16 hi/mid (written directly by attn epilogue)
__device__ __align__(16) __nv_bfloat16 g_ah[BSZ*NTOK*DINNER], g_am[BSZ*NTOK*DINNER];
__device__ __align__(16) __nv_bfloat16 g_wqh[QKV3*DMODEL], g_wqm[QKV3*DMODEL], g_wql[QKV3*DMODEL];
__device__ __align__(16) __nv_bfloat16 g_woh[DINNER*DMODEL], g_wom[DINNER*DMODEL], g_wol[DINNER*DMODEL];

// ---------------- helpers -------------------------------------------------------
static __device__ __forceinline__ uint32_t smem_to_u32(const void* p) {
    uint32_t a;
    asm("{ .reg .u64 t; cvta.to.shared.u64 t, %1; cvt.u32.u64 %0, t; }" : "=r"(a) : "l"(p));
    return a;
}
static __device__ __forceinline__ void ldsm4(uint32_t addr, uint32_t& r0, uint32_t& r1,
                                             uint32_t& r2, uint32_t& r3) {
    asm volatile("ldmatrix.sync.aligned.m8n8.x4.shared.b16 {%0,%1,%2,%3}, [%4];"
        : "=r"(r0), "=r"(r1), "=r"(r2), "=r"(r3) : "r"(addr));
}
static __device__ __forceinline__ void mma16816(float* c,
    uint32_t a0, uint32_t a1, uint32_t a2, uint32_t a3, uint32_t b0, uint32_t b1) {
    asm volatile("mma.sync.aligned.m16n8k16.row.col.f32.bf16.bf16.f32 "
        "{%0,%1,%2,%3}, {%4,%5,%6,%7}, {%8,%9}, {%0,%1,%2,%3};"
        : "+f"(c[0]), "+f"(c[1]), "+f"(c[2]), "+f"(c[3])
        : "r"(a0), "r"(a1), "r"(a2), "r"(a3), "r"(b0), "r"(b1));
}
static __device__ __forceinline__ uint32_t packbf2(float lo, float hi) {
    uint32_t r;
    asm("cvt.rn.bf16x2.f32 %0, %1, %2;" : "=r"(r) : "f"(hi), "f"(lo));
    return r;
}
static __device__ __forceinline__ float bflo(uint32_t p) { return __uint_as_float(p << 16); }
static __device__ __forceinline__ float bfhi(uint32_t p) { return __uint_as_float(p & 0xffff0000u); }
static __device__ __forceinline__ u64 pack4bf(float v0, float v1, float v2, float v3) {
    uint32_t p0 = packbf2(v0, v1), p1 = packbf2(v2, v3);
    u64 r; asm("mov.b64 %0,{%1,%2};" : "=l"(r) : "r"(p0), "r"(p1)); return r;
}
#define CP_ASYNC16(dst, src) \
    asm volatile("cp.async.cg.shared.global [%0], [%1], 16;" :: "r"(dst), "l"(src) : "memory")
#define CP_COMMIT() asm volatile("cp.async.commit_group;" ::: "memory")
#define CP_WAIT(n)  asm volatile("cp.async.wait_group %0;" :: "n"(n) : "memory")

// ---------------- small kernels -------------------------------------------------
__global__ void zero_score_kernel() {
    int i = blockIdx.x * blockDim.x + threadIdx.x;
    if (i < BSZ * NTOK) g_score[i] = 0.0;
}
__global__ void nnz_kernel(const int* __restrict__ mask) {
    int row = blockIdx.x, t = threadIdx.x;
    int cnt = 0;
    for (int c = t; c < NTOK; c += 256) cnt += (mask[row * NTOK + c] != 0);
    for (int o = 16; o; o >>= 1) cnt += __shfl_xor_sync(0xffffffffu, cnt, o);
    __shared__ int sred[8];
    if ((t & 31) == 0) sred[t >> 5] = cnt;
    __syncthreads();
    if (t == 0) {
        int s = 0;
        for (int i = 0; i < 8; i++) s += sred[i];
        g_nnz[row] = (float)s;
    }
}
__global__ void cvt_split3_kernel(const float* __restrict__ src, int n)
{
    int i = blockIdx.x * blockDim.x + threadIdx.x;
    if (i >= n) return;
    float v = src[i];
    __nv_bfloat16 hh = __float2bfloat16(v);
    float r1 = v - __bfloat162float(hh);
    __nv_bfloat16 mm = __float2bfloat16(r1);
    float r2 = r1 - __bfloat162float(mm);
    g_xh[i] = hh; g_xm[i] = mm; g_xl[i] = __float2bfloat16(r2);
}
__global__ void transpose_split3_kernel(const float* __restrict__ src, int sel,
                                        int K, int N)
{
    __shared__ float t[32][33];
    __nv_bfloat16 *h = sel ? g_woh : g_wqh;
    __nv_bfloat16 *m = sel ? g_wom : g_wqm;
    __nv_bfloat16 *l = sel ? g_wol : g_wql;
    int k0 = blockIdx.y * 32, n0 = blockIdx.x * 32;
    int tx = threadIdx.x, ty = threadIdx.y;
#pragma unroll
    for (int j = 0; j < 32; j += 8)
        t[ty + j][tx] = src[(size_t)(k0 + ty + j) * N + n0 + tx];
    __syncthreads();
#pragma unroll
    for (int j = 0; j < 32; j += 8) {
        float v = t[tx][ty + j];
        int n = n0 + ty + j, k = k0 + tx;
        __nv_bfloat16 hh = __float2bfloat16(v);
        float r1 = v - __bfloat162float(hh);
        __nv_bfloat16 mm = __float2bfloat16(r1);
        float r2 = r1 - __bfloat162float(mm);
        h[(size_t)n * K + k] = hh;
        m[(size_t)n * K + k] = mm;
        l[(size_t)n * K + k] = __float2bfloat16(r2);
    }
}
// V region of g_qkv -> transposed bf16 hi/mid [(b,h)][64 d][1024 tok]
__global__ void cvt_v_kernel()
{
    __shared__ float s[64][132];
    int tb = blockIdx.x, h = blockIdx.y, b = blockIdx.z;
    int tid = threadIdx.x;
    int tok0 = tb * 128;
#pragma unroll
    for (int l = 0; l < 8; l++) {
        int idx = tid + l * 256;
        int tok = idx >> 4, d4 = idx & 15;
        float4 v = *(const float4*)&g_qkv[(size_t)(b * NTOK + tok0 + tok) * QKV3 + 1024 + h * DHE + d4 * 4];
        s[d4 * 4 + 0][tok] = v.x;
        s[d4 * 4 + 1][tok] = v.y;
        s[d4 * 4 + 2][tok] = v.z;
        s[d4 * 4 + 3][tok] = v.w;
    }
    __syncthreads();
#pragma unroll
    for (int l = 0; l < 8; l++) {
        int idx = tid + l * 256;
        int d = idx >> 5, tc = idx & 31;
        float f0 = s[d][tc * 4 + 0], f1 = s[d][tc * 4 + 1];
        float f2 = s[d][tc * 4 + 2], f3 = s[d][tc * 4 + 3];
        u64 hh = pack4bf(f0, f1, f2, f3);
        uint32_t hl = (uint32_t)hh, hu = (uint32_t)(hh >> 32);
        u64 mm = pack4bf(f0 - bflo(hl), f1 - bfhi(hl), f2 - bflo(hu), f3 - bfhi(hu));
        size_t off = ((size_t)(b * NH + h) * 64 + d) * 1024 + tok0 + tc * 4;
        *(u64*)&g_vth[off] = hh;
        *(u64*)&g_vtm[off] = mm;
    }
}

// ---------------- HMMA GEMM ------------------------------------------------------
// sel=0: qkv = x @ wq, 3-way split (6 terms). sel=1: out = gather(A) @ wo + bias,
// 2-way split (3 terms). cp.async loads, occ 2.
#define TILE_B 16384
#define SMG_HDR 1024
#define GEMM_SMEM (SMG_HDR + 6 * TILE_B)

__global__ __launch_bounds__(256, 2) void gemm_mma_kernel(
    int sel, float* __restrict__ OutX, const float* __restrict__ bias)
{
    extern __shared__ char smg[];
    uint32_t sb = smem_to_u32(smg);
    int tid = threadIdx.x, lane = tid & 31, wid = tid >> 5;
    int wm = wid & 3, wn = wid >> 2;
    int bm = blockIdx.y * 128, bn = blockIdx.x * 128;

    const uint4 *A0, *A1, *A2, *B0, *B1, *B2;
    float* Out; int Nt;
    if (sel) {
        A0 = (const uint4*)g_ah;  A1 = (const uint4*)g_am;  A2 = A0;
        B0 = (const uint4*)g_woh; B1 = (const uint4*)g_wom; B2 = B0;
        Out = OutX; Nt = DMODEL;
    } else {
        A0 = (const uint4*)g_xh;  A1 = (const uint4*)g_xm;  A2 = (const uint4*)g_xl;
        B0 = (const uint4*)g_wqh; B1 = (const uint4*)g_wqm; B2 = (const uint4*)g_wql;
        Out = g_qkv; Nt = QKV3;
    }
    const int tmax = sel ? 1 : 2;       // max s+bs
    int* rmap = (int*)smg;
    float* sbias = (float*)(smg + 512);
    if (tid < 128) {
        int row = bm + tid;
        rmap[tid] = sel ? ((row & ~(NTOK - 1)) + g_src[row]) : row;
        sbias[tid] = sel ? bias[bn + tid] : 0.f;
    }

    float acc[16][4];
#pragma unroll
    for (int i = 0; i < 16; i++)
#pragma unroll
        for (int j = 0; j < 4; j++) acc[i][j] = 0.f;

#pragma unroll 1
    for (int c = 0; c < 8; c++) {
        __syncthreads();
#pragma unroll
        for (int l = 0; l < 4; l++) {
            int idx = tid + l * 256;
            int r = idx >> 3, q = idx & 7;
            uint32_t so = (uint32_t)(r * 128 + ((q ^ (r & 7)) << 4));
            size_t ga = (size_t)rmap[r] * 64 + c * 8 + q;
            size_t gb = (size_t)(bn + r) * 64 + c * 8 + q;
            CP_ASYNC16(sb + SMG_HDR + 0 * TILE_B + so, A0 + ga);
            CP_ASYNC16(sb + SMG_HDR + 1 * TILE_B + so, A1 + ga);
            CP_ASYNC16(sb + SMG_HDR + 3 * TILE_B + so, B0 + gb);
            CP_ASYNC16(sb + SMG_HDR + 4 * TILE_B + so, B1 + gb);
            if (!sel) {
                CP_ASYNC16(sb + SMG_HDR + 2 * TILE_B + so, A2 + ga);
                CP_ASYNC16(sb + SMG_HDR + 5 * TILE_B + so, B2 + gb);
            }
        }
        CP_COMMIT();
        CP_WAIT(0);
        __syncthreads();

#pragma unroll
        for (int ks = 0; ks < 4; ks++) {
            uint32_t ch = (uint32_t)(ks * 2 + (lane >> 4));
            uint32_t ar0 = (uint32_t)(wm * 32 + (lane & 15));
            uint32_t ar1 = ar0 + 16;
            uint32_t aoff0 = ar0 * 128 + ((ch ^ (ar0 & 7)) << 4);
            uint32_t aoff1 = ar1 * 128 + ((ch ^ (ar1 & 7)) << 4);
            uint32_t boff[4];
#pragma unroll
            for (int nb = 0; nb < 4; nb++) {
                uint32_t br = (uint32_t)(wn * 64 + nb * 16 + (lane & 15));
                boff[nb] = br * 128 + ((ch ^ (br & 7)) << 4);
            }
            uint32_t Af[3][8];
#pragma unroll
            for (int s = 0; s < 3; s++) {
                if (s <= tmax) {
                    ldsm4(sb + SMG_HDR + s * TILE_B + aoff0, Af[s][0], Af[s][1], Af[s][2], Af[s][3]);
                    ldsm4(sb + SMG_HDR + s * TILE_B + aoff1, Af[s][4], Af[s][5], Af[s][6], Af[s][7]);
                }
            }
#pragma unroll
            for (int bs = 0; bs < 3; bs++) {
                if (bs > tmax) continue;
                uint32_t bbase = sb + SMG_HDR + (3 + bs) * TILE_B;
#pragma unroll
                for (int nb = 0; nb < 4; nb++) {
                    uint32_t b0, b1, b2, b3;
                    ldsm4(bbase + boff[nb], b0, b1, b2, b3);
#pragma unroll
                    for (int s = 0; s < 3; s++) {
                        if (s + bs <= tmax) {
                            mma16816(acc[nb * 2 + 0],     Af[s][0], Af[s][1], Af[s][2], Af[s][3], b0, b2);
                            mma16816(acc[nb * 2 + 1],     Af[s][0], Af[s][1], Af[s][2], Af[s][3], b1, b3);
                            mma16816(acc[8 + nb * 2 + 0], Af[s][4], Af[s][5], Af[s][6], Af[s][7], b0, b2);
                            mma16816(acc[8 + nb * 2 + 1], Af[s][4], Af[s][5], Af[s][6], Af[s][7], b1, b3);
                        }
                    }
                }
            }
        }
    }

    // ---- epilogue (+bias); sel==0 also emits bf16 hi/mid of [Q*0.125 | K] ----
#pragma unroll
    for (int ma = 0; ma < 2; ma++) {
        int row = bm + wm * 32 + ma * 16 + (lane >> 2);
#pragma unroll
        for (int na = 0; na < 8; na++) {
            int colr = wn * 64 + na * 8 + (lane & 3) * 2;
            int col = bn + colr;
            float* a = acc[ma * 8 + na];
            float2 v0 = make_float2(a[0] + sbias[colr], a[1] + sbias[colr + 1]);
            float2 v1 = make_float2(a[2] + sbias[colr], a[3] + sbias[colr + 1]);
            *(float2*)&Out[(size_t)row * Nt + col] = v0;
            *(float2*)&Out[(size_t)(row + 8) * Nt + col] = v1;
            if (!sel && col < 1024) {
                float sc = (col < 512) ? ASCALE : 1.f;
                float u0 = v0.x * sc, u1 = v0.y * sc;
                float w0 = v1.x * sc, w1 = v1.y * sc;
                uint32_t h0 = packbf2(u0, u1), h1 = packbf2(w0, w1);
                uint32_t m0 = packbf2(u0 - bflo(h0), u1 - bfhi(h0));
                uint32_t m1 = packbf2(w0 - bflo(h1), w1 - bfhi(h1));
                *(uint32_t*)&g_qkvh[(size_t)row * 1024 + col] = h0;
                *(uint32_t*)&g_qkvm[(size_t)row * 1024 + col] = m0;
                *(uint32_t*)&g_qkvh[(size_t)(row + 8) * 1024 + col] = h1;
                *(uint32_t*)&g_qkvm[(size_t)(row + 8) * 1024 + col] = m1;
            }
        }
    }
}

// ---------------- HMMA flash attention (cp.async pipelined) ---------------------
#define AQH 0
#define AQM 16384
#define ABUF 32768
#define BUF_SZ 65536
#define ATT_SMEM (ABUF + 2 * BUF_SZ)

__global__ __launch_bounds__(256, 1) void attn_mma_kernel(const int* __restrict__ mask)
{
    extern __shared__ char sma[];
    uint32_t sb = smem_to_u32(sma);
    int tid = threadIdx.x, lane = tid & 31, w = tid >> 5;
    int qt = blockIdx.x, h = blockIdx.y, b = blockIdx.z;
    int q0 = qt * 128;

    // ---- Q tiles via cp.async (group 0) ----
#pragma unroll
    for (int l = 0; l < 8; l++) {
        int idx = tid + l * 256;
        int ts = idx >> 10;
        int rem = idx & 1023;
        int r = rem >> 3, q = rem & 7;
        const __nv_bfloat16* src = (ts ? g_qkvm : g_qkvh) +
            (((size_t)(b * NTOK + q0 + r) * 128 + h * 8 + q) << 3);
        uint32_t dst = sb + (ts ? AQM : AQH) + (uint32_t)(r * 128 + ((q ^ (r & 7)) << 4));
        CP_ASYNC16(dst, src);
    }
    auto issue_kv = [&](int kt, int buf) {
        int k0 = kt * 128;
        uint32_t bb = sb + ABUF + buf * BUF_SZ;
#pragma unroll
        for (int l = 0; l < 16; l++) {
            int idx = tid + l * 256;
            if (idx < 2048) {
                int ts = idx >> 10;
                int rem = idx & 1023;
                int r = rem >> 3, q = rem & 7;
                const __nv_bfloat16* src = (ts ? g_qkvm : g_qkvh) +
                    (((size_t)(b * NTOK + k0 + r) * 128 + 64 + h * 8 + q) << 3);
                uint32_t dst = bb + ts * 16384 + (uint32_t)(r * 128 + ((q ^ (r & 7)) << 4));
                CP_ASYNC16(dst, src);
            } else {
                int idx2 = idx - 2048;
                int ts = idx2 >> 10;
                int rem = idx2 & 1023;
                int d = rem >> 4, c = rem & 15;
                const __nv_bfloat16* src = (ts ? g_vtm : g_vth) +
                    ((((size_t)(b * NH + h) * 64 + d) * 128 + (k0 >> 3) + c) << 3);
                uint32_t dst = bb + 32768 + ts * 16384 + (uint32_t)(d * 256 + ((c ^ (d & 7)) << 4));
                CP_ASYNC16(dst, src);
            }
        }
    };
    issue_kv(0, 0);
    CP_COMMIT();

    float oacc[8][4];
#pragma unroll
    for (int i = 0; i < 8; i++)
#pragma unroll
        for (int j = 0; j < 4; j++) oacc[i][j] = 0.f;
    float l0 = 0.f, l1 = 0.f;
    double scd0 = 0.0, scd1 = 0.0;
    int buf = 0;

#pragma unroll 1
    for (int kt = 0; kt < 8; kt++) {
        int k0 = kt * 128;
        if (kt < 7) { issue_kv(kt + 1, buf ^ 1); CP_COMMIT(); CP_WAIT(1); }
        else        { CP_WAIT(0); }
        __syncthreads();

        uint32_t KH = sb + ABUF + buf * BUF_SZ;
        uint32_t KM = KH + 16384;
        uint32_t VH = KH + 32768;
        uint32_t VM = KH + 49152;

        float sacc[16][4];
#pragma unroll
        for (int i = 0; i < 16; i++)
#pragma unroll
            for (int j = 0; j < 4; j++) sacc[i][j] = 0.f;

#pragma unroll
        for (int ks = 0; ks < 4; ks++) {
            uint32_t ch = (uint32_t)(ks * 2 + (lane >> 4));
            uint32_t ar = (uint32_t)(w * 16 + (lane & 15));
            uint32_t aoff = ar * 128 + ((ch ^ (ar & 7)) << 4);
            uint32_t qh0, qh1, qh2, qh3, qm0, qm1, qm2, qm3;
            ldsm4(sb + AQH + aoff, qh0, qh1, qh2, qh3);
            ldsm4(sb + AQM + aoff, qm0, qm1, qm2, qm3);
#pragma unroll
            for (int nb = 0; nb < 8; nb++) {
                uint32_t br = (uint32_t)(nb * 16 + (lane & 15));
                uint32_t boff = br * 128 + ((ch ^ (br & 7)) << 4);
                uint32_t kh0, kh1, kh2, kh3, km0, km1, km2, km3;
                ldsm4(KH + boff, kh0, kh1, kh2, kh3);
                ldsm4(KM + boff, km0, km1, km2, km3);
                mma16816(sacc[2 * nb + 0], qh0, qh1, qh2, qh3, kh0, kh2);
                mma16816(sacc[2 * nb + 1], qh0, qh1, qh2, qh3, kh1, kh3);
                mma16816(sacc[2 * nb + 0], qh0, qh1, qh2, qh3, km0, km2);
                mma16816(sacc[2 * nb + 1], qh0, qh1, qh2, qh3, km1, km3);
                mma16816(sacc[2 * nb + 0], qm0, qm1, qm2, qm3, kh0, kh2);
                mma16816(sacc[2 * nb + 1], qm0, qm1, qm2, qm3, kh1, kh3);
            }
        }

        {
            int r0g = q0 + w * 16 + (lane >> 2);
            const int* mr0 = mask + (size_t)r0g * NTOK + k0 + (lane & 3) * 2;
            const int* mr1 = mr0 + (size_t)8 * NTOK;
            float ss0 = 0.f, ss1 = 0.f, ls0 = 0.f, ls1 = 0.f;
#pragma unroll
            for (int t = 0; t < 16; t++) {
                int2 m0 = *(const int2*)(mr0 + 8 * t);
                int2 m1 = *(const int2*)(mr1 + 8 * t);
                float g0 = sacc[t][0] * (float)m0.x;
                float g1 = sacc[t][1] * (float)m0.y;
                float g2 = sacc[t][2] * (float)m1.x;
                float g3 = sacc[t][3] * (float)m1.y;
                ss0 += fabsf(g0) + fabsf(g1);
                ss1 += fabsf(g2) + fabsf(g3);
                float p0 = __expf(g0), p1 = __expf(g1);
                float p2 = __expf(g2), p3 = __expf(g3);
                ls0 += p0 + p1; ls1 += p2 + p3;
                sacc[t][0] = p0; sacc[t][1] = p1;
                sacc[t][2] = p2; sacc[t][3] = p3;
            }
            scd0 += (double)ss0; scd1 += (double)ss1;
            l0 += ls0; l1 += ls1;
        }

#pragma unroll
        for (int ks = 0; ks < 8; ks++) {
            float* e = sacc[2 * ks];
            float* o = sacc[2 * ks + 1];
            uint32_t ah0 = packbf2(e[0], e[1]);
            uint32_t ah1 = packbf2(e[2], e[3]);
            uint32_t ah2 = packbf2(o[0], o[1]);
            uint32_t ah3 = packbf2(o[2], o[3]);
            uint32_t am0 = packbf2(e[0] - bflo(ah0), e[1] - bfhi(ah0));
            uint32_t am1 = packbf2(e[2] - bflo(ah1), e[3] - bfhi(ah1));
            uint32_t am2 = packbf2(o[0] - bflo(ah2), o[1] - bfhi(ah2));
            uint32_t am3 = packbf2(o[2] - bflo(ah3), o[3] - bfhi(ah3));
            uint32_t ch = (uint32_t)(ks * 2 + (lane >> 4));
#pragma unroll
            for (int nd = 0; nd < 4; nd++) {
                uint32_t br = (uint32_t)(nd * 16 + (lane & 15));
                uint32_t boff = br * 256 + ((ch ^ (br & 7)) << 4);
                uint32_t vh0, vh1, vh2, vh3, vm0, vm1, vm2, vm3;
                ldsm4(VH + boff, vh0, vh1, vh2, vh3);
                ldsm4(VM + boff, vm0, vm1, vm2, vm3);
                mma16816(oacc[2 * nd + 0], ah0, ah1, ah2, ah3, vh0, vh2);
                mma16816(oacc[2 * nd + 1], ah0, ah1, ah2, ah3, vh1, vh3);
                mma16816(oacc[2 * nd + 0], ah0, ah1, ah2, ah3, vm0, vm2);
                mma16816(oacc[2 * nd + 1], ah0, ah1, ah2, ah3, vm1, vm3);
                mma16816(oacc[2 * nd + 0], am0, am1, am2, am3, vh0, vh2);
                mma16816(oacc[2 * nd + 1], am0, am1, am2, am3, vh1, vh3);
            }
        }
        __syncthreads();
        buf ^= 1;
    }

    // ---- epilogue: normalize, emit bf16 hi/mid directly ----
    l0 += __shfl_xor_sync(0xffffffffu, l0, 1);
    l0 += __shfl_xor_sync(0xffffffffu, l0, 2);
    l1 += __shfl_xor_sync(0xffffffffu, l1, 1);
    l1 += __shfl_xor_sync(0xffffffffu, l1, 2);
    scd0 += __shfl_xor_sync(0xffffffffu, scd0, 1);
    scd0 += __shfl_xor_sync(0xffffffffu, scd0, 2);
    scd1 += __shfl_xor_sync(0xffffffffu, scd1, 1);
    scd1 += __shfl_xor_sync(0xffffffffu, scd1, 2);
    float inv0 = 1.0f / l0, inv1 = 1.0f / l1;

    int r0 = q0 + w * 16 + (lane >> 2);
    int r1 = r0 + 8;
#pragma unroll
    for (int t = 0; t < 8; t++) {
        int col = h * DHE + 8 * t + (lane & 3) * 2;
        float a0 = oacc[t][0] * inv0, a1 = oacc[t][1] * inv0;
        float b0 = oacc[t][2] * inv1, b1 = oacc[t][3] * inv1;
        uint32_t h0 = packbf2(a0, a1), h1 = packbf2(b0, b1);
        uint32_t m0 = packbf2(a0 - bflo(h0), a1 - bfhi(h0));
        uint32_t m1 = packbf2(b0 - bflo(h1), b1 - bfhi(h1));
        *(uint32_t*)&g_ah[(size_t)(b * NTOK + r0) * DINNER + col] = h0;
        *(uint32_t*)&g_am[(size_t)(b * NTOK + r0) * DINNER + col] = m0;
        *(uint32_t*)&g_ah[(size_t)(b * NTOK + r1) * DINNER + col] = h1;
        *(uint32_t*)&g_am[(size_t)(b * NTOK + r1) * DINNER + col] = m1;
    }
    if ((lane & 3) == 0) {
        atomicAdd(&g_score[b * NTOK + r0], scd0);
        atomicAdd(&g_score[b * NTOK + r1], scd1);
    }
}

// ---------------- sort + swap map ------------------------------------------------
__global__ __launch_bounds__(1024) void sort_swap_kernel(const int* __restrict__ patches)
{
    int bb = blockIdx.x;
    int t = threadIdx.x;
    __shared__ double sval[NTOK];
    __shared__ int sidx[NTOK];
    sval[t] = g_score[bb * NTOK + t] / (double)g_nnz[t];
    sidx[t] = t;
    __syncthreads();

    for (int k = 2; k <= NTOK; k <<= 1) {
        for (int j = k >> 1; j > 0; j >>= 1) {
            int ixj = t ^ j;
            if (ixj > t) {
                double v1 = sval[t], v2 = sval[ixj];
                int i1 = sidx[t], i2 = sidx[ixj];
                bool gt = (v1 > v2) || (v1 == v2 && i1 > i2);
                bool up = ((t & k) == 0);
                if (gt == up) {
                    sval[t] = v2; sval[ixj] = v1;
                    sidx[t] = i2; sidx[ixj] = i1;
                }
            }
            __syncthreads();
        }
    }

    int bo = (BSZ - 1) - bb;
    g_src[bo * NTOK + t] = t;
    __syncthreads();
    if (t == 0) {
        int P = patches[0];
        for (int i = 1; i <= P; i++) {
            int ti = sidx[i];
            g_src[bo * NTOK + i] = ti;
            g_src[bo * NTOK + ti] = i;
        }
    }
}

// ---------------- launch -----------------------------------------------------------
extern "C" void kernel_launch(void* const* d_in, const int* in_sizes, int n_in,
                              void* d_out, int out_size)
{
    const float* x       = (const float*)d_in[0];
    const int*   cp_mask = (const int*)d_in[1];
    const float* w_qkv   = (const float*)d_in[2];
    const float* w_out   = (const float*)d_in[3];
    const float* b_out   = (const float*)d_in[4];
    const int*   patches = (const int*)d_in[5];
    float* out = (float*)d_out;

    cudaFuncSetAttribute(gemm_mma_kernel, cudaFuncAttributeMaxDynamicSharedMemorySize, GEMM_SMEM);
    cudaFuncSetAttribute(attn_mma_kernel, cudaFuncAttributeMaxDynamicSharedMemorySize, ATT_SMEM);

    zero_score_kernel<<<32, 256>>>();
    nnz_kernel<<<NTOK, 256>>>(cp_mask);
    cvt_split3_kernel<<<(BSZ * NTOK * DMODEL) / 512, 512>>>(x, BSZ * NTOK * DMODEL);
    transpose_split3_kernel<<<dim3(QKV3 / 32, DMODEL / 32), dim3(32, 8)>>>(w_qkv, 0, DMODEL, QKV3);
    transpose_split3_kernel<<<dim3(DMODEL / 32, DINNER / 32), dim3(32, 8)>>>(w_out, 1, DINNER, DMODEL);
    gemm_mma_kernel<<<dim3(QKV3 / 128, (BSZ * NTOK) / 128), 256, GEMM_SMEM>>>(0, nullptr, nullptr);
    cvt_v_kernel<<<dim3(8, NH, BSZ), 256>>>();
    attn_mma_kernel<<<dim3(8, NH, BSZ), 256, ATT_SMEM>>>(cp_mask);
    sort_swap_kernel<<<BSZ, 1024>>>(patches);
    gemm_mma_kernel<<<dim3(DMODEL / 128, (BSZ * NTOK) / 128), 256, GEMM_SMEM>>>(1, out, b_out);
}

// round 14
// speedup vs baseline: 2.5708x; 1.0730x over previous
#include <cuda_runtime.h>
#include <cuda_bf16.h>
#include <math.h>
#include <stdint.h>

#define BSZ    8
#define NTOK   1024
#define DMODEL 512
#define QKV3   1536
#define NH     8
#define DHE    64
#define DINNER 512
#define ASCALE 0.125f
typedef unsigned long long u64;

// ---------------- scratch (device globals; referenced ONLY from device code) --
__device__ float  g_qkv[BSZ * NTOK * QKV3];
__device__ double g_score[BSZ * NTOK];
__device__ float  g_nnz[NTOK];
__device__ int    g_src[BSZ * NTOK];
__device__ __align__(16) __nv_bfloat16 g_qkvh[BSZ*NTOK*1024], g_qkvm[BSZ*NTOK*1024];
__device__ __align__(16) __nv_bfloat16 g_vth[BSZ*NH*64*1024], g_vtm[BSZ*NH*64*1024];
__device__ __align__(16) __nv_bfloat16 g_xh[BSZ*NTOK*DMODEL], g_xm[BSZ*NTOK*DMODEL], g_xl[BSZ*NTOK*DMODEL];
__device__ __align__(16) __nv_bfloat16 g_ah[BSZ*NTOK*DINNER], g_am[BSZ*NTOK*DINNER];
__device__ __align__(16) __nv_bfloat16 g_wqh[QKV3*DMODEL], g_wqm[QKV3*DMODEL], g_wql[QKV3*DMODEL];
__device__ __align__(16) __nv_bfloat16 g_woh[DINNER*DMODEL], g_wom[DINNER*DMODEL], g_wol[DINNER*DMODEL];

// ---------------- helpers -------------------------------------------------------
static __device__ __forceinline__ uint32_t smem_to_u32(const void* p) {
    uint32_t a;
    asm("{ .reg .u64 t; cvta.to.shared.u64 t, %1; cvt.u32.u64 %0, t; }" : "=r"(a) : "l"(p));
    return a;
}
static __device__ __forceinline__ void ldsm4(uint32_t addr, uint32_t& r0, uint32_t& r1,
                                             uint32_t& r2, uint32_t& r3) {
    asm volatile("ldmatrix.sync.aligned.m8n8.x4.shared.b16 {%0,%1,%2,%3}, [%4];"
        : "=r"(r0), "=r"(r1), "=r"(r2), "=r"(r3) : "r"(addr));
}
static __device__ __forceinline__ void mma16816(float* c,
    uint32_t a0, uint32_t a1, uint32_t a2, uint32_t a3, uint32_t b0, uint32_t b1) {
    asm volatile("mma.sync.aligned.m16n8k16.row.col.f32.bf16.bf16.f32 "
        "{%0,%1,%2,%3}, {%4,%5,%6,%7}, {%8,%9}, {%0,%1,%2,%3};"
        : "+f"(c[0]), "+f"(c[1]), "+f"(c[2]), "+f"(c[3])
        : "r"(a0), "r"(a1), "r"(a2), "r"(a3), "r"(b0), "r"(b1));
}
static __device__ __forceinline__ uint32_t packbf2(float lo, float hi) {
    uint32_t r;
    asm("cvt.rn.bf16x2.f32 %0, %1, %2;" : "=r"(r) : "f"(hi), "f"(lo));
    return r;
}
static __device__ __forceinline__ float bflo(uint32_t p) { return __uint_as_float(p << 16); }
static __device__ __forceinline__ float bfhi(uint32_t p) { return __uint_as_float(p & 0xffff0000u); }
static __device__ __forceinline__ u64 pack4bf(float v0, float v1, float v2, float v3) {
    uint32_t p0 = packbf2(v0, v1), p1 = packbf2(v2, v3);
    u64 r; asm("mov.b64 %0,{%1,%2};" : "=l"(r) : "r"(p0), "r"(p1)); return r;
}
#define CP_ASYNC16(dst, src) \
    asm volatile("cp.async.cg.shared.global [%0], [%1], 16;" :: "r"(dst), "l"(src) : "memory")
#define CP_COMMIT() asm volatile("cp.async.commit_group;" ::: "memory")
#define CP_WAIT(n)  asm volatile("cp.async.wait_group %0;" :: "n"(n) : "memory")

// ---------------- small kernels -------------------------------------------------
__global__ void nnz_kernel(const int* __restrict__ mask) {
    int row = blockIdx.x, t = threadIdx.x;
    int gi = row * 256 + t;
    if (gi < BSZ * NTOK) g_score[gi] = 0.0;   // fold score zeroing in
    int cnt = 0;
    for (int c = t; c < NTOK; c += 256) cnt += (mask[row * NTOK + c] != 0);
    for (int o = 16; o; o >>= 1) cnt += __shfl_xor_sync(0xffffffffu, cnt, o);
    __shared__ int sred[8];
    if ((t & 31) == 0) sred[t >> 5] = cnt;
    __syncthreads();
    if (t == 0) {
        int s = 0;
        for (int i = 0; i < 8; i++) s += sred[i];
        g_nnz[row] = (float)s;
    }
}
__global__ void cvt_split3_kernel(const float* __restrict__ src, int n)
{
    int i = blockIdx.x * blockDim.x + threadIdx.x;
    if (i >= n) return;
    float v = src[i];
    __nv_bfloat16 hh = __float2bfloat16(v);
    float r1 = v - __bfloat162float(hh);
    __nv_bfloat16 mm = __float2bfloat16(r1);
    float r2 = r1 - __bfloat162float(mm);
    g_xh[i] = hh; g_xm[i] = mm; g_xl[i] = __float2bfloat16(r2);
}
__global__ void transpose_split3_kernel(const float* __restrict__ src, int sel,
                                        int K, int N)
{
    __shared__ float t[32][33];
    __nv_bfloat16 *h = sel ? g_woh : g_wqh;
    __nv_bfloat16 *m = sel ? g_wom : g_wqm;
    __nv_bfloat16 *l = sel ? g_wol : g_wql;
    int k0 = blockIdx.y * 32, n0 = blockIdx.x * 32;
    int tx = threadIdx.x, ty = threadIdx.y;
#pragma unroll
    for (int j = 0; j < 32; j += 8)
        t[ty + j][tx] = src[(size_t)(k0 + ty + j) * N + n0 + tx];
    __syncthreads();
#pragma unroll
    for (int j = 0; j < 32; j += 8) {
        float v = t[tx][ty + j];
        int n = n0 + ty + j, k = k0 + tx;
        __nv_bfloat16 hh = __float2bfloat16(v);
        float r1 = v - __bfloat162float(hh);
        __nv_bfloat16 mm = __float2bfloat16(r1);
        float r2 = r1 - __bfloat162float(mm);
        h[(size_t)n * K + k] = hh;
        m[(size_t)n * K + k] = mm;
        l[(size_t)n * K + k] = __float2bfloat16(r2);
    }
}
// V region of g_qkv -> transposed bf16 hi/mid [(b,h)][64 d][1024 tok]
__global__ void cvt_v_kernel()
{
    __shared__ float s[64][132];
    int tb = blockIdx.x, h = blockIdx.y, b = blockIdx.z;
    int tid = threadIdx.x;
    int tok0 = tb * 128;
#pragma unroll
    for (int l = 0; l < 8; l++) {
        int idx = tid + l * 256;
        int tok = idx >> 4, d4 = idx & 15;
        float4 v = *(const float4*)&g_qkv[(size_t)(b * NTOK + tok0 + tok) * QKV3 + 1024 + h * DHE + d4 * 4];
        s[d4 * 4 + 0][tok] = v.x;
        s[d4 * 4 + 1][tok] = v.y;
        s[d4 * 4 + 2][tok] = v.z;
        s[d4 * 4 + 3][tok] = v.w;
    }
    __syncthreads();
#pragma unroll
    for (int l = 0; l < 8; l++) {
        int idx = tid + l * 256;
        int d = idx >> 5, tc = idx & 31;
        float f0 = s[d][tc * 4 + 0], f1 = s[d][tc * 4 + 1];
        float f2 = s[d][tc * 4 + 2], f3 = s[d][tc * 4 + 3];
        u64 hh = pack4bf(f0, f1, f2, f3);
        uint32_t hl = (uint32_t)hh, hu = (uint32_t)(hh >> 32);
        u64 mm = pack4bf(f0 - bflo(hl), f1 - bfhi(hl), f2 - bflo(hu), f3 - bfhi(hu));
        size_t off = ((size_t)(b * NH + h) * 64 + d) * 1024 + tok0 + tc * 4;
        *(u64*)&g_vth[off] = hh;
        *(u64*)&g_vtm[off] = mm;
    }
}

// ---------------- HMMA GEMM ------------------------------------------------------
// sel=0: qkv = x @ wq. Q/K blocks (bn<1024): 3-way split (6 terms), bf16 out only.
//        V blocks (bn>=1024): 2-way split (3 terms), f32 out (feeds cvt_v).
// sel=1: out = gather(A) @ wo + bias, 2-way split (3 terms).
#define TILE_B 16384
#define SMG_HDR 1024
#define GEMM_SMEM (SMG_HDR + 6 * TILE_B)

__global__ __launch_bounds__(256, 2) void gemm_mma_kernel(
    int sel, float* __restrict__ OutX, const float* __restrict__ bias)
{
    extern __shared__ char smg[];
    uint32_t sb = smem_to_u32(smg);
    int tid = threadIdx.x, lane = tid & 31, wid = tid >> 5;
    int wm = wid & 3, wn = wid >> 2;
    int bm = blockIdx.y * 128, bn = blockIdx.x * 128;

    const uint4 *A0, *A1, *A2, *B0, *B1, *B2;
    float* Out; int Nt;
    if (sel) {
        A0 = (const uint4*)g_ah;  A1 = (const uint4*)g_am;  A2 = A0;
        B0 = (const uint4*)g_woh; B1 = (const uint4*)g_wom; B2 = B0;
        Out = OutX; Nt = DMODEL;
    } else {
        A0 = (const uint4*)g_xh;  A1 = (const uint4*)g_xm;  A2 = (const uint4*)g_xl;
        B0 = (const uint4*)g_wqh; B1 = (const uint4*)g_wqm; B2 = (const uint4*)g_wql;
        Out = g_qkv; Nt = QKV3;
    }
    const int tmax = (sel || bn >= 1024) ? 1 : 2;   // split depth
    int* rmap = (int*)smg;
    float* sbias = (float*)(smg + 512);
    if (tid < 128) {
        int row = bm + tid;
        rmap[tid] = sel ? ((row & ~(NTOK - 1)) + g_src[row]) : row;
        sbias[tid] = sel ? bias[bn + tid] : 0.f;
    }

    float acc[16][4];
#pragma unroll
    for (int i = 0; i < 16; i++)
#pragma unroll
        for (int j = 0; j < 4; j++) acc[i][j] = 0.f;

#pragma unroll 1
    for (int c = 0; c < 8; c++) {
        __syncthreads();
#pragma unroll
        for (int l = 0; l < 4; l++) {
            int idx = tid + l * 256;
            int r = idx >> 3, q = idx & 7;
            uint32_t so = (uint32_t)(r * 128 + ((q ^ (r & 7)) << 4));
            size_t ga = (size_t)rmap[r] * 64 + c * 8 + q;
            size_t gb = (size_t)(bn + r) * 64 + c * 8 + q;
            CP_ASYNC16(sb + SMG_HDR + 0 * TILE_B + so, A0 + ga);
            CP_ASYNC16(sb + SMG_HDR + 1 * TILE_B + so, A1 + ga);
            CP_ASYNC16(sb + SMG_HDR + 3 * TILE_B + so, B0 + gb);
            CP_ASYNC16(sb + SMG_HDR + 4 * TILE_B + so, B1 + gb);
            if (tmax == 2) {
                CP_ASYNC16(sb + SMG_HDR + 2 * TILE_B + so, A2 + ga);
                CP_ASYNC16(sb + SMG_HDR + 5 * TILE_B + so, B2 + gb);
            }
        }
        CP_COMMIT();
        CP_WAIT(0);
        __syncthreads();

#pragma unroll
        for (int ks = 0; ks < 4; ks++) {
            uint32_t ch = (uint32_t)(ks * 2 + (lane >> 4));
            uint32_t ar0 = (uint32_t)(wm * 32 + (lane & 15));
            uint32_t ar1 = ar0 + 16;
            uint32_t aoff0 = ar0 * 128 + ((ch ^ (ar0 & 7)) << 4);
            uint32_t aoff1 = ar1 * 128 + ((ch ^ (ar1 & 7)) << 4);
            uint32_t boff[4];
#pragma unroll
            for (int nb = 0; nb < 4; nb++) {
                uint32_t br = (uint32_t)(wn * 64 + nb * 16 + (lane & 15));
                boff[nb] = br * 128 + ((ch ^ (br & 7)) << 4);
            }
            uint32_t Af[3][8];
#pragma unroll
            for (int s = 0; s < 3; s++) {
                if (s <= tmax) {
                    ldsm4(sb + SMG_HDR + s * TILE_B + aoff0, Af[s][0], Af[s][1], Af[s][2], Af[s][3]);
                    ldsm4(sb + SMG_HDR + s * TILE_B + aoff1, Af[s][4], Af[s][5], Af[s][6], Af[s][7]);
                }
            }
#pragma unroll
            for (int bs = 0; bs < 3; bs++) {
                if (bs > tmax) continue;
                uint32_t bbase = sb + SMG_HDR + (3 + bs) * TILE_B;
#pragma unroll
                for (int nb = 0; nb < 4; nb++) {
                    uint32_t b0, b1, b2, b3;
                    ldsm4(bbase + boff[nb], b0, b1, b2, b3);
#pragma unroll
                    for (int s = 0; s < 3; s++) {
                        if (s + bs <= tmax) {
                            mma16816(acc[nb * 2 + 0],     Af[s][0], Af[s][1], Af[s][2], Af[s][3], b0, b2);
                            mma16816(acc[nb * 2 + 1],     Af[s][0], Af[s][1], Af[s][2], Af[s][3], b1, b3);
                            mma16816(acc[8 + nb * 2 + 0], Af[s][4], Af[s][5], Af[s][6], Af[s][7], b0, b2);
                            mma16816(acc[8 + nb * 2 + 1], Af[s][4], Af[s][5], Af[s][6], Af[s][7], b1, b3);
                        }
                    }
                }
            }
        }
    }

    // ---- epilogue ----
#pragma unroll
    for (int ma = 0; ma < 2; ma++) {
        int row = bm + wm * 32 + ma * 16 + (lane >> 2);
#pragma unroll
        for (int na = 0; na < 8; na++) {
            int colr = wn * 64 + na * 8 + (lane & 3) * 2;
            int col = bn + colr;
            float* a = acc[ma * 8 + na];
            float2 v0 = make_float2(a[0] + sbias[colr], a[1] + sbias[colr + 1]);
            float2 v1 = make_float2(a[2] + sbias[colr], a[3] + sbias[colr + 1]);
            if (sel || col >= 1024) {       // f32 needed only for out / V region
                *(float2*)&Out[(size_t)row * Nt + col] = v0;
                *(float2*)&Out[(size_t)(row + 8) * Nt + col] = v1;
            }
            if (!sel && col < 1024) {
                float sc = (col < 512) ? ASCALE : 1.f;
                float u0 = v0.x * sc, u1 = v0.y * sc;
                float w0 = v1.x * sc, w1 = v1.y * sc;
                uint32_t h0 = packbf2(u0, u1), h1 = packbf2(w0, w1);
                uint32_t m0 = packbf2(u0 - bflo(h0), u1 - bfhi(h0));
                uint32_t m1 = packbf2(w0 - bflo(h1), w1 - bfhi(h1));
                *(uint32_t*)&g_qkvh[(size_t)row * 1024 + col] = h0;
                *(uint32_t*)&g_qkvm[(size_t)row * 1024 + col] = m0;
                *(uint32_t*)&g_qkvh[(size_t)(row + 8) * 1024 + col] = h1;
                *(uint32_t*)&g_qkvm[(size_t)(row + 8) * 1024 + col] = m1;
            }
        }
    }
}

// ---------------- HMMA flash attention (cp.async pipelined) ---------------------
#define AQH 0
#define AQM 16384
#define ABUF 32768
#define BUF_SZ 65536
#define ATT_SMEM (ABUF + 2 * BUF_SZ)

__global__ __launch_bounds__(256, 1) void attn_mma_kernel(const int* __restrict__ mask)
{
    extern __shared__ char sma[];
    uint32_t sb = smem_to_u32(sma);
    int tid = threadIdx.x, lane = tid & 31, w = tid >> 5;
    int qt = blockIdx.x, h = blockIdx.y, b = blockIdx.z;
    int q0 = qt * 128;

#pragma unroll
    for (int l = 0; l < 8; l++) {
        int idx = tid + l * 256;
        int ts = idx >> 10;
        int rem = idx & 1023;
        int r = rem >> 3, q = rem & 7;
        const __nv_bfloat16* src = (ts ? g_qkvm : g_qkvh) +
            (((size_t)(b * NTOK + q0 + r) * 128 + h * 8 + q) << 3);
        uint32_t dst = sb + (ts ? AQM : AQH) + (uint32_t)(r * 128 + ((q ^ (r & 7)) << 4));
        CP_ASYNC16(dst, src);
    }
    auto issue_kv = [&](int kt, int buf) {
        int k0 = kt * 128;
        uint32_t bb = sb + ABUF + buf * BUF_SZ;
#pragma unroll
        for (int l = 0; l < 16; l++) {
            int idx = tid + l * 256;
            if (idx < 2048) {
                int ts = idx >> 10;
                int rem = idx & 1023;
                int r = rem >> 3, q = rem & 7;
                const __nv_bfloat16* src = (ts ? g_qkvm : g_qkvh) +
                    (((size_t)(b * NTOK + k0 + r) * 128 + 64 + h * 8 + q) << 3);
                uint32_t dst = bb + ts * 16384 + (uint32_t)(r * 128 + ((q ^ (r & 7)) << 4));
                CP_ASYNC16(dst, src);
            } else {
                int idx2 = idx - 2048;
                int ts = idx2 >> 10;
                int rem = idx2 & 1023;
                int d = rem >> 4, c = rem & 15;
                const __nv_bfloat16* src = (ts ? g_vtm : g_vth) +
                    ((((size_t)(b * NH + h) * 64 + d) * 128 + (k0 >> 3) + c) << 3);
                uint32_t dst = bb + 32768 + ts * 16384 + (uint32_t)(d * 256 + ((c ^ (d & 7)) << 4));
                CP_ASYNC16(dst, src);
            }
        }
    };
    issue_kv(0, 0);
    CP_COMMIT();

    float oacc[8][4];
#pragma unroll
    for (int i = 0; i < 8; i++)
#pragma unroll
        for (int j = 0; j < 4; j++) oacc[i][j] = 0.f;
    float l0 = 0.f, l1 = 0.f;
    double scd0 = 0.0, scd1 = 0.0;
    int buf = 0;

#pragma unroll 1
    for (int kt = 0; kt < 8; kt++) {
        int k0 = kt * 128;
        if (kt < 7) { issue_kv(kt + 1, buf ^ 1); CP_COMMIT(); CP_WAIT(1); }
        else        { CP_WAIT(0); }
        __syncthreads();

        uint32_t KH = sb + ABUF + buf * BUF_SZ;
        uint32_t KM = KH + 16384;
        uint32_t VH = KH + 32768;
        uint32_t VM = KH + 49152;

        float sacc[16][4];
#pragma unroll
        for (int i = 0; i < 16; i++)
#pragma unroll
            for (int j = 0; j < 4; j++) sacc[i][j] = 0.f;

#pragma unroll
        for (int ks = 0; ks < 4; ks++) {
            uint32_t ch = (uint32_t)(ks * 2 + (lane >> 4));
            uint32_t ar = (uint32_t)(w * 16 + (lane & 15));
            uint32_t aoff = ar * 128 + ((ch ^ (ar & 7)) << 4);
            uint32_t qh0, qh1, qh2, qh3, qm0, qm1, qm2, qm3;
            ldsm4(sb + AQH + aoff, qh0, qh1, qh2, qh3);
            ldsm4(sb + AQM + aoff, qm0, qm1, qm2, qm3);
#pragma unroll
            for (int nb = 0; nb < 8; nb++) {
                uint32_t br = (uint32_t)(nb * 16 + (lane & 15));
                uint32_t boff = br * 128 + ((ch ^ (br & 7)) << 4);
                uint32_t kh0, kh1, kh2, kh3, km0, km1, km2, km3;
                ldsm4(KH + boff, kh0, kh1, kh2, kh3);
                ldsm4(KM + boff, km0, km1, km2, km3);
                mma16816(sacc[2 * nb + 0], qh0, qh1, qh2, qh3, kh0, kh2);
                mma16816(sacc[2 * nb + 1], qh0, qh1, qh2, qh3, kh1, kh3);
                mma16816(sacc[2 * nb + 0], qh0, qh1, qh2, qh3, km0, km2);
                mma16816(sacc[2 * nb + 1], qh0, qh1, qh2, qh3, km1, km3);
                mma16816(sacc[2 * nb + 0], qm0, qm1, qm2, qm3, kh0, kh2);
                mma16816(sacc[2 * nb + 1], qm0, qm1, qm2, qm3, kh1, kh3);
            }
        }

        {
            int r0g = q0 + w * 16 + (lane >> 2);
            const int* mr0 = mask + (size_t)r0g * NTOK + k0 + (lane & 3) * 2;
            const int* mr1 = mr0 + (size_t)8 * NTOK;
            float ss0 = 0.f, ss1 = 0.f, ls0 = 0.f, ls1 = 0.f;
#pragma unroll
            for (int t = 0; t < 16; t++) {
                int2 m0 = *(const int2*)(mr0 + 8 * t);
                int2 m1 = *(const int2*)(mr1 + 8 * t);
                float g0 = sacc[t][0] * (float)m0.x;
                float g1 = sacc[t][1] * (float)m0.y;
                float g2 = sacc[t][2] * (float)m1.x;
                float g3 = sacc[t][3] * (float)m1.y;
                ss0 += fabsf(g0) + fabsf(g1);
                ss1 += fabsf(g2) + fabsf(g3);
                float p0 = __expf(g0), p1 = __expf(g1);
                float p2 = __expf(g2), p3 = __expf(g3);
                ls0 += p0 + p1; ls1 += p2 + p3;
                sacc[t][0] = p0; sacc[t][1] = p1;
                sacc[t][2] = p2; sacc[t][3] = p3;
            }
            scd0 += (double)ss0; scd1 += (double)ss1;
            l0 += ls0; l1 += ls1;
        }

#pragma unroll
        for (int ks = 0; ks < 8; ks++) {
            float* e = sacc[2 * ks];
            float* o = sacc[2 * ks + 1];
            uint32_t ah0 = packbf2(e[0], e[1]);
            uint32_t ah1 = packbf2(e[2], e[3]);
            uint32_t ah2 = packbf2(o[0], o[1]);
            uint32_t ah3 = packbf2(o[2], o[3]);
            uint32_t am0 = packbf2(e[0] - bflo(ah0), e[1] - bfhi(ah0));
            uint32_t am1 = packbf2(e[2] - bflo(ah1), e[3] - bfhi(ah1));
            uint32_t am2 = packbf2(o[0] - bflo(ah2), o[1] - bfhi(ah2));
            uint32_t am3 = packbf2(o[2] - bflo(ah3), o[3] - bfhi(ah3));
            uint32_t ch = (uint32_t)(ks * 2 + (lane >> 4));
#pragma unroll
            for (int nd = 0; nd < 4; nd++) {
                uint32_t br = (uint32_t)(nd * 16 + (lane & 15));
                uint32_t boff = br * 256 + ((ch ^ (br & 7)) << 4);
                uint32_t vh0, vh1, vh2, vh3, vm0, vm1, vm2, vm3;
                ldsm4(VH + boff, vh0, vh1, vh2, vh3);
                ldsm4(VM + boff, vm0, vm1, vm2, vm3);
                mma16816(oacc[2 * nd + 0], ah0, ah1, ah2, ah3, vh0, vh2);
                mma16816(oacc[2 * nd + 1], ah0, ah1, ah2, ah3, vh1, vh3);
                mma16816(oacc[2 * nd + 0], ah0, ah1, ah2, ah3, vm0, vm2);
                mma16816(oacc[2 * nd + 1], ah0, ah1, ah2, ah3, vm1, vm3);
                mma16816(oacc[2 * nd + 0], am0, am1, am2, am3, vh0, vh2);
                mma16816(oacc[2 * nd + 1], am0, am1, am2, am3, vh1, vh3);
            }
        }
        __syncthreads();
        buf ^= 1;
    }

    l0 += __shfl_xor_sync(0xffffffffu, l0, 1);
    l0 += __shfl_xor_sync(0xffffffffu, l0, 2);
    l1 += __shfl_xor_sync(0xffffffffu, l1, 1);
    l1 += __shfl_xor_sync(0xffffffffu, l1, 2);
    scd0 += __shfl_xor_sync(0xffffffffu, scd0, 1);
    scd0 += __shfl_xor_sync(0xffffffffu, scd0, 2);
    scd1 += __shfl_xor_sync(0xffffffffu, scd1, 1);
    scd1 += __shfl_xor_sync(0xffffffffu, scd1, 2);
    float inv0 = 1.0f / l0, inv1 = 1.0f / l1;

    int r0 = q0 + w * 16 + (lane >> 2);
    int r1 = r0 + 8;
#pragma unroll
    for (int t = 0; t < 8; t++) {
        int col = h * DHE + 8 * t + (lane & 3) * 2;
        float a0 = oacc[t][0] * inv0, a1 = oacc[t][1] * inv0;
        float b0 = oacc[t][2] * inv1, b1 = oacc[t][3] * inv1;
        uint32_t h0 = packbf2(a0, a1), h1 = packbf2(b0, b1);
        uint32_t m0 = packbf2(a0 - bflo(h0), a1 - bfhi(h0));
        uint32_t m1 = packbf2(b0 - bflo(h1), b1 - bfhi(h1));
        *(uint32_t*)&g_ah[(size_t)(b * NTOK + r0) * DINNER + col] = h0;
        *(uint32_t*)&g_am[(size_t)(b * NTOK + r0) * DINNER + col] = m0;
        *(uint32_t*)&g_ah[(size_t)(b * NTOK + r1) * DINNER + col] = h1;
        *(uint32_t*)&g_am[(size_t)(b * NTOK + r1) * DINNER + col] = m1;
    }
    if ((lane & 3) == 0) {
        atomicAdd(&g_score[b * NTOK + r0], scd0);
        atomicAdd(&g_score[b * NTOK + r1], scd1);
    }
}

// ---------------- sort + swap map ------------------------------------------------
__global__ __launch_bounds__(1024) void sort_swap_kernel(const int* __restrict__ patches)
{
    int bb = blockIdx.x;
    int t = threadIdx.x;
    __shared__ double sval[NTOK];
    __shared__ int sidx[NTOK];
    sval[t] = g_score[bb * NTOK + t] / (double)g_nnz[t];
    sidx[t] = t;
    __syncthreads();

    for (int k = 2; k <= NTOK; k <<= 1) {
        for (int j = k >> 1; j > 0; j >>= 1) {
            int ixj = t ^ j;
            if (ixj > t) {
                double v1 = sval[t], v2 = sval[ixj];
                int i1 = sidx[t], i2 = sidx[ixj];
                bool gt = (v1 > v2) || (v1 == v2 && i1 > i2);
                bool up = ((t & k) == 0);
                if (gt == up) {
                    sval[t] = v2; sval[ixj] = v1;
                    sidx[t] = i2; sidx[ixj] = i1;
                }
            }
            __syncthreads();
        }
    }

    int bo = (BSZ - 1) - bb;
    g_src[bo * NTOK + t] = t;
    __syncthreads();
    if (t == 0) {
        int P = patches[0];
        for (int i = 1; i <= P; i++) {
            int ti = sidx[i];
            g_src[bo * NTOK + i] = ti;
            g_src[bo * NTOK + ti] = i;
        }
    }
}

// ---------------- launch -----------------------------------------------------------
extern "C" void kernel_launch(void* const* d_in, const int* in_sizes, int n_in,
                              void* d_out, int out_size)
{
    const float* x       = (const float*)d_in[0];
    const int*   cp_mask = (const int*)d_in[1];
    const float* w_qkv   = (const float*)d_in[2];
    const float* w_out   = (const float*)d_in[3];
    const float* b_out   = (const float*)d_in[4];
    const int*   patches = (const int*)d_in[5];
    float* out = (float*)d_out;

    cudaFuncSetAttribute(gemm_mma_kernel, cudaFuncAttributeMaxDynamicSharedMemorySize, GEMM_SMEM);
    cudaFuncSetAttribute(attn_mma_kernel, cudaFuncAttributeMaxDynamicSharedMemorySize, ATT_SMEM);

    nnz_kernel<<<NTOK, 256>>>(cp_mask);
    cvt_split3_kernel<<<(BSZ * NTOK * DMODEL) / 512, 512>>>(x, BSZ * NTOK * DMODEL);
    transpose_split3_kernel<<<dim3(QKV3 / 32, DMODEL / 32), dim3(32, 8)>>>(w_qkv, 0, DMODEL, QKV3);
    transpose_split3_kernel<<<dim3(DMODEL / 32, DINNER / 32), dim3(32, 8)>>>(w_out, 1, DINNER, DMODEL);
    gemm_mma_kernel<<<dim3(QKV3 / 128, (BSZ * NTOK) / 128), 256, GEMM_SMEM>>>(0, nullptr, nullptr);
    cvt_v_kernel<<<dim3(8, NH, BSZ), 256>>>();
    attn_mma_kernel<<<dim3(8, NH, BSZ), 256, ATT_SMEM>>>(cp_mask);
    sort_swap_kernel<<<BSZ, 1024>>>(patches);
    gemm_mma_kernel<<<dim3(DMODEL / 128, (BSZ * NTOK) / 128), 256, GEMM_SMEM>>>(1, out, b_out);
}

// round 15
// speedup vs baseline: 2.6001x; 1.0114x over previous
#include <cuda_runtime.h>
#include <cuda_bf16.h>
#include <math.h>
#include <stdint.h>

#define BSZ    8
#define NTOK   1024
#define DMODEL 512
#define QKV3   1536
#define NH     8
#define DHE    64
#define DINNER 512
#define ASCALE 0.125f
typedef unsigned long long u64;

// ---------------- scratch (device globals; referenced ONLY from device code) --
__device__ double g_score[BSZ * NTOK];
__device__ float  g_nnz[NTOK];
__device__ int    g_src[BSZ * NTOK];
__device__ __align__(16) __nv_bfloat16 g_qkvh[BSZ*NTOK*1024], g_qkvm[BSZ*NTOK*1024];
__device__ __align__(16) __nv_bfloat16 g_vth[BSZ*NH*64*1024], g_vtm[BSZ*NH*64*1024];
__device__ __align__(16) __nv_bfloat16 g_xh[BSZ*NTOK*DMODEL], g_xm[BSZ*NTOK*DMODEL], g_xl[BSZ*NTOK*DMODEL];
__device__ __align__(16) __nv_bfloat16 g_ah[BSZ*NTOK*DINNER], g_am[BSZ*NTOK*DINNER];
__device__ __align__(16) __nv_bfloat16 g_wqh[QKV3*DMODEL], g_wqm[QKV3*DMODEL], g_wql[QKV3*DMODEL];
__device__ __align__(16) __nv_bfloat16 g_woh[DINNER*DMODEL], g_wom[DINNER*DMODEL], g_wol[DINNER*DMODEL];

// ---------------- helpers -------------------------------------------------------
static __device__ __forceinline__ uint32_t smem_to_u32(const void* p) {
    uint32_t a;
    asm("{ .reg .u64 t; cvta.to.shared.u64 t, %1; cvt.u32.u64 %0, t; }" : "=r"(a) : "l"(p));
    return a;
}
static __device__ __forceinline__ void ldsm4(uint32_t addr, uint32_t& r0, uint32_t& r1,
                                             uint32_t& r2, uint32_t& r3) {
    asm volatile("ldmatrix.sync.aligned.m8n8.x4.shared.b16 {%0,%1,%2,%3}, [%4];"
        : "=r"(r0), "=r"(r1), "=r"(r2), "=r"(r3) : "r"(addr));
}
static __device__ __forceinline__ void mma16816(float* c,
    uint32_t a0, uint32_t a1, uint32_t a2, uint32_t a3, uint32_t b0, uint32_t b1) {
    asm volatile("mma.sync.aligned.m16n8k16.row.col.f32.bf16.bf16.f32 "
        "{%0,%1,%2,%3}, {%4,%5,%6,%7}, {%8,%9}, {%0,%1,%2,%3};"
        : "+f"(c[0]), "+f"(c[1]), "+f"(c[2]), "+f"(c[3])
        : "r"(a0), "r"(a1), "r"(a2), "r"(a3), "r"(b0), "r"(b1));
}
static __device__ __forceinline__ uint32_t packbf2(float lo, float hi) {
    uint32_t r;
    asm("cvt.rn.bf16x2.f32 %0, %1, %2;" : "=r"(r) : "f"(hi), "f"(lo));
    return r;
}
static __device__ __forceinline__ float bflo(uint32_t p) { return __uint_as_float(p << 16); }
static __device__ __forceinline__ float bfhi(uint32_t p) { return __uint_as_float(p & 0xffff0000u); }
#define CP_ASYNC16(dst, src) \
    asm volatile("cp.async.cg.shared.global [%0], [%1], 16;" :: "r"(dst), "l"(src) : "memory")
#define CP_COMMIT() asm volatile("cp.async.commit_group;" ::: "memory")
#define CP_WAIT(n)  asm volatile("cp.async.wait_group %0;" :: "n"(n) : "memory")

// ---------------- small kernels -------------------------------------------------
__global__ void nnz_kernel(const int* __restrict__ mask) {
    int row = blockIdx.x, t = threadIdx.x;
    int gi = row * 256 + t;
    if (gi < BSZ * NTOK) g_score[gi] = 0.0;
    int cnt = 0;
    for (int c = t; c < NTOK; c += 256) cnt += (mask[row * NTOK + c] != 0);
    for (int o = 16; o; o >>= 1) cnt += __shfl_xor_sync(0xffffffffu, cnt, o);
    __shared__ int sred[8];
    if ((t & 31) == 0) sred[t >> 5] = cnt;
    __syncthreads();
    if (t == 0) {
        int s = 0;
        for (int i = 0; i < 8; i++) s += sred[i];
        g_nnz[row] = (float)s;
    }
}
__global__ void cvt_split3_kernel(const float* __restrict__ src, int n)
{
    int i = blockIdx.x * blockDim.x + threadIdx.x;
    if (i >= n) return;
    float v = src[i];
    __nv_bfloat16 hh = __float2bfloat16(v);
    float r1 = v - __bfloat162float(hh);
    __nv_bfloat16 mm = __float2bfloat16(r1);
    float r2 = r1 - __bfloat162float(mm);
    g_xh[i] = hh; g_xm[i] = mm; g_xl[i] = __float2bfloat16(r2);
}
__global__ void transpose_split3_kernel(const float* __restrict__ src, int sel,
                                        int K, int N)
{
    __shared__ float t[32][33];
    __nv_bfloat16 *h = sel ? g_woh : g_wqh;
    __nv_bfloat16 *m = sel ? g_wom : g_wqm;
    __nv_bfloat16 *l = sel ? g_wol : g_wql;
    int k0 = blockIdx.y * 32, n0 = blockIdx.x * 32;
    int tx = threadIdx.x, ty = threadIdx.y;
#pragma unroll
    for (int j = 0; j < 32; j += 8)
        t[ty + j][tx] = src[(size_t)(k0 + ty + j) * N + n0 + tx];
    __syncthreads();
#pragma unroll
    for (int j = 0; j < 32; j += 8) {
        float v = t[tx][ty + j];
        int n = n0 + ty + j, k = k0 + tx;
        __nv_bfloat16 hh = __float2bfloat16(v);
        float r1 = v - __bfloat162float(hh);
        __nv_bfloat16 mm = __float2bfloat16(r1);
        float r2 = r1 - __bfloat162float(mm);
        h[(size_t)n * K + k] = hh;
        m[(size_t)n * K + k] = mm;
        l[(size_t)n * K + k] = __float2bfloat16(r2);
    }
}

// ---------------- HMMA GEMM ------------------------------------------------------
// sel=0: qkv = x @ wq. Q/K blocks (bn<1024): 3-way split, bf16 hi/mid out.
//        V blocks (bn>=1024): 2-way split, transposed bf16 hi/mid out (g_vth/m).
// sel=1: out = gather(A) @ wo + bias, 2-way split.
#define TILE_B 16384
#define SMG_HDR 1024
#define GEMM_SMEM (SMG_HDR + 6 * TILE_B)

__global__ __launch_bounds__(256, 2) void gemm_mma_kernel(
    int sel, float* __restrict__ OutX, const float* __restrict__ bias)
{
    extern __shared__ char smg[];
    uint32_t sb = smem_to_u32(smg);
    int tid = threadIdx.x, lane = tid & 31, wid = tid >> 5;
    int wm = wid & 3, wn = wid >> 2;
    int bm = blockIdx.y * 128, bn = blockIdx.x * 128;

    const uint4 *A0, *A1, *A2, *B0, *B1, *B2;
    if (sel) {
        A0 = (const uint4*)g_ah;  A1 = (const uint4*)g_am;  A2 = A0;
        B0 = (const uint4*)g_woh; B1 = (const uint4*)g_wom; B2 = B0;
    } else {
        A0 = (const uint4*)g_xh;  A1 = (const uint4*)g_xm;  A2 = (const uint4*)g_xl;
        B0 = (const uint4*)g_wqh; B1 = (const uint4*)g_wqm; B2 = (const uint4*)g_wql;
    }
    const int tmax = (sel || bn >= 1024) ? 1 : 2;
    int* rmap = (int*)smg;
    float* sbias = (float*)(smg + 512);
    if (tid < 128) {
        int row = bm + tid;
        rmap[tid] = sel ? ((row & ~(NTOK - 1)) + g_src[row]) : row;
        sbias[tid] = sel ? bias[bn + tid] : 0.f;
    }

    float acc[16][4];
#pragma unroll
    for (int i = 0; i < 16; i++)
#pragma unroll
        for (int j = 0; j < 4; j++) acc[i][j] = 0.f;

#pragma unroll 1
    for (int c = 0; c < 8; c++) {
        __syncthreads();
#pragma unroll
        for (int l = 0; l < 4; l++) {
            int idx = tid + l * 256;
            int r = idx >> 3, q = idx & 7;
            uint32_t so = (uint32_t)(r * 128 + ((q ^ (r & 7)) << 4));
            size_t ga = (size_t)rmap[r] * 64 + c * 8 + q;
            size_t gb = (size_t)(bn + r) * 64 + c * 8 + q;
            CP_ASYNC16(sb + SMG_HDR + 0 * TILE_B + so, A0 + ga);
            CP_ASYNC16(sb + SMG_HDR + 1 * TILE_B + so, A1 + ga);
            CP_ASYNC16(sb + SMG_HDR + 3 * TILE_B + so, B0 + gb);
            CP_ASYNC16(sb + SMG_HDR + 4 * TILE_B + so, B1 + gb);
            if (tmax == 2) {
                CP_ASYNC16(sb + SMG_HDR + 2 * TILE_B + so, A2 + ga);
                CP_ASYNC16(sb + SMG_HDR + 5 * TILE_B + so, B2 + gb);
            }
        }
        CP_COMMIT();
        CP_WAIT(0);
        __syncthreads();

#pragma unroll
        for (int ks = 0; ks < 4; ks++) {
            uint32_t ch = (uint32_t)(ks * 2 + (lane >> 4));
            uint32_t ar0 = (uint32_t)(wm * 32 + (lane & 15));
            uint32_t ar1 = ar0 + 16;
            uint32_t aoff0 = ar0 * 128 + ((ch ^ (ar0 & 7)) << 4);
            uint32_t aoff1 = ar1 * 128 + ((ch ^ (ar1 & 7)) << 4);
            uint32_t boff[4];
#pragma unroll
            for (int nb = 0; nb < 4; nb++) {
                uint32_t br = (uint32_t)(wn * 64 + nb * 16 + (lane & 15));
                boff[nb] = br * 128 + ((ch ^ (br & 7)) << 4);
            }
            uint32_t Af[3][8];
#pragma unroll
            for (int s = 0; s < 3; s++) {
                if (s <= tmax) {
                    ldsm4(sb + SMG_HDR + s * TILE_B + aoff0, Af[s][0], Af[s][1], Af[s][2], Af[s][3]);
                    ldsm4(sb + SMG_HDR + s * TILE_B + aoff1, Af[s][4], Af[s][5], Af[s][6], Af[s][7]);
                }
            }
#pragma unroll
            for (int bs = 0; bs < 3; bs++) {
                if (bs > tmax) continue;
                uint32_t bbase = sb + SMG_HDR + (3 + bs) * TILE_B;
#pragma unroll
                for (int nb = 0; nb < 4; nb++) {
                    uint32_t b0, b1, b2, b3;
                    ldsm4(bbase + boff[nb], b0, b1, b2, b3);
#pragma unroll
                    for (int s = 0; s < 3; s++) {
                        if (s + bs <= tmax) {
                            mma16816(acc[nb * 2 + 0],     Af[s][0], Af[s][1], Af[s][2], Af[s][3], b0, b2);
                            mma16816(acc[nb * 2 + 1],     Af[s][0], Af[s][1], Af[s][2], Af[s][3], b1, b3);
                            mma16816(acc[8 + nb * 2 + 0], Af[s][4], Af[s][5], Af[s][6], Af[s][7], b0, b2);
                            mma16816(acc[8 + nb * 2 + 1], Af[s][4], Af[s][5], Af[s][6], Af[s][7], b1, b3);
                        }
                    }
                }
            }
        }
    }

    // ---- epilogue ----
#pragma unroll
    for (int ma = 0; ma < 2; ma++) {
        int row = bm + wm * 32 + ma * 16 + (lane >> 2);
#pragma unroll
        for (int na = 0; na < 8; na++) {
            int colr = wn * 64 + na * 8 + (lane & 3) * 2;
            int col = bn + colr;
            float* a = acc[ma * 8 + na];
            float2 v0 = make_float2(a[0] + sbias[colr], a[1] + sbias[colr + 1]);
            float2 v1 = make_float2(a[2] + sbias[colr], a[3] + sbias[colr + 1]);
            if (sel) {
                *(float2*)&OutX[(size_t)row * DMODEL + col] = v0;
                *(float2*)&OutX[(size_t)(row + 8) * DMODEL + col] = v1;
            } else if (col < 1024) {
                float sc = (col < 512) ? ASCALE : 1.f;
                float u0 = v0.x * sc, u1 = v0.y * sc;
                float w0 = v1.x * sc, w1 = v1.y * sc;
                uint32_t h0 = packbf2(u0, u1), h1 = packbf2(w0, w1);
                uint32_t m0 = packbf2(u0 - bflo(h0), u1 - bfhi(h0));
                uint32_t m1 = packbf2(w0 - bflo(h1), w1 - bfhi(h1));
                *(uint32_t*)&g_qkvh[(size_t)row * 1024 + col] = h0;
                *(uint32_t*)&g_qkvm[(size_t)row * 1024 + col] = m0;
                *(uint32_t*)&g_qkvh[(size_t)(row + 8) * 1024 + col] = h1;
                *(uint32_t*)&g_qkvm[(size_t)(row + 8) * 1024 + col] = m1;
            } else {
                // V region: write transposed bf16 hi/mid directly
                int vc = col - 1024;
                int hh = vc >> 6, dd = vc & 63;
                int bb2 = row >> 10, tok = row & 1023;
                size_t base = ((size_t)(bb2 * NH + hh) * 64 + dd) * 1024 + tok;
                __nv_bfloat16 e;
                e = __float2bfloat16(v0.x);
                g_vth[base] = e;
                g_vtm[base] = __float2bfloat16(v0.x - __bfloat162float(e));
                e = __float2bfloat16(v0.y);
                g_vth[base + 1024] = e;
                g_vtm[base + 1024] = __float2bfloat16(v0.y - __bfloat162float(e));
                e = __float2bfloat16(v1.x);
                g_vth[base + 8] = e;
                g_vtm[base + 8] = __float2bfloat16(v1.x - __bfloat162float(e));
                e = __float2bfloat16(v1.y);
                g_vth[base + 1024 + 8] = e;
                g_vtm[base + 1024 + 8] = __float2bfloat16(v1.y - __bfloat162float(e));
            }
        }
    }
}

// ---------------- HMMA flash attention (cp.async pipelined) ---------------------
#define AQH 0
#define AQM 16384
#define ABUF 32768
#define BUF_SZ 65536
#define ATT_SMEM (ABUF + 2 * BUF_SZ)

__global__ __launch_bounds__(256, 1) void attn_mma_kernel(const int* __restrict__ mask)
{
    extern __shared__ char sma[];
    uint32_t sb = smem_to_u32(sma);
    int tid = threadIdx.x, lane = tid & 31, w = tid >> 5;
    int qt = blockIdx.x, h = blockIdx.y, b = blockIdx.z;
    int q0 = qt * 128;

#pragma unroll
    for (int l = 0; l < 8; l++) {
        int idx = tid + l * 256;
        int ts = idx >> 10;
        int rem = idx & 1023;
        int r = rem >> 3, q = rem & 7;
        const __nv_bfloat16* src = (ts ? g_qkvm : g_qkvh) +
            (((size_t)(b * NTOK + q0 + r) * 128 + h * 8 + q) << 3);
        uint32_t dst = sb + (ts ? AQM : AQH) + (uint32_t)(r * 128 + ((q ^ (r & 7)) << 4));
        CP_ASYNC16(dst, src);
    }
    auto issue_kv = [&](int kt, int buf) {
        int k0 = kt * 128;
        uint32_t bb = sb + ABUF + buf * BUF_SZ;
#pragma unroll
        for (int l = 0; l < 16; l++) {
            int idx = tid + l * 256;
            if (idx < 2048) {
                int ts = idx >> 10;
                int rem = idx & 1023;
                int r = rem >> 3, q = rem & 7;
                const __nv_bfloat16* src = (ts ? g_qkvm : g_qkvh) +
                    (((size_t)(b * NTOK + k0 + r) * 128 + 64 + h * 8 + q) << 3);
                uint32_t dst = bb + ts * 16384 + (uint32_t)(r * 128 + ((q ^ (r & 7)) << 4));
                CP_ASYNC16(dst, src);
            } else {
                int idx2 = idx - 2048;
                int ts = idx2 >> 10;
                int rem = idx2 & 1023;
                int d = rem >> 4, c = rem & 15;
                const __nv_bfloat16* src = (ts ? g_vtm : g_vth) +
                    ((((size_t)(b * NH + h) * 64 + d) * 128 + (k0 >> 3) + c) << 3);
                uint32_t dst = bb + 32768 + ts * 16384 + (uint32_t)(d * 256 + ((c ^ (d & 7)) << 4));
                CP_ASYNC16(dst, src);
            }
        }
    };
    issue_kv(0, 0);
    CP_COMMIT();

    float oacc[8][4];
#pragma unroll
    for (int i = 0; i < 8; i++)
#pragma unroll
        for (int j = 0; j < 4; j++) oacc[i][j] = 0.f;
    float l0 = 0.f, l1 = 0.f;
    double scd0 = 0.0, scd1 = 0.0;
    int buf = 0;

#pragma unroll 1
    for (int kt = 0; kt < 8; kt++) {
        int k0 = kt * 128;
        if (kt < 7) { issue_kv(kt + 1, buf ^ 1); CP_COMMIT(); CP_WAIT(1); }
        else        { CP_WAIT(0); }
        __syncthreads();

        uint32_t KH = sb + ABUF + buf * BUF_SZ;
        uint32_t KM = KH + 16384;
        uint32_t VH = KH + 32768;
        uint32_t VM = KH + 49152;

        float sacc[16][4];
#pragma unroll
        for (int i = 0; i < 16; i++)
#pragma unroll
            for (int j = 0; j < 4; j++) sacc[i][j] = 0.f;

#pragma unroll
        for (int ks = 0; ks < 4; ks++) {
            uint32_t ch = (uint32_t)(ks * 2 + (lane >> 4));
            uint32_t ar = (uint32_t)(w * 16 + (lane & 15));
            uint32_t aoff = ar * 128 + ((ch ^ (ar & 7)) << 4);
            uint32_t qh0, qh1, qh2, qh3, qm0, qm1, qm2, qm3;
            ldsm4(sb + AQH + aoff, qh0, qh1, qh2, qh3);
            ldsm4(sb + AQM + aoff, qm0, qm1, qm2, qm3);
#pragma unroll
            for (int nb = 0; nb < 8; nb++) {
                uint32_t br = (uint32_t)(nb * 16 + (lane & 15));
                uint32_t boff = br * 128 + ((ch ^ (br & 7)) << 4);
                uint32_t kh0, kh1, kh2, kh3, km0, km1, km2, km3;
                ldsm4(KH + boff, kh0, kh1, kh2, kh3);
                ldsm4(KM + boff, km0, km1, km2, km3);
                mma16816(sacc[2 * nb + 0], qh0, qh1, qh2, qh3, kh0, kh2);
                mma16816(sacc[2 * nb + 1], qh0, qh1, qh2, qh3, kh1, kh3);
                mma16816(sacc[2 * nb + 0], qh0, qh1, qh2, qh3, km0, km2);
                mma16816(sacc[2 * nb + 1], qh0, qh1, qh2, qh3, km1, km3);
                mma16816(sacc[2 * nb + 0], qm0, qm1, qm2, qm3, kh0, kh2);
                mma16816(sacc[2 * nb + 1], qm0, qm1, qm2, qm3, kh1, kh3);
            }
        }

        {
            int r0g = q0 + w * 16 + (lane >> 2);
            const int* mr0 = mask + (size_t)r0g * NTOK + k0 + (lane & 3) * 2;
            const int* mr1 = mr0 + (size_t)8 * NTOK;
            float ss0 = 0.f, ss1 = 0.f, ls0 = 0.f, ls1 = 0.f;
#pragma unroll
            for (int t = 0; t < 16; t++) {
                int2 m0 = *(const int2*)(mr0 + 8 * t);
                int2 m1 = *(const int2*)(mr1 + 8 * t);
                float g0 = sacc[t][0] * (float)m0.x;
                float g1 = sacc[t][1] * (float)m0.y;
                float g2 = sacc[t][2] * (float)m1.x;
                float g3 = sacc[t][3] * (float)m1.y;
                ss0 += fabsf(g0) + fabsf(g1);
                ss1 += fabsf(g2) + fabsf(g3);
                float p0 = __expf(g0), p1 = __expf(g1);
                float p2 = __expf(g2), p3 = __expf(g3);
                ls0 += p0 + p1; ls1 += p2 + p3;
                sacc[t][0] = p0; sacc[t][1] = p1;
                sacc[t][2] = p2; sacc[t][3] = p3;
            }
            scd0 += (double)ss0; scd1 += (double)ss1;
            l0 += ls0; l1 += ls1;
        }

#pragma unroll
        for (int ks = 0; ks < 8; ks++) {
            float* e = sacc[2 * ks];
            float* o = sacc[2 * ks + 1];
            uint32_t ah0 = packbf2(e[0], e[1]);
            uint32_t ah1 = packbf2(e[2], e[3]);
            uint32_t ah2 = packbf2(o[0], o[1]);
            uint32_t ah3 = packbf2(o[2], o[3]);
            uint32_t am0 = packbf2(e[0] - bflo(ah0), e[1] - bfhi(ah0));
            uint32_t am1 = packbf2(e[2] - bflo(ah1), e[3] - bfhi(ah1));
            uint32_t am2 = packbf2(o[0] - bflo(ah2), o[1] - bfhi(ah2));
            uint32_t am3 = packbf2(o[2] - bflo(ah3), o[3] - bfhi(ah3));
            uint32_t ch = (uint32_t)(ks * 2 + (lane >> 4));
#pragma unroll
            for (int nd = 0; nd < 4; nd++) {
                uint32_t br = (uint32_t)(nd * 16 + (lane & 15));
                uint32_t boff = br * 256 + ((ch ^ (br & 7)) << 4);
                uint32_t vh0, vh1, vh2, vh3, vm0, vm1, vm2, vm3;
                ldsm4(VH + boff, vh0, vh1, vh2, vh3);
                ldsm4(VM + boff, vm0, vm1, vm2, vm3);
                mma16816(oacc[2 * nd + 0], ah0, ah1, ah2, ah3, vh0, vh2);
                mma16816(oacc[2 * nd + 1], ah0, ah1, ah2, ah3, vh1, vh3);
                mma16816(oacc[2 * nd + 0], ah0, ah1, ah2, ah3, vm0, vm2);
                mma16816(oacc[2 * nd + 1], ah0, ah1, ah2, ah3, vm1, vm3);
                mma16816(oacc[2 * nd + 0], am0, am1, am2, am3, vh0, vh2);
                mma16816(oacc[2 * nd + 1], am0, am1, am2, am3, vh1, vh3);
            }
        }
        __syncthreads();
        buf ^= 1;
    }

    l0 += __shfl_xor_sync(0xffffffffu, l0, 1);
    l0 += __shfl_xor_sync(0xffffffffu, l0, 2);
    l1 += __shfl_xor_sync(0xffffffffu, l1, 1);
    l1 += __shfl_xor_sync(0xffffffffu, l1, 2);
    scd0 += __shfl_xor_sync(0xffffffffu, scd0, 1);
    scd0 += __shfl_xor_sync(0xffffffffu, scd0, 2);
    scd1 += __shfl_xor_sync(0xffffffffu, scd1, 1);
    scd1 += __shfl_xor_sync(0xffffffffu, scd1, 2);
    float inv0 = 1.0f / l0, inv1 = 1.0f / l1;

    int r0 = q0 + w * 16 + (lane >> 2);
    int r1 = r0 + 8;
#pragma unroll
    for (int t = 0; t < 8; t++) {
        int col = h * DHE + 8 * t + (lane & 3) * 2;
        float a0 = oacc[t][0] * inv0, a1 = oacc[t][1] * inv0;
        float b0 = oacc[t][2] * inv1, b1 = oacc[t][3] * inv1;
        uint32_t h0 = packbf2(a0, a1), h1 = packbf2(b0, b1);
        uint32_t m0 = packbf2(a0 - bflo(h0), a1 - bfhi(h0));
        uint32_t m1 = packbf2(b0 - bflo(h1), b1 - bfhi(h1));
        *(uint32_t*)&g_ah[(size_t)(b * NTOK + r0) * DINNER + col] = h0;
        *(uint32_t*)&g_am[(size_t)(b * NTOK + r0) * DINNER + col] = m0;
        *(uint32_t*)&g_ah[(size_t)(b * NTOK + r1) * DINNER + col] = h1;
        *(uint32_t*)&g_am[(size_t)(b * NTOK + r1) * DINNER + col] = m1;
    }
    if ((lane & 3) == 0) {
        atomicAdd(&g_score[b * NTOK + r0], scd0);
        atomicAdd(&g_score[b * NTOK + r1], scd1);
    }
}

// ---------------- sort + swap map ------------------------------------------------
__global__ __launch_bounds__(1024) void sort_swap_kernel(const int* __restrict__ patches)
{
    int bb = blockIdx.x;
    int t = threadIdx.x;
    __shared__ double sval[NTOK];
    __shared__ int sidx[NTOK];
    sval[t] = g_score[bb * NTOK + t] / (double)g_nnz[t];
    sidx[t] = t;
    __syncthreads();

    for (int k = 2; k <= NTOK; k <<= 1) {
        for (int j = k >> 1; j > 0; j >>= 1) {
            int ixj = t ^ j;
            if (ixj > t) {
                double v1 = sval[t], v2 = sval[ixj];
                int i1 = sidx[t], i2 = sidx[ixj];
                bool gt = (v1 > v2) || (v1 == v2 && i1 > i2);
                bool up = ((t & k) == 0);
                if (gt == up) {
                    sval[t] = v2; sval[ixj] = v1;
                    sidx[t] = i2; sidx[ixj] = i1;
                }
            }
            __syncthreads();
        }
    }

    int bo = (BSZ - 1) - bb;
    g_src[bo * NTOK + t] = t;
    __syncthreads();
    if (t == 0) {
        int P = patches[0];
        for (int i = 1; i <= P; i++) {
            int ti = sidx[i];
            g_src[bo * NTOK + i] = ti;
            g_src[bo * NTOK + ti] = i;
        }
    }
}

// ---------------- launch -----------------------------------------------------------
extern "C" void kernel_launch(void* const* d_in, const int* in_sizes, int n_in,
                              void* d_out, int out_size)
{
    const float* x       = (const float*)d_in[0];
    const int*   cp_mask = (const int*)d_in[1];
    const float* w_qkv   = (const float*)d_in[2];
    const float* w_out   = (const float*)d_in[3];
    const float* b_out   = (const float*)d_in[4];
    const int*   patches = (const int*)d_in[5];
    float* out = (float*)d_out;

    cudaFuncSetAttribute(gemm_mma_kernel, cudaFuncAttributeMaxDynamicSharedMemorySize, GEMM_SMEM);
    cudaFuncSetAttribute(attn_mma_kernel, cudaFuncAttributeMaxDynamicSharedMemorySize, ATT_SMEM);

    nnz_kernel<<<NTOK, 256>>>(cp_mask);
    cvt_split3_kernel<<<(BSZ * NTOK * DMODEL) / 512, 512>>>(x, BSZ * NTOK * DMODEL);
    transpose_split3_kernel<<<dim3(QKV3 / 32, DMODEL / 32), dim3(32, 8)>>>(w_qkv, 0, DMODEL, QKV3);
    transpose_split3_kernel<<<dim3(DMODEL / 32, DINNER / 32), dim3(32, 8)>>>(w_out, 1, DINNER, DMODEL);
    gemm_mma_kernel<<<dim3(QKV3 / 128, (BSZ * NTOK) / 128), 256, GEMM_SMEM>>>(0, nullptr, nullptr);
    attn_mma_kernel<<<dim3(8, NH, BSZ), 256, ATT_SMEM>>>(cp_mask);
    sort_swap_kernel<<<BSZ, 1024>>>(patches);
    gemm_mma_kernel<<<dim3(DMODEL / 128, (BSZ * NTOK) / 128), 256, GEMM_SMEM>>>(1, out, b_out);
}

// round 16
// speedup vs baseline: 2.6278x; 1.0107x over previous
#include <cuda_runtime.h>
#include <cuda_bf16.h>
#include <math.h>
#include <stdint.h>

#define BSZ    8
#define NTOK   1024
#define DMODEL 512
#define QKV3   1536
#define NH     8
#define DHE    64
#define DINNER 512
#define ASCALE 0.125f
typedef unsigned long long u64;

// ---------------- scratch (device globals; referenced ONLY from device code) --
__device__ double g_score[BSZ * NTOK];
__device__ float  g_nnz[NTOK];
__device__ int    g_src[BSZ * NTOK];
__device__ __align__(16) __nv_bfloat16 g_qkvh[BSZ*NTOK*1024], g_qkvm[BSZ*NTOK*1024];
__device__ __align__(16) __nv_bfloat16 g_vth[BSZ*NH*64*1024], g_vtm[BSZ*NH*64*1024];
__device__ __align__(16) __nv_bfloat16 g_xh[BSZ*NTOK*DMODEL], g_xm[BSZ*NTOK*DMODEL], g_xl[BSZ*NTOK*DMODEL];
__device__ __align__(16) __nv_bfloat16 g_ah[BSZ*NTOK*DINNER], g_am[BSZ*NTOK*DINNER];
__device__ __align__(16) __nv_bfloat16 g_wqh[QKV3*DMODEL], g_wqm[QKV3*DMODEL], g_wql[QKV3*DMODEL];
__device__ __align__(16) __nv_bfloat16 g_woh[DINNER*DMODEL], g_wom[DINNER*DMODEL], g_wol[DINNER*DMODEL];

// ---------------- helpers -------------------------------------------------------
static __device__ __forceinline__ uint32_t smem_to_u32(const void* p) {
    uint32_t a;
    asm("{ .reg .u64 t; cvta.to.shared.u64 t, %1; cvt.u32.u64 %0, t; }" : "=r"(a) : "l"(p));
    return a;
}
static __device__ __forceinline__ void ldsm4(uint32_t addr, uint32_t& r0, uint32_t& r1,
                                             uint32_t& r2, uint32_t& r3) {
    asm volatile("ldmatrix.sync.aligned.m8n8.x4.shared.b16 {%0,%1,%2,%3}, [%4];"
        : "=r"(r0), "=r"(r1), "=r"(r2), "=r"(r3) : "r"(addr));
}
static __device__ __forceinline__ void mma16816(float* c,
    uint32_t a0, uint32_t a1, uint32_t a2, uint32_t a3, uint32_t b0, uint32_t b1) {
    asm volatile("mma.sync.aligned.m16n8k16.row.col.f32.bf16.bf16.f32 "
        "{%0,%1,%2,%3}, {%4,%5,%6,%7}, {%8,%9}, {%0,%1,%2,%3};"
        : "+f"(c[0]), "+f"(c[1]), "+f"(c[2]), "+f"(c[3])
        : "r"(a0), "r"(a1), "r"(a2), "r"(a3), "r"(b0), "r"(b1));
}
static __device__ __forceinline__ uint32_t packbf2(float lo, float hi) {
    uint32_t r;
    asm("cvt.rn.bf16x2.f32 %0, %1, %2;" : "=r"(r) : "f"(hi), "f"(lo));
    return r;
}
static __device__ __forceinline__ float bflo(uint32_t p) { return __uint_as_float(p << 16); }
static __device__ __forceinline__ float bfhi(uint32_t p) { return __uint_as_float(p & 0xffff0000u); }
#define CP_ASYNC16(dst, src) \
    asm volatile("cp.async.cg.shared.global [%0], [%1], 16;" :: "r"(dst), "l"(src) : "memory")
#define CP_COMMIT() asm volatile("cp.async.commit_group;" ::: "memory")
#define CP_WAIT(n)  asm volatile("cp.async.wait_group %0;" :: "n"(n) : "memory")

// ---------------- small kernels -------------------------------------------------
__global__ void nnz_kernel(const int* __restrict__ mask) {
    int row = blockIdx.x, t = threadIdx.x;
    int gi = row * 256 + t;
    if (gi < BSZ * NTOK) g_score[gi] = 0.0;
    int cnt = 0;
    for (int c = t; c < NTOK; c += 256) cnt += (mask[row * NTOK + c] != 0);
    for (int o = 16; o; o >>= 1) cnt += __shfl_xor_sync(0xffffffffu, cnt, o);
    __shared__ int sred[8];
    if ((t & 31) == 0) sred[t >> 5] = cnt;
    __syncthreads();
    if (t == 0) {
        int s = 0;
        for (int i = 0; i < 8; i++) s += sred[i];
        g_nnz[row] = (float)s;
    }
}
__global__ void cvt_split3_kernel(const float* __restrict__ src, int n)
{
    int i = blockIdx.x * blockDim.x + threadIdx.x;
    if (i >= n) return;
    float v = src[i];
    __nv_bfloat16 hh = __float2bfloat16(v);
    float r1 = v - __bfloat162float(hh);
    __nv_bfloat16 mm = __float2bfloat16(r1);
    float r2 = r1 - __bfloat162float(mm);
    g_xh[i] = hh; g_xm[i] = mm; g_xl[i] = __float2bfloat16(r2);
}
__global__ void transpose_split3_kernel(const float* __restrict__ src, int sel,
                                        int K, int N)
{
    __shared__ float t[32][33];
    __nv_bfloat16 *h = sel ? g_woh : g_wqh;
    __nv_bfloat16 *m = sel ? g_wom : g_wqm;
    __nv_bfloat16 *l = sel ? g_wol : g_wql;
    int k0 = blockIdx.y * 32, n0 = blockIdx.x * 32;
    int tx = threadIdx.x, ty = threadIdx.y;
#pragma unroll
    for (int j = 0; j < 32; j += 8)
        t[ty + j][tx] = src[(size_t)(k0 + ty + j) * N + n0 + tx];
    __syncthreads();
#pragma unroll
    for (int j = 0; j < 32; j += 8) {
        float v = t[tx][ty + j];
        int n = n0 + ty + j, k = k0 + tx;
        __nv_bfloat16 hh = __float2bfloat16(v);
        float r1 = v - __bfloat162float(hh);
        __nv_bfloat16 mm = __float2bfloat16(r1);
        float r2 = r1 - __bfloat162float(mm);
        h[(size_t)n * K + k] = hh;
        m[(size_t)n * K + k] = mm;
        l[(size_t)n * K + k] = __float2bfloat16(r2);
    }
}

// ---------------- HMMA GEMM ------------------------------------------------------
#define TILE_B 16384
#define SMG_HDR 1024
#define GEMM_SMEM (SMG_HDR + 6 * TILE_B)

__global__ __launch_bounds__(256, 2) void gemm_mma_kernel(
    int sel, float* __restrict__ OutX, const float* __restrict__ bias)
{
    extern __shared__ char smg[];
    uint32_t sb = smem_to_u32(smg);
    int tid = threadIdx.x, lane = tid & 31, wid = tid >> 5;
    int wm = wid & 3, wn = wid >> 2;
    int bm = blockIdx.y * 128, bn = blockIdx.x * 128;

    const uint4 *A0, *A1, *A2, *B0, *B1, *B2;
    if (sel) {
        A0 = (const uint4*)g_ah;  A1 = (const uint4*)g_am;  A2 = A0;
        B0 = (const uint4*)g_woh; B1 = (const uint4*)g_wom; B2 = B0;
    } else {
        A0 = (const uint4*)g_xh;  A1 = (const uint4*)g_xm;  A2 = (const uint4*)g_xl;
        B0 = (const uint4*)g_wqh; B1 = (const uint4*)g_wqm; B2 = (const uint4*)g_wql;
    }
    const int tmax = (sel || bn >= 1024) ? 1 : 2;
    int* rmap = (int*)smg;
    float* sbias = (float*)(smg + 512);
    if (tid < 128) {
        int row = bm + tid;
        rmap[tid] = sel ? ((row & ~(NTOK - 1)) + g_src[row]) : row;
        sbias[tid] = sel ? bias[bn + tid] : 0.f;
    }

    float acc[16][4];
#pragma unroll
    for (int i = 0; i < 16; i++)
#pragma unroll
        for (int j = 0; j < 4; j++) acc[i][j] = 0.f;

#pragma unroll 1
    for (int c = 0; c < 8; c++) {
        __syncthreads();
#pragma unroll
        for (int l = 0; l < 4; l++) {
            int idx = tid + l * 256;
            int r = idx >> 3, q = idx & 7;
            uint32_t so = (uint32_t)(r * 128 + ((q ^ (r & 7)) << 4));
            size_t ga = (size_t)rmap[r] * 64 + c * 8 + q;
            size_t gb = (size_t)(bn + r) * 64 + c * 8 + q;
            CP_ASYNC16(sb + SMG_HDR + 0 * TILE_B + so, A0 + ga);
            CP_ASYNC16(sb + SMG_HDR + 1 * TILE_B + so, A1 + ga);
            CP_ASYNC16(sb + SMG_HDR + 3 * TILE_B + so, B0 + gb);
            CP_ASYNC16(sb + SMG_HDR + 4 * TILE_B + so, B1 + gb);
            if (tmax == 2) {
                CP_ASYNC16(sb + SMG_HDR + 2 * TILE_B + so, A2 + ga);
                CP_ASYNC16(sb + SMG_HDR + 5 * TILE_B + so, B2 + gb);
            }
        }
        CP_COMMIT();
        CP_WAIT(0);
        __syncthreads();

#pragma unroll
        for (int ks = 0; ks < 4; ks++) {
            uint32_t ch = (uint32_t)(ks * 2 + (lane >> 4));
            uint32_t ar0 = (uint32_t)(wm * 32 + (lane & 15));
            uint32_t ar1 = ar0 + 16;
            uint32_t aoff0 = ar0 * 128 + ((ch ^ (ar0 & 7)) << 4);
            uint32_t aoff1 = ar1 * 128 + ((ch ^ (ar1 & 7)) << 4);
            uint32_t boff[4];
#pragma unroll
            for (int nb = 0; nb < 4; nb++) {
                uint32_t br = (uint32_t)(wn * 64 + nb * 16 + (lane & 15));
                boff[nb] = br * 128 + ((ch ^ (br & 7)) << 4);
            }
            uint32_t Af[3][8];
#pragma unroll
            for (int s = 0; s < 3; s++) {
                if (s <= tmax) {
                    ldsm4(sb + SMG_HDR + s * TILE_B + aoff0, Af[s][0], Af[s][1], Af[s][2], Af[s][3]);
                    ldsm4(sb + SMG_HDR + s * TILE_B + aoff1, Af[s][4], Af[s][5], Af[s][6], Af[s][7]);
                }
            }
#pragma unroll
            for (int bs = 0; bs < 3; bs++) {
                if (bs > tmax) continue;
                uint32_t bbase = sb + SMG_HDR + (3 + bs) * TILE_B;
#pragma unroll
                for (int nb = 0; nb < 4; nb++) {
                    uint32_t b0, b1, b2, b3;
                    ldsm4(bbase + boff[nb], b0, b1, b2, b3);
#pragma unroll
                    for (int s = 0; s < 3; s++) {
                        if (s + bs <= tmax) {
                            mma16816(acc[nb * 2 + 0],     Af[s][0], Af[s][1], Af[s][2], Af[s][3], b0, b2);
                            mma16816(acc[nb * 2 + 1],     Af[s][0], Af[s][1], Af[s][2], Af[s][3], b1, b3);
                            mma16816(acc[8 + nb * 2 + 0], Af[s][4], Af[s][5], Af[s][6], Af[s][7], b0, b2);
                            mma16816(acc[8 + nb * 2 + 1], Af[s][4], Af[s][5], Af[s][6], Af[s][7], b1, b3);
                        }
                    }
                }
            }
        }
    }

    // ---- epilogue ----
#pragma unroll
    for (int ma = 0; ma < 2; ma++) {
        int row = bm + wm * 32 + ma * 16 + (lane >> 2);
#pragma unroll
        for (int na = 0; na < 8; na++) {
            int colr = wn * 64 + na * 8 + (lane & 3) * 2;
            int col = bn + colr;
            float* a = acc[ma * 8 + na];
            float2 v0 = make_float2(a[0] + sbias[colr], a[1] + sbias[colr + 1]);
            float2 v1 = make_float2(a[2] + sbias[colr], a[3] + sbias[colr + 1]);
            if (sel) {
                *(float2*)&OutX[(size_t)row * DMODEL + col] = v0;
                *(float2*)&OutX[(size_t)(row + 8) * DMODEL + col] = v1;
            } else if (col < 1024) {
                float sc = (col < 512) ? ASCALE : 1.f;
                float u0 = v0.x * sc, u1 = v0.y * sc;
                float w0 = v1.x * sc, w1 = v1.y * sc;
                uint32_t h0 = packbf2(u0, u1), h1 = packbf2(w0, w1);
                uint32_t m0 = packbf2(u0 - bflo(h0), u1 - bfhi(h0));
                uint32_t m1 = packbf2(w0 - bflo(h1), w1 - bfhi(h1));
                *(uint32_t*)&g_qkvh[(size_t)row * 1024 + col] = h0;
                *(uint32_t*)&g_qkvm[(size_t)row * 1024 + col] = m0;
                *(uint32_t*)&g_qkvh[(size_t)(row + 8) * 1024 + col] = h1;
                *(uint32_t*)&g_qkvm[(size_t)(row + 8) * 1024 + col] = m1;
            } else {
                int vc = col - 1024;
                int hh = vc >> 6, dd = vc & 63;
                int bb2 = row >> 10, tok = row & 1023;
                size_t base = ((size_t)(bb2 * NH + hh) * 64 + dd) * 1024 + tok;
                __nv_bfloat16 e;
                e = __float2bfloat16(v0.x);
                g_vth[base] = e;
                g_vtm[base] = __float2bfloat16(v0.x - __bfloat162float(e));
                e = __float2bfloat16(v0.y);
                g_vth[base + 1024] = e;
                g_vtm[base + 1024] = __float2bfloat16(v0.y - __bfloat162float(e));
                e = __float2bfloat16(v1.x);
                g_vth[base + 8] = e;
                g_vtm[base + 8] = __float2bfloat16(v1.x - __bfloat162float(e));
                e = __float2bfloat16(v1.y);
                g_vth[base + 1024 + 8] = e;
                g_vtm[base + 1024 + 8] = __float2bfloat16(v1.y - __bfloat162float(e));
            }
        }
    }
}

// ---------------- HMMA flash attention: single buffer, 2 CTAs/SM ----------------
// Q: 2x16KB persistent. KV buffer: KH|KM|VH|VM = 64KB (single). 96KB/CTA total.
// S/PV processed in two 64-wide k-halves to keep sacc at 32 regs.
#define AQH 0
#define AQM 16384
#define ABUF 32768
#define ATT_SMEM (ABUF + 65536)

__global__ __launch_bounds__(256, 2) void attn_mma_kernel(const int* __restrict__ mask)
{
    extern __shared__ char sma[];
    uint32_t sb = smem_to_u32(sma);
    int tid = threadIdx.x, lane = tid & 31, w = tid >> 5;
    int qt = blockIdx.x, h = blockIdx.y, b = blockIdx.z;
    int q0 = qt * 128;

    // ---- Q tiles via cp.async ----
#pragma unroll
    for (int l = 0; l < 8; l++) {
        int idx = tid + l * 256;
        int ts = idx >> 10;
        int rem = idx & 1023;
        int r = rem >> 3, q = rem & 7;
        const __nv_bfloat16* src = (ts ? g_qkvm : g_qkvh) +
            (((size_t)(b * NTOK + q0 + r) * 128 + h * 8 + q) << 3);
        uint32_t dst = sb + (ts ? AQM : AQH) + (uint32_t)(r * 128 + ((q ^ (r & 7)) << 4));
        CP_ASYNC16(dst, src);
    }

    float oacc[8][4];
#pragma unroll
    for (int i = 0; i < 8; i++)
#pragma unroll
        for (int j = 0; j < 4; j++) oacc[i][j] = 0.f;
    float l0 = 0.f, l1 = 0.f;
    double scd0 = 0.0, scd1 = 0.0;

    uint32_t KH = sb + ABUF;
    uint32_t KM = KH + 16384;
    uint32_t VH = KH + 32768;
    uint32_t VM = KH + 49152;

#pragma unroll 1
    for (int kt = 0; kt < 8; kt++) {
        int k0 = kt * 128;
        // ---- load KV tile (single buffer) ----
#pragma unroll
        for (int l = 0; l < 16; l++) {
            int idx = tid + l * 256;
            if (idx < 2048) {
                int ts = idx >> 10;
                int rem = idx & 1023;
                int r = rem >> 3, q = rem & 7;
                const __nv_bfloat16* src = (ts ? g_qkvm : g_qkvh) +
                    (((size_t)(b * NTOK + k0 + r) * 128 + 64 + h * 8 + q) << 3);
                uint32_t dst = KH + ts * 16384 + (uint32_t)(r * 128 + ((q ^ (r & 7)) << 4));
                CP_ASYNC16(dst, src);
            } else {
                int idx2 = idx - 2048;
                int ts = idx2 >> 10;
                int rem = idx2 & 1023;
                int d = rem >> 4, c = rem & 15;
                const __nv_bfloat16* src = (ts ? g_vtm : g_vth) +
                    ((((size_t)(b * NH + h) * 64 + d) * 128 + (k0 >> 3) + c) << 3);
                uint32_t dst = VH + ts * 16384 + (uint32_t)(d * 256 + ((c ^ (d & 7)) << 4));
                CP_ASYNC16(dst, src);
            }
        }
        CP_COMMIT();
        CP_WAIT(0);
        __syncthreads();

        // ---- two 64-wide k-halves ----
#pragma unroll
        for (int half = 0; half < 2; half++) {
            float sacc[8][4];
#pragma unroll
            for (int i = 0; i < 8; i++)
#pragma unroll
                for (int j = 0; j < 4; j++) sacc[i][j] = 0.f;

            // S = Q K^T (3 split terms) for k columns [half*64, half*64+64)
#pragma unroll
            for (int ks = 0; ks < 4; ks++) {
                uint32_t ch = (uint32_t)(ks * 2 + (lane >> 4));
                uint32_t ar = (uint32_t)(w * 16 + (lane & 15));
                uint32_t aoff = ar * 128 + ((ch ^ (ar & 7)) << 4);
                uint32_t qh0, qh1, qh2, qh3, qm0, qm1, qm2, qm3;
                ldsm4(sb + AQH + aoff, qh0, qh1, qh2, qh3);
                ldsm4(sb + AQM + aoff, qm0, qm1, qm2, qm3);
#pragma unroll
                for (int nb = 0; nb < 4; nb++) {
                    uint32_t br = (uint32_t)((half * 4 + nb) * 16 + (lane & 15));
                    uint32_t boff = br * 128 + ((ch ^ (br & 7)) << 4);
                    uint32_t kh0, kh1, kh2, kh3, km0, km1, km2, km3;
                    ldsm4(KH + boff, kh0, kh1, kh2, kh3);
                    ldsm4(KM + boff, km0, km1, km2, km3);
                    mma16816(sacc[2 * nb + 0], qh0, qh1, qh2, qh3, kh0, kh2);
                    mma16816(sacc[2 * nb + 1], qh0, qh1, qh2, qh3, kh1, kh3);
                    mma16816(sacc[2 * nb + 0], qh0, qh1, qh2, qh3, km0, km2);
                    mma16816(sacc[2 * nb + 1], qh0, qh1, qh2, qh3, km1, km3);
                    mma16816(sacc[2 * nb + 0], qm0, qm1, qm2, qm3, kh0, kh2);
                    mma16816(sacc[2 * nb + 1], qm0, qm1, qm2, qm3, kh1, kh3);
                }
            }

            // mask, score, exp
            {
                int r0g = q0 + w * 16 + (lane >> 2);
                const int* mr0 = mask + (size_t)r0g * NTOK + k0 + half * 64 + (lane & 3) * 2;
                const int* mr1 = mr0 + (size_t)8 * NTOK;
                float ss0 = 0.f, ss1 = 0.f, ls0 = 0.f, ls1 = 0.f;
#pragma unroll
                for (int t = 0; t < 8; t++) {
                    int2 m0 = *(const int2*)(mr0 + 8 * t);
                    int2 m1 = *(const int2*)(mr1 + 8 * t);
                    float g0 = sacc[t][0] * (float)m0.x;
                    float g1 = sacc[t][1] * (float)m0.y;
                    float g2 = sacc[t][2] * (float)m1.x;
                    float g3 = sacc[t][3] * (float)m1.y;
                    ss0 += fabsf(g0) + fabsf(g1);
                    ss1 += fabsf(g2) + fabsf(g3);
                    float p0 = __expf(g0), p1 = __expf(g1);
                    float p2 = __expf(g2), p3 = __expf(g3);
                    ls0 += p0 + p1; ls1 += p2 + p3;
                    sacc[t][0] = p0; sacc[t][1] = p1;
                    sacc[t][2] = p2; sacc[t][3] = p3;
                }
                scd0 += (double)ss0; scd1 += (double)ss1;
                l0 += ls0; l1 += ls1;
            }

            // O += P V (3 terms) for k16 steps [half*4, half*4+4)
#pragma unroll
            for (int ks2 = 0; ks2 < 4; ks2++) {
                float* e = sacc[2 * ks2];
                float* o = sacc[2 * ks2 + 1];
                uint32_t ah0 = packbf2(e[0], e[1]);
                uint32_t ah1 = packbf2(e[2], e[3]);
                uint32_t ah2 = packbf2(o[0], o[1]);
                uint32_t ah3 = packbf2(o[2], o[3]);
                uint32_t am0 = packbf2(e[0] - bflo(ah0), e[1] - bfhi(ah0));
                uint32_t am1 = packbf2(e[2] - bflo(ah1), e[3] - bfhi(ah1));
                uint32_t am2 = packbf2(o[0] - bflo(ah2), o[1] - bfhi(ah2));
                uint32_t am3 = packbf2(o[2] - bflo(ah3), o[3] - bfhi(ah3));
                uint32_t ch = (uint32_t)((half * 4 + ks2) * 2 + (lane >> 4));
#pragma unroll
                for (int nd = 0; nd < 4; nd++) {
                    uint32_t br = (uint32_t)(nd * 16 + (lane & 15));
                    uint32_t boff = br * 256 + ((ch ^ (br & 7)) << 4);
                    uint32_t vh0, vh1, vh2, vh3, vm0, vm1, vm2, vm3;
                    ldsm4(VH + boff, vh0, vh1, vh2, vh3);
                    ldsm4(VM + boff, vm0, vm1, vm2, vm3);
                    mma16816(oacc[2 * nd + 0], ah0, ah1, ah2, ah3, vh0, vh2);
                    mma16816(oacc[2 * nd + 1], ah0, ah1, ah2, ah3, vh1, vh3);
                    mma16816(oacc[2 * nd + 0], ah0, ah1, ah2, ah3, vm0, vm2);
                    mma16816(oacc[2 * nd + 1], ah0, ah1, ah2, ah3, vm1, vm3);
                    mma16816(oacc[2 * nd + 0], am0, am1, am2, am3, vh0, vh2);
                    mma16816(oacc[2 * nd + 1], am0, am1, am2, am3, vh1, vh3);
                }
            }
        }
        __syncthreads();
    }

    l0 += __shfl_xor_sync(0xffffffffu, l0, 1);
    l0 += __shfl_xor_sync(0xffffffffu, l0, 2);
    l1 += __shfl_xor_sync(0xffffffffu, l1, 1);
    l1 += __shfl_xor_sync(0xffffffffu, l1, 2);
    scd0 += __shfl_xor_sync(0xffffffffu, scd0, 1);
    scd0 += __shfl_xor_sync(0xffffffffu, scd0, 2);
    scd1 += __shfl_xor_sync(0xffffffffu, scd1, 1);
    scd1 += __shfl_xor_sync(0xffffffffu, scd1, 2);
    float inv0 = 1.0f / l0, inv1 = 1.0f / l1;

    int r0 = q0 + w * 16 + (lane >> 2);
    int r1 = r0 + 8;
#pragma unroll
    for (int t = 0; t < 8; t++) {
        int col = h * DHE + 8 * t + (lane & 3) * 2;
        float a0 = oacc[t][0] * inv0, a1 = oacc[t][1] * inv0;
        float b0 = oacc[t][2] * inv1, b1 = oacc[t][3] * inv1;
        uint32_t h0 = packbf2(a0, a1), h1 = packbf2(b0, b1);
        uint32_t m0 = packbf2(a0 - bflo(h0), a1 - bfhi(h0));
        uint32_t m1 = packbf2(b0 - bflo(h1), b1 - bfhi(h1));
        *(uint32_t*)&g_ah[(size_t)(b * NTOK + r0) * DINNER + col] = h0;
        *(uint32_t*)&g_am[(size_t)(b * NTOK + r0) * DINNER + col] = m0;
        *(uint32_t*)&g_ah[(size_t)(b * NTOK + r1) * DINNER + col] = h1;
        *(uint32_t*)&g_am[(size_t)(b * NTOK + r1) * DINNER + col] = m1;
    }
    if ((lane & 3) == 0) {
        atomicAdd(&g_score[b * NTOK + r0], scd0);
        atomicAdd(&g_score[b * NTOK + r1], scd1);
    }
}

// ---------------- sort + swap map ------------------------------------------------
__global__ __launch_bounds__(1024) void sort_swap_kernel(const int* __restrict__ patches)
{
    int bb = blockIdx.x;
    int t = threadIdx.x;
    __shared__ double sval[NTOK];
    __shared__ int sidx[NTOK];
    sval[t] = g_score[bb * NTOK + t] / (double)g_nnz[t];
    sidx[t] = t;
    __syncthreads();

    for (int k = 2; k <= NTOK; k <<= 1) {
        for (int j = k >> 1; j > 0; j >>= 1) {
            int ixj = t ^ j;
            if (ixj > t) {
                double v1 = sval[t], v2 = sval[ixj];
                int i1 = sidx[t], i2 = sidx[ixj];
                bool gt = (v1 > v2) || (v1 == v2 && i1 > i2);
                bool up = ((t & k) == 0);
                if (gt == up) {
                    sval[t] = v2; sval[ixj] = v1;
                    sidx[t] = i2; sidx[ixj] = i1;
                }
            }
            __syncthreads();
        }
    }

    int bo = (BSZ - 1) - bb;
    g_src[bo * NTOK + t] = t;
    __syncthreads();
    if (t == 0) {
        int P = patches[0];
        for (int i = 1; i <= P; i++) {
            int ti = sidx[i];
            g_src[bo * NTOK + i] = ti;
            g_src[bo * NTOK + ti] = i;
        }
    }
}

// ---------------- launch -----------------------------------------------------------
extern "C" void kernel_launch(void* const* d_in, const int* in_sizes, int n_in,
                              void* d_out, int out_size)
{
    const float* x       = (const float*)d_in[0];
    const int*   cp_mask = (const int*)d_in[1];
    const float* w_qkv   = (const float*)d_in[2];
    const float* w_out   = (const float*)d_in[3];
    const float* b_out   = (const float*)d_in[4];
    const int*   patches = (const int*)d_in[5];
    float* out = (float*)d_out;

    cudaFuncSetAttribute(gemm_mma_kernel, cudaFuncAttributeMaxDynamicSharedMemorySize, GEMM_SMEM);
    cudaFuncSetAttribute(attn_mma_kernel, cudaFuncAttributeMaxDynamicSharedMemorySize, ATT_SMEM);

    nnz_kernel<<<NTOK, 256>>>(cp_mask);
    cvt_split3_kernel<<<(BSZ * NTOK * DMODEL) / 512, 512>>>(x, BSZ * NTOK * DMODEL);
    transpose_split3_kernel<<<dim3(QKV3 / 32, DMODEL / 32), dim3(32, 8)>>>(w_qkv, 0, DMODEL, QKV3);
    transpose_split3_kernel<<<dim3(DMODEL / 32, DINNER / 32), dim3(32, 8)>>>(w_out, 1, DINNER, DMODEL);
    gemm_mma_kernel<<<dim3(QKV3 / 128, (BSZ * NTOK) / 128), 256, GEMM_SMEM>>>(0, nullptr, nullptr);
    attn_mma_kernel<<<dim3(8, NH, BSZ), 256, ATT_SMEM>>>(cp_mask);
    sort_swap_kernel<<<BSZ, 1024>>>(patches);
    gemm_mma_kernel<<<dim3(DMODEL / 128, (BSZ * NTOK) / 128), 256, GEMM_SMEM>>>(1, out, b_out);
}

// round 17
// speedup vs baseline: 3.1131x; 1.1847x over previous
#include <cuda_runtime.h>
#include <cuda_bf16.h>
#include <math.h>
#include <stdint.h>

#define BSZ    8
#define NTOK   1024
#define DMODEL 512
#define QKV3   1536
#define NH     8
#define DHE    64
#define DINNER 512
#define ASCALE 0.125f
typedef unsigned long long u64;

// ---------------- scratch (device globals; referenced ONLY from device code) --
__device__ double g_score[BSZ * NTOK];
__device__ float  g_nnz[NTOK];
__device__ int    g_src[BSZ * NTOK];
__device__ __align__(16) __nv_bfloat16 g_qkvh[BSZ*NTOK*1024], g_qkvm[BSZ*NTOK*1024];
__device__ __align__(16) __nv_bfloat16 g_vth[BSZ*NH*64*1024], g_vtm[BSZ*NH*64*1024];
__device__ __align__(16) __nv_bfloat16 g_xh[BSZ*NTOK*DMODEL], g_xm[BSZ*NTOK*DMODEL];
__device__ __align__(16) __nv_bfloat16 g_ah[BSZ*NTOK*DINNER], g_am[BSZ*NTOK*DINNER];
__device__ __align__(16) __nv_bfloat16 g_wqh[QKV3*DMODEL], g_wqm[QKV3*DMODEL];
__device__ __align__(16) __nv_bfloat16 g_woh[DINNER*DMODEL], g_wom[DINNER*DMODEL];

// ---------------- helpers -------------------------------------------------------
static __device__ __forceinline__ uint32_t smem_to_u32(const void* p) {
    uint32_t a;
    asm("{ .reg .u64 t; cvta.to.shared.u64 t, %1; cvt.u32.u64 %0, t; }" : "=r"(a) : "l"(p));
    return a;
}
static __device__ __forceinline__ void ldsm4(uint32_t addr, uint32_t& r0, uint32_t& r1,
                                             uint32_t& r2, uint32_t& r3) {
    asm volatile("ldmatrix.sync.aligned.m8n8.x4.shared.b16 {%0,%1,%2,%3}, [%4];"
        : "=r"(r0), "=r"(r1), "=r"(r2), "=r"(r3) : "r"(addr));
}
static __device__ __forceinline__ void mma16816(float* c,
    uint32_t a0, uint32_t a1, uint32_t a2, uint32_t a3, uint32_t b0, uint32_t b1) {
    asm volatile("mma.sync.aligned.m16n8k16.row.col.f32.bf16.bf16.f32 "
        "{%0,%1,%2,%3}, {%4,%5,%6,%7}, {%8,%9}, {%0,%1,%2,%3};"
        : "+f"(c[0]), "+f"(c[1]), "+f"(c[2]), "+f"(c[3])
        : "r"(a0), "r"(a1), "r"(a2), "r"(a3), "r"(b0), "r"(b1));
}
static __device__ __forceinline__ uint32_t packbf2(float lo, float hi) {
    uint32_t r;
    asm("cvt.rn.bf16x2.f32 %0, %1, %2;" : "=r"(r) : "f"(hi), "f"(lo));
    return r;
}
static __device__ __forceinline__ float bflo(uint32_t p) { return __uint_as_float(p << 16); }
static __device__ __forceinline__ float bfhi(uint32_t p) { return __uint_as_float(p & 0xffff0000u); }
#define CP_ASYNC16(dst, src) \
    asm volatile("cp.async.cg.shared.global [%0], [%1], 16;" :: "r"(dst), "l"(src) : "memory")
#define CP_COMMIT() asm volatile("cp.async.commit_group;" ::: "memory")
#define CP_WAIT(n)  asm volatile("cp.async.wait_group %0;" :: "n"(n) : "memory")

// ---------------- small kernels -------------------------------------------------
__global__ void nnz_kernel(const int* __restrict__ mask) {
    int row = blockIdx.x, t = threadIdx.x;
    int gi = row * 256 + t;
    if (gi < BSZ * NTOK) g_score[gi] = 0.0;
    int cnt = 0;
    for (int c = t; c < NTOK; c += 256) cnt += (mask[row * NTOK + c] != 0);
    for (int o = 16; o; o >>= 1) cnt += __shfl_xor_sync(0xffffffffu, cnt, o);
    __shared__ int sred[8];
    if ((t & 31) == 0) sred[t >> 5] = cnt;
    __syncthreads();
    if (t == 0) {
        int s = 0;
        for (int i = 0; i < 8; i++) s += sred[i];
        g_nnz[row] = (float)s;
    }
}
__global__ void cvt_split2_kernel(const float* __restrict__ src, int n)
{
    int i = blockIdx.x * blockDim.x + threadIdx.x;
    if (i >= n) return;
    float v = src[i];
    __nv_bfloat16 hh = __float2bfloat16(v);
    g_xh[i] = hh;
    g_xm[i] = __float2bfloat16(v - __bfloat162float(hh));
}
__global__ void transpose_split2_kernel(const float* __restrict__ src, int sel,
                                        int K, int N)
{
    __shared__ float t[32][33];
    __nv_bfloat16 *h = sel ? g_woh : g_wqh;
    __nv_bfloat16 *m = sel ? g_wom : g_wqm;
    int k0 = blockIdx.y * 32, n0 = blockIdx.x * 32;
    int tx = threadIdx.x, ty = threadIdx.y;
#pragma unroll
    for (int j = 0; j < 32; j += 8)
        t[ty + j][tx] = src[(size_t)(k0 + ty + j) * N + n0 + tx];
    __syncthreads();
#pragma unroll
    for (int j = 0; j < 32; j += 8) {
        float v = t[tx][ty + j];
        int n = n0 + ty + j, k = k0 + tx;
        __nv_bfloat16 hh = __float2bfloat16(v);
        h[(size_t)n * K + k] = hh;
        m[(size_t)n * K + k] = __float2bfloat16(v - __bfloat162float(hh));
    }
}

// ---------------- HMMA GEMM (2-way split, 3 terms, 4 tiles) ----------------------
#define TILE_B 16384
#define SMG_HDR 1024
#define GEMM_SMEM (SMG_HDR + 4 * TILE_B)

__global__ __launch_bounds__(256, 2) void gemm_mma_kernel(
    int sel, float* __restrict__ OutX, const float* __restrict__ bias)
{
    extern __shared__ char smg[];
    uint32_t sb = smem_to_u32(smg);
    int tid = threadIdx.x, lane = tid & 31, wid = tid >> 5;
    int wm = wid & 3, wn = wid >> 2;
    int bm = blockIdx.y * 128, bn = blockIdx.x * 128;

    const uint4 *A0, *A1, *B0, *B1;
    if (sel) {
        A0 = (const uint4*)g_ah;  A1 = (const uint4*)g_am;
        B0 = (const uint4*)g_woh; B1 = (const uint4*)g_wom;
    } else {
        A0 = (const uint4*)g_xh;  A1 = (const uint4*)g_xm;
        B0 = (const uint4*)g_wqh; B1 = (const uint4*)g_wqm;
    }
    int* rmap = (int*)smg;
    float* sbias = (float*)(smg + 512);
    if (tid < 128) {
        int row = bm + tid;
        rmap[tid] = sel ? ((row & ~(NTOK - 1)) + g_src[row]) : row;
        sbias[tid] = sel ? bias[bn + tid] : 0.f;
    }

    float acc[16][4];
#pragma unroll
    for (int i = 0; i < 16; i++)
#pragma unroll
        for (int j = 0; j < 4; j++) acc[i][j] = 0.f;

#pragma unroll 1
    for (int c = 0; c < 8; c++) {
        __syncthreads();
#pragma unroll
        for (int l = 0; l < 4; l++) {
            int idx = tid + l * 256;
            int r = idx >> 3, q = idx & 7;
            uint32_t so = (uint32_t)(r * 128 + ((q ^ (r & 7)) << 4));
            size_t ga = (size_t)rmap[r] * 64 + c * 8 + q;
            size_t gb = (size_t)(bn + r) * 64 + c * 8 + q;
            CP_ASYNC16(sb + SMG_HDR + 0 * TILE_B + so, A0 + ga);
            CP_ASYNC16(sb + SMG_HDR + 1 * TILE_B + so, A1 + ga);
            CP_ASYNC16(sb + SMG_HDR + 2 * TILE_B + so, B0 + gb);
            CP_ASYNC16(sb + SMG_HDR + 3 * TILE_B + so, B1 + gb);
        }
        CP_COMMIT();
        CP_WAIT(0);
        __syncthreads();

#pragma unroll
        for (int ks = 0; ks < 4; ks++) {
            uint32_t ch = (uint32_t)(ks * 2 + (lane >> 4));
            uint32_t ar0 = (uint32_t)(wm * 32 + (lane & 15));
            uint32_t ar1 = ar0 + 16;
            uint32_t aoff0 = ar0 * 128 + ((ch ^ (ar0 & 7)) << 4);
            uint32_t aoff1 = ar1 * 128 + ((ch ^ (ar1 & 7)) << 4);
            uint32_t boff[4];
#pragma unroll
            for (int nb = 0; nb < 4; nb++) {
                uint32_t br = (uint32_t)(wn * 64 + nb * 16 + (lane & 15));
                boff[nb] = br * 128 + ((ch ^ (br & 7)) << 4);
            }
            uint32_t Af[2][8];
#pragma unroll
            for (int s = 0; s < 2; s++) {
                ldsm4(sb + SMG_HDR + s * TILE_B + aoff0, Af[s][0], Af[s][1], Af[s][2], Af[s][3]);
                ldsm4(sb + SMG_HDR + s * TILE_B + aoff1, Af[s][4], Af[s][5], Af[s][6], Af[s][7]);
            }
#pragma unroll
            for (int bs = 0; bs < 2; bs++) {
                uint32_t bbase = sb + SMG_HDR + (2 + bs) * TILE_B;
#pragma unroll
                for (int nb = 0; nb < 4; nb++) {
                    uint32_t b0, b1, b2, b3;
                    ldsm4(bbase + boff[nb], b0, b1, b2, b3);
#pragma unroll
                    for (int s = 0; s < 2; s++) {
                        if (s + bs <= 1) {
                            mma16816(acc[nb * 2 + 0],     Af[s][0], Af[s][1], Af[s][2], Af[s][3], b0, b2);
                            mma16816(acc[nb * 2 + 1],     Af[s][0], Af[s][1], Af[s][2], Af[s][3], b1, b3);
                            mma16816(acc[8 + nb * 2 + 0], Af[s][4], Af[s][5], Af[s][6], Af[s][7], b0, b2);
                            mma16816(acc[8 + nb * 2 + 1], Af[s][4], Af[s][5], Af[s][6], Af[s][7], b1, b3);
                        }
                    }
                }
            }
        }
    }

    // ---- epilogue ----
#pragma unroll
    for (int ma = 0; ma < 2; ma++) {
        int row = bm + wm * 32 + ma * 16 + (lane >> 2);
#pragma unroll
        for (int na = 0; na < 8; na++) {
            int colr = wn * 64 + na * 8 + (lane & 3) * 2;
            int col = bn + colr;
            float* a = acc[ma * 8 + na];
            float2 v0 = make_float2(a[0] + sbias[colr], a[1] + sbias[colr + 1]);
            float2 v1 = make_float2(a[2] + sbias[colr], a[3] + sbias[colr + 1]);
            if (sel) {
                *(float2*)&OutX[(size_t)row * DMODEL + col] = v0;
                *(float2*)&OutX[(size_t)(row + 8) * DMODEL + col] = v1;
            } else if (col < 1024) {
                float sc = (col < 512) ? ASCALE : 1.f;
                float u0 = v0.x * sc, u1 = v0.y * sc;
                float w0 = v1.x * sc, w1 = v1.y * sc;
                uint32_t h0 = packbf2(u0, u1), h1 = packbf2(w0, w1);
                uint32_t m0 = packbf2(u0 - bflo(h0), u1 - bfhi(h0));
                uint32_t m1 = packbf2(w0 - bflo(h1), w1 - bfhi(h1));
                *(uint32_t*)&g_qkvh[(size_t)row * 1024 + col] = h0;
                *(uint32_t*)&g_qkvm[(size_t)row * 1024 + col] = m0;
                *(uint32_t*)&g_qkvh[(size_t)(row + 8) * 1024 + col] = h1;
                *(uint32_t*)&g_qkvm[(size_t)(row + 8) * 1024 + col] = m1;
            } else {
                int vc = col - 1024;
                int hh = vc >> 6, dd = vc & 63;
                int bb2 = row >> 10, tok = row & 1023;
                size_t base = ((size_t)(bb2 * NH + hh) * 64 + dd) * 1024 + tok;
                __nv_bfloat16 e;
                e = __float2bfloat16(v0.x);
                g_vth[base] = e;
                g_vtm[base] = __float2bfloat16(v0.x - __bfloat162float(e));
                e = __float2bfloat16(v0.y);
                g_vth[base + 1024] = e;
                g_vtm[base + 1024] = __float2bfloat16(v0.y - __bfloat162float(e));
                e = __float2bfloat16(v1.x);
                g_vth[base + 8] = e;
                g_vtm[base + 8] = __float2bfloat16(v1.x - __bfloat162float(e));
                e = __float2bfloat16(v1.y);
                g_vth[base + 1024 + 8] = e;
                g_vtm[base + 1024 + 8] = __float2bfloat16(v1.y - __bfloat162float(e));
            }
        }
    }
}

// ---------------- HMMA flash attention: single buffer, 2 CTAs/SM ----------------
#define AQH 0
#define AQM 16384
#define ABUF 32768
#define ATT_SMEM (ABUF + 65536)

__global__ __launch_bounds__(256, 2) void attn_mma_kernel(const int* __restrict__ mask)
{
    extern __shared__ char sma[];
    uint32_t sb = smem_to_u32(sma);
    int tid = threadIdx.x, lane = tid & 31, w = tid >> 5;
    int qt = blockIdx.x, h = blockIdx.y, b = blockIdx.z;
    int q0 = qt * 128;

#pragma unroll
    for (int l = 0; l < 8; l++) {
        int idx = tid + l * 256;
        int ts = idx >> 10;
        int rem = idx & 1023;
        int r = rem >> 3, q = rem & 7;
        const __nv_bfloat16* src = (ts ? g_qkvm : g_qkvh) +
            (((size_t)(b * NTOK + q0 + r) * 128 + h * 8 + q) << 3);
        uint32_t dst = sb + (ts ? AQM : AQH) + (uint32_t)(r * 128 + ((q ^ (r & 7)) << 4));
        CP_ASYNC16(dst, src);
    }

    float oacc[8][4];
#pragma unroll
    for (int i = 0; i < 8; i++)
#pragma unroll
        for (int j = 0; j < 4; j++) oacc[i][j] = 0.f;
    float l0 = 0.f, l1 = 0.f;
    double scd0 = 0.0, scd1 = 0.0;

    uint32_t KH = sb + ABUF;
    uint32_t KM = KH + 16384;
    uint32_t VH = KH + 32768;
    uint32_t VM = KH + 49152;

#pragma unroll 1
    for (int kt = 0; kt < 8; kt++) {
        int k0 = kt * 128;
#pragma unroll
        for (int l = 0; l < 16; l++) {
            int idx = tid + l * 256;
            if (idx < 2048) {
                int ts = idx >> 10;
                int rem = idx & 1023;
                int r = rem >> 3, q = rem & 7;
                const __nv_bfloat16* src = (ts ? g_qkvm : g_qkvh) +
                    (((size_t)(b * NTOK + k0 + r) * 128 + 64 + h * 8 + q) << 3);
                uint32_t dst = KH + ts * 16384 + (uint32_t)(r * 128 + ((q ^ (r & 7)) << 4));
                CP_ASYNC16(dst, src);
            } else {
                int idx2 = idx - 2048;
                int ts = idx2 >> 10;
                int rem = idx2 & 1023;
                int d = rem >> 4, c = rem & 15;
                const __nv_bfloat16* src = (ts ? g_vtm : g_vth) +
                    ((((size_t)(b * NH + h) * 64 + d) * 128 + (k0 >> 3) + c) << 3);
                uint32_t dst = VH + ts * 16384 + (uint32_t)(d * 256 + ((c ^ (d & 7)) << 4));
                CP_ASYNC16(dst, src);
            }
        }
        CP_COMMIT();
        CP_WAIT(0);
        __syncthreads();

#pragma unroll
        for (int half = 0; half < 2; half++) {
            float sacc[8][4];
#pragma unroll
            for (int i = 0; i < 8; i++)
#pragma unroll
                for (int j = 0; j < 4; j++) sacc[i][j] = 0.f;

#pragma unroll
            for (int ks = 0; ks < 4; ks++) {
                uint32_t ch = (uint32_t)(ks * 2 + (lane >> 4));
                uint32_t ar = (uint32_t)(w * 16 + (lane & 15));
                uint32_t aoff = ar * 128 + ((ch ^ (ar & 7)) << 4);
                uint32_t qh0, qh1, qh2, qh3, qm0, qm1, qm2, qm3;
                ldsm4(sb + AQH + aoff, qh0, qh1, qh2, qh3);
                ldsm4(sb + AQM + aoff, qm0, qm1, qm2, qm3);
#pragma unroll
                for (int nb = 0; nb < 4; nb++) {
                    uint32_t br = (uint32_t)((half * 4 + nb) * 16 + (lane & 15));
                    uint32_t boff = br * 128 + ((ch ^ (br & 7)) << 4);
                    uint32_t kh0, kh1, kh2, kh3, km0, km1, km2, km3;
                    ldsm4(KH + boff, kh0, kh1, kh2, kh3);
                    ldsm4(KM + boff, km0, km1, km2, km3);
                    mma16816(sacc[2 * nb + 0], qh0, qh1, qh2, qh3, kh0, kh2);
                    mma16816(sacc[2 * nb + 1], qh0, qh1, qh2, qh3, kh1, kh3);
                    mma16816(sacc[2 * nb + 0], qh0, qh1, qh2, qh3, km0, km2);
                    mma16816(sacc[2 * nb + 1], qh0, qh1, qh2, qh3, km1, km3);
                    mma16816(sacc[2 * nb + 0], qm0, qm1, qm2, qm3, kh0, kh2);
                    mma16816(sacc[2 * nb + 1], qm0, qm1, qm2, qm3, kh1, kh3);
                }
            }

            {
                int r0g = q0 + w * 16 + (lane >> 2);
                const int* mr0 = mask + (size_t)r0g * NTOK + k0 + half * 64 + (lane & 3) * 2;
                const int* mr1 = mr0 + (size_t)8 * NTOK;
                float ss0 = 0.f, ss1 = 0.f, ls0 = 0.f, ls1 = 0.f;
#pragma unroll
                for (int t = 0; t < 8; t++) {
                    int2 m0 = *(const int2*)(mr0 + 8 * t);
                    int2 m1 = *(const int2*)(mr1 + 8 * t);
                    float g0 = sacc[t][0] * (float)m0.x;
                    float g1 = sacc[t][1] * (float)m0.y;
                    float g2 = sacc[t][2] * (float)m1.x;
                    float g3 = sacc[t][3] * (float)m1.y;
                    ss0 += fabsf(g0) + fabsf(g1);
                    ss1 += fabsf(g2) + fabsf(g3);
                    float p0 = __expf(g0), p1 = __expf(g1);
                    float p2 = __expf(g2), p3 = __expf(g3);
                    ls0 += p0 + p1; ls1 += p2 + p3;
                    sacc[t][0] = p0; sacc[t][1] = p1;
                    sacc[t][2] = p2; sacc[t][3] = p3;
                }
                scd0 += (double)ss0; scd1 += (double)ss1;
                l0 += ls0; l1 += ls1;
            }

            // O += P V : PhVh + PmVh (Ph·Vm dropped)
#pragma unroll
            for (int ks2 = 0; ks2 < 4; ks2++) {
                float* e = sacc[2 * ks2];
                float* o = sacc[2 * ks2 + 1];
                uint32_t ah0 = packbf2(e[0], e[1]);
                uint32_t ah1 = packbf2(e[2], e[3]);
                uint32_t ah2 = packbf2(o[0], o[1]);
                uint32_t ah3 = packbf2(o[2], o[3]);
                uint32_t am0 = packbf2(e[0] - bflo(ah0), e[1] - bfhi(ah0));
                uint32_t am1 = packbf2(e[2] - bflo(ah1), e[3] - bfhi(ah1));
                uint32_t am2 = packbf2(o[0] - bflo(ah2), o[1] - bfhi(ah2));
                uint32_t am3 = packbf2(o[2] - bflo(ah3), o[3] - bfhi(ah3));
                uint32_t ch = (uint32_t)((half * 4 + ks2) * 2 + (lane >> 4));
#pragma unroll
                for (int nd = 0; nd < 4; nd++) {
                    uint32_t br = (uint32_t)(nd * 16 + (lane & 15));
                    uint32_t boff = br * 256 + ((ch ^ (br & 7)) << 4);
                    uint32_t vh0, vh1, vh2, vh3, vm0, vm1, vm2, vm3;
                    ldsm4(VH + boff, vh0, vh1, vh2, vh3);
                    ldsm4(VM + boff, vm0, vm1, vm2, vm3);
                    mma16816(oacc[2 * nd + 0], ah0, ah1, ah2, ah3, vh0, vh2);
                    mma16816(oacc[2 * nd + 1], ah0, ah1, ah2, ah3, vh1, vh3);
                    mma16816(oacc[2 * nd + 0], ah0, ah1, ah2, ah3, vm0, vm2);
                    mma16816(oacc[2 * nd + 1], ah0, ah1, ah2, ah3, vm1, vm3);
                    mma16816(oacc[2 * nd + 0], am0, am1, am2, am3, vh0, vh2);
                    mma16816(oacc[2 * nd + 1], am0, am1, am2, am3, vh1, vh3);
                }
            }
        }
        __syncthreads();
    }

    l0 += __shfl_xor_sync(0xffffffffu, l0, 1);
    l0 += __shfl_xor_sync(0xffffffffu, l0, 2);
    l1 += __shfl_xor_sync(0xffffffffu, l1, 1);
    l1 += __shfl_xor_sync(0xffffffffu, l1, 2);
    scd0 += __shfl_xor_sync(0xffffffffu, scd0, 1);
    scd0 += __shfl_xor_sync(0xffffffffu, scd0, 2);
    scd1 += __shfl_xor_sync(0xffffffffu, scd1, 1);
    scd1 += __shfl_xor_sync(0xffffffffu, scd1, 2);
    float inv0 = 1.0f / l0, inv1 = 1.0f / l1;

    int r0 = q0 + w * 16 + (lane >> 2);
    int r1 = r0 + 8;
#pragma unroll
    for (int t = 0; t < 8; t++) {
        int col = h * DHE + 8 * t + (lane & 3) * 2;
        float a0 = oacc[t][0] * inv0, a1 = oacc[t][1] * inv0;
        float b0 = oacc[t][2] * inv1, b1 = oacc[t][3] * inv1;
        uint32_t h0 = packbf2(a0, a1), h1 = packbf2(b0, b1);
        uint32_t m0 = packbf2(a0 - bflo(h0), a1 - bfhi(h0));
        uint32_t m1 = packbf2(b0 - bflo(h1), b1 - bfhi(h1));
        *(uint32_t*)&g_ah[(size_t)(b * NTOK + r0) * DINNER + col] = h0;
        *(uint32_t*)&g_am[(size_t)(b * NTOK + r0) * DINNER + col] = m0;
        *(uint32_t*)&g_ah[(size_t)(b * NTOK + r1) * DINNER + col] = h1;
        *(uint32_t*)&g_am[(size_t)(b * NTOK + r1) * DINNER + col] = m1;
    }
    if ((lane & 3) == 0) {
        atomicAdd(&g_score[b * NTOK + r0], scd0);
        atomicAdd(&g_score[b * NTOK + r1], scd1);
    }
}

// ---------------- sort + swap map ------------------------------------------------
__global__ __launch_bounds__(1024) void sort_swap_kernel(const int* __restrict__ patches)
{
    int bb = blockIdx.x;
    int t = threadIdx.x;
    __shared__ double sval[NTOK];
    __shared__ int sidx[NTOK];
    sval[t] = g_score[bb * NTOK + t] / (double)g_nnz[t];
    sidx[t] = t;
    __syncthreads();

    for (int k = 2; k <= NTOK; k <<= 1) {
        for (int j = k >> 1; j > 0; j >>= 1) {
            int ixj = t ^ j;
            if (ixj > t) {
                double v1 = sval[t], v2 = sval[ixj];
                int i1 = sidx[t], i2 = sidx[ixj];
                bool gt = (v1 > v2) || (v1 == v2 && i1 > i2);
                bool up = ((t & k) == 0);
                if (gt == up) {
                    sval[t] = v2; sval[ixj] = v1;
                    sidx[t] = i2; sidx[ixj] = i1;
                }
            }
            __syncthreads();
        }
    }

    int bo = (BSZ - 1) - bb;
    g_src[bo * NTOK + t] = t;
    __syncthreads();
    if (t == 0) {
        int P = patches[0];
        for (int i = 1; i <= P; i++) {
            int ti = sidx[i];
            g_src[bo * NTOK + i] = ti;
            g_src[bo * NTOK + ti] = i;
        }
    }
}

// ---------------- launch -----------------------------------------------------------
extern "C" void kernel_launch(void* const* d_in, const int* in_sizes, int n_in,
                              void* d_out, int out_size)
{
    const float* x       = (const float*)d_in[0];
    const int*   cp_mask = (const int*)d_in[1];
    const float* w_qkv   = (const float*)d_in[2];
    const float* w_out   = (const float*)d_in[3];
    const float* b_out   = (const float*)d_in[4];
    const int*   patches = (const int*)d_in[5];
    float* out = (float*)d_out;

    cudaFuncSetAttribute(gemm_mma_kernel, cudaFuncAttributeMaxDynamicSharedMemorySize, GEMM_SMEM);
    cudaFuncSetAttribute(attn_mma_kernel, cudaFuncAttributeMaxDynamicSharedMemorySize, ATT_SMEM);

    nnz_kernel<<<NTOK, 256>>>(cp_mask);
    cvt_split2_kernel<<<(BSZ * NTOK * DMODEL) / 512, 512>>>(x, BSZ * NTOK * DMODEL);
    transpose_split2_kernel<<<dim3(QKV3 / 32, DMODEL / 32), dim3(32, 8)>>>(w_qkv, 0, DMODEL, QKV3);
    transpose_split2_kernel<<<dim3(DMODEL / 32, DINNER / 32), dim3(32, 8)>>>(w_out, 1, DINNER, DMODEL);
    gemm_mma_kernel<<<dim3(QKV3 / 128, (BSZ * NTOK) / 128), 256, GEMM_SMEM>>>(0, nullptr, nullptr);
    attn_mma_kernel<<<dim3(8, NH, BSZ), 256, ATT_SMEM>>>(cp_mask);
    sort_swap_kernel<<<BSZ, 1024>>>(patches);
    gemm_mma_kernel<<<dim3(DMODEL / 128, (BSZ * NTOK) / 128), 256, GEMM_SMEM>>>(1, out, b_out);
}